// round 10
// baseline (speedup 1.0000x reference)
#include <cuda_runtime.h>
#include <cuda_bf16.h>
#include <math.h>
#include <cstdint>

// ---------------- problem constants ----------------
#define NHEADS 8
#define HD 64
#define EMB 512
#define PS 16
#define GH 16
#define GW 44
#define SEQ 704            // GH*GW
#define NVIEW 6
#define MQ (NVIEW*SEQ)     // 4224
#define LM 16              // landmarks
#define KSEQ (5*SEQ)       // 3520
#define SCALE 0.125f       // 1/sqrt(64)

#define PE_C 256
#define IMG_H 256
#define IMG_W 704
#define K_PE (PE_C*PS*PS)  // 65536
#define K_X  (3*PS*PS)     // 768

#define MPAD 768           // 704 padded to 6x128
#define SPLITK 32
#define KSLICE (K_PE / SPLITK)   // 2048
#define KS 32                    // K per stage
#define NSTAGE (KSLICE / KS)     // 64

// smem tile geometry: rows stored with 40-element (80B) stride for
// conflict-free ldmatrix; 128 rows x 32 bf16 -> 10240 B per tile.
#define ROWB 80
#define TILEB (128 * ROWB)       // 10240
#define STAGEB (4 * TILEB)       // 40960 (Ahi, Alo, Bhi, Blo)

// ---------------- scratch (device globals, no cudaMalloc) ----------------
__device__ float g_maskf[SEQ];
__device__ float g_tokens[MQ * EMB];
__device__ float g_qkv[MQ * 3 * EMB];
__device__ float g_scratch[SPLITK * SEQ * EMB];
__device__ float g_pe_tok[SEQ * EMB];
__device__ float g_qn[NHEADS * SEQ * HD];
__device__ float g_kn[NHEADS * KSEQ * HD];
__device__ float g_vc[NHEADS * KSEQ * HD];
__device__ float g_qL[NHEADS * LM * HD];
__device__ float g_kL[NHEADS * LM * HD];
__device__ float g_a1[NHEADS * SEQ * LM];
__device__ float g_a2[NHEADS * LM * KSEQ];
__device__ float g_a2v[NHEADS * LM * HD];
__device__ float g_xout[SEQ * EMB];

// bf16 hi/lo split operands for pe GEMM
__device__ __nv_bfloat16 g_Ahi[(size_t)MPAD * K_PE];
__device__ __nv_bfloat16 g_Alo[(size_t)MPAD * K_PE];
__device__ __nv_bfloat16 g_Bhi[(size_t)EMB * K_PE];
__device__ __nv_bfloat16 g_Blo[(size_t)EMB * K_PE];

// ======================= PTX helpers (compute_103-safe) =======================
__device__ __forceinline__ uint32_t smem_u32(const void* p) {
    uint32_t a;
    asm("{ .reg .u64 t; cvta.to.shared.u64 t, %1; cvt.u32.u64 %0, t; }"
        : "=r"(a) : "l"(p));
    return a;
}

#define CP_ASYNC16(sp, gp) \
    asm volatile("cp.async.cg.shared.global [%0], [%1], 16;\n" :: "r"(sp), "l"(gp) : "memory")
#define CP_COMMIT() asm volatile("cp.async.commit_group;\n" ::: "memory")
#define CP_WAIT(n)  asm volatile("cp.async.wait_group %0;\n" :: "n"(n) : "memory")

#define LDSM4(r, addr) \
    asm volatile("ldmatrix.sync.aligned.m8n8.x4.shared.b16 {%0,%1,%2,%3}, [%4];" \
        : "=r"((r)[0]), "=r"((r)[1]), "=r"((r)[2]), "=r"((r)[3]) : "r"(addr))
#define LDSM2(r, addr) \
    asm volatile("ldmatrix.sync.aligned.m8n8.x2.shared.b16 {%0,%1}, [%2];" \
        : "=r"((r)[0]), "=r"((r)[1]) : "r"(addr))

#define MMA16816(d, a, b) \
    asm volatile("mma.sync.aligned.m16n8k16.row.col.f32.bf16.bf16.f32 " \
        "{%0,%1,%2,%3}, {%4,%5,%6,%7}, {%8,%9}, {%0,%1,%2,%3};" \
        : "+f"((d)[0]), "+f"((d)[1]), "+f"((d)[2]), "+f"((d)[3]) \
        : "r"((a)[0]), "r"((a)[1]), "r"((a)[2]), "r"((a)[3]), "r"((b)[0]), "r"((b)[1]))

// ---------------- patch mask: 16x16 avg pool > 0 ----------------
__global__ void mask_kernel(const float* __restrict__ mask_map, float* __restrict__ maskf) {
    int p = blockIdx.x;
    int gh = p / GW, gw = p % GW;
    int i = threadIdx.x >> 4, j = threadIdx.x & 15;
    float v = mask_map[(gh * PS + i) * IMG_W + gw * PS + j];
    __shared__ float red[256];
    red[threadIdx.x] = v;
    __syncthreads();
    for (int off = 128; off > 0; off >>= 1) {
        if (threadIdx.x < off) red[threadIdx.x] += red[threadIdx.x + off];
        __syncthreads();
    }
    if (threadIdx.x == 0) maskf[p] = (red[0] > 0.0f) ? 1.0f : 0.0f;
}

// ---------------- bf16 hi/lo conversion kernels ----------------
__device__ __forceinline__ void split4(float4 v, uint2& hi, uint2& lo) {
    __nv_bfloat16 h0 = __float2bfloat16(v.x);
    __nv_bfloat16 h1 = __float2bfloat16(v.y);
    __nv_bfloat16 h2 = __float2bfloat16(v.z);
    __nv_bfloat16 h3 = __float2bfloat16(v.w);
    __nv_bfloat16 l0 = __float2bfloat16(v.x - __bfloat162float(h0));
    __nv_bfloat16 l1 = __float2bfloat16(v.y - __bfloat162float(h1));
    __nv_bfloat16 l2 = __float2bfloat16(v.z - __bfloat162float(h2));
    __nv_bfloat16 l3 = __float2bfloat16(v.w - __bfloat162float(h3));
    __nv_bfloat162 ph0; ph0.x = h0; ph0.y = h1;
    __nv_bfloat162 ph1; ph1.x = h2; ph1.y = h3;
    __nv_bfloat162 pl0; pl0.x = l0; pl0.y = l1;
    __nv_bfloat162 pl1; pl1.x = l2; pl1.y = l3;
    hi.x = *reinterpret_cast<uint32_t*>(&ph0);
    hi.y = *reinterpret_cast<uint32_t*>(&ph1);
    lo.x = *reinterpret_cast<uint32_t*>(&pl0);
    lo.y = *reinterpret_cast<uint32_t*>(&pl1);
}

// A = im2col(pe[ft]) -> [MPAD][K_PE], rows >= SEQ zero
__global__ void conv_a_kernel(const float* __restrict__ pe, const int* __restrict__ ftag) {
    size_t idx = (size_t)blockIdx.x * 256 + threadIdx.x;   // one per 4 elems
    int m = (int)(idx >> 14);               // K_PE/4 = 16384 per row
    int kq = ((int)idx & 16383) << 2;
    float4 v = make_float4(0.f, 0.f, 0.f, 0.f);
    if (m < SEQ) {
        int c = kq >> 8, rem = kq & 255, i = rem >> 4, j = rem & 15;
        int gh = m / GW, gw = m % GW;
        const float* src = pe + (size_t)ftag[0] * PE_C * IMG_H * IMG_W
                              + ((size_t)c * IMG_H + gh * PS + i) * IMG_W + gw * PS + j;
        v = *(const float4*)src;
    }
    uint2 hi, lo;
    split4(v, hi, lo);
    size_t off = (size_t)m * K_PE + kq;
    *(uint2*)(g_Ahi + off) = hi;
    *(uint2*)(g_Alo + off) = lo;
}

// B = conv_pe_w (512 x 65536) straight split
__global__ void conv_b_kernel(const float* __restrict__ w) {
    size_t idx = (size_t)blockIdx.x * 256 + threadIdx.x;
    size_t off = idx << 2;
    float4 v = *(const float4*)(w + off);
    uint2 hi, lo;
    split4(v, hi, lo);
    *(uint2*)(g_Bhi + off) = hi;
    *(uint2*)(g_Blo + off) = lo;
}

// ---------------- pe GEMM via mma.sync bf16 (3-pass hi/lo) ----------------
// CTA tile M=128, N=128, K-stage 32, double-buffered cp.async, split-K=32.
// 8 warps: warp_m (2) x warp_n (4); each warp 64x32, 4x4 m16n8k16 tiles.
__device__ __forceinline__ void load_stage(uint32_t smbuf, int m0, int n0, int koff, int tid) {
#pragma unroll
    for (int it = 0; it < 8; it++) {
        int f = it * 256 + tid;        // 0..2047 chunks of 16B
        int tile = f >> 9;             // 0:Ahi 1:Alo 2:Bhi 3:Blo (512 chunks each)
        int idx = f & 511;
        int row = idx >> 2;            // 0..127
        int q = idx & 3;               // 16B chunk in 64B row
        const __nv_bfloat16* g;
        int r0;
        if (tile == 0)      { g = g_Ahi; r0 = m0; }
        else if (tile == 1) { g = g_Alo; r0 = m0; }
        else if (tile == 2) { g = g_Bhi; r0 = n0; }
        else                { g = g_Blo; r0 = n0; }
        const __nv_bfloat16* gp = g + (size_t)(r0 + row) * K_PE + koff + q * 8;
        uint32_t sp = smbuf + tile * TILEB + row * ROWB + q * 16;
        CP_ASYNC16(sp, gp);
    }
    CP_COMMIT();
}

__global__ void __launch_bounds__(256, 2) pe_gemm_kernel() {
    extern __shared__ __align__(128) char dsm[];
    const uint32_t base = smem_u32(dsm);
    const int tid = threadIdx.x;
    const int wid = tid >> 5, lane = tid & 31;
    const int warp_m = wid >> 2;            // 0..1
    const int warp_n = wid & 3;             // 0..3
    const int n0 = blockIdx.x * 128;
    const int m0 = blockIdx.y * 128;
    const int z  = blockIdx.z;
    const int kbase = z * KSLICE;

    float acc[4][4][4];
#pragma unroll
    for (int i = 0; i < 4; i++)
#pragma unroll
        for (int j = 0; j < 4; j++)
#pragma unroll
            for (int c = 0; c < 4; c++) acc[i][j][c] = 0.0f;

    // per-lane ldmatrix address offsets (within a tile)
    const uint32_t a_off = (uint32_t)((warp_m * 64 + (lane & 15)) * ROWB + ((lane >> 4) << 4));
    const uint32_t b_off = (uint32_t)((warp_n * 32 + (lane & 7)) * ROWB + (((lane >> 3) & 1) << 4));

    load_stage(base, m0, n0, kbase, tid);

#pragma unroll 1
    for (int s = 0; s < NSTAGE; s++) {
        uint32_t cb = base + (s & 1) * STAGEB;
        if (s + 1 < NSTAGE) {
            load_stage(base + ((s + 1) & 1) * STAGEB, m0, n0, kbase + (s + 1) * KS, tid);
            CP_WAIT(1);
        } else {
            CP_WAIT(0);
        }
        __syncthreads();

        const uint32_t Ah = cb;
        const uint32_t Al = cb + TILEB;
        const uint32_t Bh = cb + 2 * TILEB;
        const uint32_t Bl = cb + 3 * TILEB;

#pragma unroll
        for (int ks = 0; ks < 2; ks++) {
            uint32_t kb = ks * 32;   // 16 bf16 = 32B per k-step
            uint32_t bh[4][2], bl[4][2];
#pragma unroll
            for (int nt = 0; nt < 4; nt++) {
                uint32_t boff = b_off + nt * 8 * ROWB + kb;
                LDSM2(bh[nt], Bh + boff);
                LDSM2(bl[nt], Bl + boff);
            }
#pragma unroll
            for (int mt = 0; mt < 4; mt++) {
                uint32_t ah[4], al[4];
                uint32_t aoff = a_off + mt * 16 * ROWB + kb;
                LDSM4(ah, Ah + aoff);
                LDSM4(al, Al + aoff);
#pragma unroll
                for (int nt = 0; nt < 4; nt++) {
                    MMA16816(acc[mt][nt], ah, bh[nt]);
                    MMA16816(acc[mt][nt], ah, bl[nt]);
                    MMA16816(acc[mt][nt], al, bh[nt]);
                }
            }
        }
        __syncthreads();
    }

    // epilogue: d0,d1 -> (row, col..col+1); d2,d3 -> (row+8, col..col+1)
    float* out = g_scratch + (size_t)z * SEQ * EMB;
    const int rbase = m0 + warp_m * 64 + (lane >> 2);
    const int cbase = n0 + warp_n * 32 + ((lane & 3) << 1);
#pragma unroll
    for (int mt = 0; mt < 4; mt++) {
#pragma unroll
        for (int nt = 0; nt < 4; nt++) {
            int r0 = rbase + mt * 16;
            int c  = cbase + nt * 8;
            if (r0 < SEQ)
                *(float2*)(out + (size_t)r0 * EMB + c) = make_float2(acc[mt][nt][0], acc[mt][nt][1]);
            if (r0 + 8 < SEQ)
                *(float2*)(out + (size_t)(r0 + 8) * EMB + c) = make_float2(acc[mt][nt][2], acc[mt][nt][3]);
        }
    }
}

// ---------------- canonical 128x128x8 FFMA SGEMM (x-embed / QKV / out-proj) ----------------
template<int MODE>
__global__ void __launch_bounds__(256, 2)
sgemm_k(const float* __restrict__ A, const float* __restrict__ B,
        float* __restrict__ C, const float* __restrict__ bias,
        const float* __restrict__ maskf,
        int M, int N, int Ktot, int imgC)
{
    __shared__ float As[8][128];
    __shared__ float Bs[8][128];

    const int tid = threadIdx.x;
    const int m0 = blockIdx.y * 128;
    const int n0 = blockIdx.x * 128;

    const int aM = tid >> 1;
    const int aQ = (tid & 1) << 2;
    const int bN = tid >> 1;
    const int bQ = (tid & 1) << 2;
    const int trow = (tid >> 4) << 3;
    const int tcol = (tid & 15) << 3;

    float acc[8][8];
#pragma unroll
    for (int i = 0; i < 8; i++)
#pragma unroll
        for (int j = 0; j < 8; j++) acc[i][j] = 0.0f;

    const int am = m0 + aM;
    const bool mvalid = (am < M);

    const float* arow = A;
    if (MODE == 1 && mvalid) {
        int v = am / SEQ;
        int s = am % SEQ;
        int gh = s / GW, gw = s % GW;
        arow = A + ((size_t)(v * imgC) * IMG_H + gh * PS) * IMG_W + gw * PS;
    }
    const float* Bp = B + (size_t)(n0 + bN) * Ktot + bQ;
    const float* Ap = (MODE == 0) ? (A + (size_t)am * Ktot + aQ) : nullptr;

    for (int kk = 0; kk < Ktot; kk += 8) {
        float4 av = make_float4(0.f, 0.f, 0.f, 0.f);
        if (MODE == 0) {
            if (mvalid) av = *(const float4*)Ap;
            Ap += 8;
        } else {
            if (mvalid) {
                int k = kk + aQ;
                int c = k >> 8;
                int rem = k & 255;
                int i = rem >> 4, j = rem & 15;
                av = *(const float4*)(arow + ((size_t)c * IMG_H + i) * IMG_W + j);
            }
        }
        As[aQ + 0][aM] = av.x;
        As[aQ + 1][aM] = av.y;
        As[aQ + 2][aM] = av.z;
        As[aQ + 3][aM] = av.w;

        float4 bv = *(const float4*)Bp;
        Bp += 8;
        Bs[bQ + 0][bN] = bv.x;
        Bs[bQ + 1][bN] = bv.y;
        Bs[bQ + 2][bN] = bv.z;
        Bs[bQ + 3][bN] = bv.w;

        __syncthreads();
#pragma unroll
        for (int k = 0; k < 8; k++) {
            float4 a0 = *(const float4*)&As[k][trow];
            float4 a1 = *(const float4*)&As[k][trow + 4];
            float4 b0 = *(const float4*)&Bs[k][tcol];
            float4 b1 = *(const float4*)&Bs[k][tcol + 4];
            float ar[8] = {a0.x, a0.y, a0.z, a0.w, a1.x, a1.y, a1.z, a1.w};
            float br[8] = {b0.x, b0.y, b0.z, b0.w, b1.x, b1.y, b1.z, b1.w};
#pragma unroll
            for (int i = 0; i < 8; i++)
#pragma unroll
                for (int j = 0; j < 8; j++) acc[i][j] += ar[i] * br[j];
        }
        __syncthreads();
    }

#pragma unroll
    for (int i = 0; i < 8; i++) {
        int m = m0 + trow + i;
        if (m >= M) break;
        float mk = (maskf != nullptr) ? maskf[m % SEQ] : 1.0f;
        float* crow = C + (size_t)m * N + n0 + tcol;
#pragma unroll
        for (int j = 0; j < 8; j += 4) {
            float4 r;
            r.x = (acc[i][j + 0] + bias[n0 + tcol + j + 0]) * mk;
            r.y = (acc[i][j + 1] + bias[n0 + tcol + j + 1]) * mk;
            r.z = (acc[i][j + 2] + bias[n0 + tcol + j + 2]) * mk;
            r.w = (acc[i][j + 3] + bias[n0 + tcol + j + 3]) * mk;
            *(float4*)(crow + j) = r;
        }
    }
}

// ---------------- reduce split-K pe partials + bias + mask ----------------
__global__ void reduce_pe_kernel(const float* __restrict__ bias,
                                 const float* __restrict__ maskf) {
    int idx = blockIdx.x * blockDim.x + threadIdx.x;
    if (idx >= SEQ * EMB) return;
    int n = idx % EMB;
    int m = idx / EMB;
    float acc = bias[n];
#pragma unroll
    for (int z = 0; z < SPLITK; z++) acc += g_scratch[(size_t)z * SEQ * EMB + idx];
    g_pe_tok[idx] = acc * maskf[m];
}

// ---------------- q/k prep, landmarks, attention core ----------------
__device__ __forceinline__ float block64_sum(float v, float* red2) {
    for (int off = 16; off > 0; off >>= 1)
        v += __shfl_xor_sync(0xffffffffu, v, off);
    if ((threadIdx.x & 31) == 0) red2[threadIdx.x >> 5] = v;
    __syncthreads();
    return red2[0] + red2[1];
}

__global__ void prep_q_kernel(const int* __restrict__ ftag) {
    int s = blockIdx.x, h = blockIdx.y, e = threadIdx.x;
    int ft = ftag[0];
    float val = g_qkv[((size_t)(ft * SEQ + s)) * (3 * EMB) + h * (3 * HD) + e]
              + g_pe_tok[(size_t)s * EMB + h * HD + e];
    __shared__ float red2[2];
    float tot = block64_sum(val * val, red2);
    float denom = fmaxf(sqrtf(tot), 1e-12f);
    g_qn[((size_t)h * SEQ + s) * HD + e] = val / denom;
}

__global__ void prep_k_kernel(const int* __restrict__ ftag) {
    int t = blockIdx.x, h = blockIdx.y, e = threadIdx.x;
    int ft = ftag[0];
    int vi = t / SEQ;
    int view = (vi < ft) ? vi : vi + 1;
    int s = t % SEQ;
    size_t base = ((size_t)(view * SEQ + s)) * (3 * EMB) + h * (3 * HD);
    float kval = g_qkv[base + HD + e];
    float vval = g_qkv[base + 2 * HD + e];
    __shared__ float red2[2];
    float tot = block64_sum(kval * kval, red2);
    float denom = fmaxf(sqrtf(tot), 1e-12f);
    g_kn[((size_t)h * KSEQ + t) * HD + e] = kval / denom;
    g_vc[((size_t)h * KSEQ + t) * HD + e] = vval;
}

__global__ void landmark_kernel(const float* __restrict__ src, float* __restrict__ dst, int seg) {
    int l = blockIdx.x, h = blockIdx.y, e = threadIdx.x;
    int S = LM * seg;
    const float* p = src + ((size_t)h * S + (size_t)l * seg) * HD + e;
    float acc = 0.f;
    for (int r = 0; r < seg; r++) acc += p[(size_t)r * HD];
    dst[((size_t)h * LM + l) * HD + e] = acc / (float)seg;
}

__global__ void a1_kernel() {
    int warp = threadIdx.x >> 5, lane = threadIdx.x & 31;
    int s = blockIdx.x * 4 + warp;
    int h = blockIdx.y;
    const float* qp = g_qn + ((size_t)h * SEQ + s) * HD;
    float q0 = qp[lane], q1 = qp[lane + 32];
    float lg[LM];
#pragma unroll
    for (int l = 0; l < LM; l++) {
        const float* kp = g_kL + ((size_t)h * LM + l) * HD;
        float p = q0 * kp[lane] + q1 * kp[lane + 32];
        for (int off = 16; off > 0; off >>= 1)
            p += __shfl_xor_sync(0xffffffffu, p, off);
        lg[l] = p * SCALE;
    }
    float mx = lg[0];
#pragma unroll
    for (int l = 1; l < LM; l++) mx = fmaxf(mx, lg[l]);
    float sum = 0.f;
#pragma unroll
    for (int l = 0; l < LM; l++) { lg[l] = expf(lg[l] - mx); sum += lg[l]; }
    float inv = 1.0f / sum;
    if (lane < LM)
        g_a1[((size_t)h * SEQ + s) * LM + lane] = lg[lane] * inv;
}

__global__ void a2_kernel() {
    int l = blockIdx.x, h = blockIdx.y, tid = threadIdx.x;
    __shared__ float sq[HD];
    __shared__ float lg[KSEQ];
    __shared__ float red[256];
    if (tid < HD) sq[tid] = g_qL[((size_t)h * LM + l) * HD + tid];
    __syncthreads();

    for (int t = tid; t < KSEQ; t += 256) {
        const float* kp = g_kn + ((size_t)h * KSEQ + t) * HD;
        float d = 0.f;
#pragma unroll
        for (int e = 0; e < HD; e += 4) {
            float4 kv = *(const float4*)(kp + e);
            d += kv.x * sq[e] + kv.y * sq[e + 1] + kv.z * sq[e + 2] + kv.w * sq[e + 3];
        }
        lg[t] = d * SCALE;
    }
    __syncthreads();

    float lmax = -1e30f;
    for (int t = tid; t < KSEQ; t += 256) lmax = fmaxf(lmax, lg[t]);
    red[tid] = lmax;
    __syncthreads();
    for (int off = 128; off > 0; off >>= 1) {
        if (tid < off) red[tid] = fmaxf(red[tid], red[tid + off]);
        __syncthreads();
    }
    float gmax = red[0];
    __syncthreads();

    float lsum = 0.f;
    for (int t = tid; t < KSEQ; t += 256) {
        float e = expf(lg[t] - gmax);
        lg[t] = e;
        lsum += e;
    }
    red[tid] = lsum;
    __syncthreads();
    for (int off = 128; off > 0; off >>= 1) {
        if (tid < off) red[tid] += red[tid + off];
        __syncthreads();
    }
    float inv = 1.0f / red[0];
    float* out = g_a2 + ((size_t)h * LM + l) * KSEQ;
    for (int t = tid; t < KSEQ; t += 256) out[t] = lg[t] * inv;
}

__global__ void a2v_kernel() {
    int l = blockIdx.x, h = blockIdx.y, e = threadIdx.x;
    const float* ar = g_a2 + ((size_t)h * LM + l) * KSEQ;
    const float* vp = g_vc + (size_t)h * KSEQ * HD + e;
    float acc = 0.f;
#pragma unroll 4
    for (int t = 0; t < KSEQ; t++) acc += ar[t] * vp[(size_t)t * HD];
    g_a2v[((size_t)h * LM + l) * HD + e] = acc;
}

__global__ void vals_kernel() {
    int s = blockIdx.x;
    int h = threadIdx.x >> 6;
    int e = threadIdx.x & 63;
    const float* ap = g_a1 + ((size_t)h * SEQ + s) * LM;
    const float* bp = g_a2v + (size_t)h * LM * HD + e;
    float acc = 0.f;
#pragma unroll
    for (int l = 0; l < LM; l++) acc += ap[l] * bp[(size_t)l * HD];
    g_xout[(size_t)s * EMB + h * HD + e] = acc;
}

// ---------------- launch ----------------
extern "C" void kernel_launch(void* const* d_in, const int* in_sizes, int n_in,
                              void* d_out, int out_size) {
    const float* x         = (const float*)d_in[0];
    const float* pe        = (const float*)d_in[1];
    const float* mask_map  = (const float*)d_in[2];
    const float* conv_in_w = (const float*)d_in[3];
    const float* conv_in_b = (const float*)d_in[4];
    const float* conv_pe_w = (const float*)d_in[5];
    const float* conv_pe_b = (const float*)d_in[6];
    const float* qkv_w     = (const float*)d_in[7];
    const float* qkv_b     = (const float*)d_in[8];
    const float* o_w       = (const float*)d_in[9];
    const float* o_b       = (const float*)d_in[10];
    const int*   ftag      = (const int*)d_in[11];

    float* maskf_p;   cudaGetSymbolAddress((void**)&maskf_p,   g_maskf);
    float* tokens_p;  cudaGetSymbolAddress((void**)&tokens_p,  g_tokens);
    float* qkv_p;     cudaGetSymbolAddress((void**)&qkv_p,     g_qkv);
    float* xout_p;    cudaGetSymbolAddress((void**)&xout_p,    g_xout);
    float* qn_p;      cudaGetSymbolAddress((void**)&qn_p,      g_qn);
    float* kn_p;      cudaGetSymbolAddress((void**)&kn_p,      g_kn);
    float* qL_p;      cudaGetSymbolAddress((void**)&qL_p,      g_qL);
    float* kL_p;      cudaGetSymbolAddress((void**)&kL_p,      g_kL);

    // 1. patch mask
    mask_kernel<<<SEQ, 256>>>(mask_map, maskf_p);

    // 2. bf16 hi/lo conversion of pe im2col (A) and conv_pe_w (B)
    conv_a_kernel<<<(MPAD * (K_PE / 4)) / 256, 256>>>(pe, ftag);
    conv_b_kernel<<<(int)(((size_t)EMB * K_PE / 4) / 256), 256>>>(conv_pe_w);

    // 3. pe GEMM via mma.sync bf16 (3-pass, split-K=32 into g_scratch)
    static int smem_set = 0;
    if (!smem_set) {
        cudaFuncSetAttribute(pe_gemm_kernel, cudaFuncAttributeMaxDynamicSharedMemorySize, 2 * STAGEB);
        smem_set = 1;
    }
    pe_gemm_kernel<<<dim3(EMB / 128, MPAD / 128, SPLITK), 256, 2 * STAGEB>>>();

    // 4. reduce split-K + bias + mask -> pe_tok
    reduce_pe_kernel<<<(SEQ * EMB + 255) / 256, 256>>>(conv_pe_b, maskf_p);

    // 5. x patch embed -> tokens (4224 x 512, K=768)
    sgemm_k<1><<<dim3(EMB / 128, MQ / 128, 1), 256>>>(
        x, conv_in_w, tokens_p, conv_in_b, maskf_p, MQ, EMB, K_X, 3);

    // 6. QKV: tokens @ qkv_w^T + b  (4224 x 1536, K=512)
    sgemm_k<0><<<dim3((3 * EMB) / 128, MQ / 128, 1), 256>>>(
        tokens_p, qkv_w, qkv_p, qkv_b, nullptr, MQ, 3 * EMB, EMB, 0);

    // 7. normalized q (+pe) and k, raw v gather
    prep_q_kernel<<<dim3(SEQ, NHEADS), HD>>>(ftag);
    prep_k_kernel<<<dim3(KSEQ, NHEADS), HD>>>(ftag);

    // 8. landmarks
    landmark_kernel<<<dim3(LM, NHEADS), HD>>>(qn_p, qL_p, SEQ / LM);
    landmark_kernel<<<dim3(LM, NHEADS), HD>>>(kn_p, kL_p, KSEQ / LM);

    // 9. attention core
    a1_kernel<<<dim3(SEQ / 4, NHEADS), 128>>>();
    a2_kernel<<<dim3(LM, NHEADS), 256>>>();
    a2v_kernel<<<dim3(LM, NHEADS), HD>>>();
    vals_kernel<<<SEQ, EMB>>>();

    // 10. output projection -> d_out (704 x 512)
    sgemm_k<0><<<dim3(EMB / 128, (SEQ + 127) / 128, 1), 256>>>(
        xout_p, o_w, (float*)d_out, o_b, nullptr, SEQ, EMB, EMB, 0);
}

// round 11
// speedup vs baseline: 1.0012x; 1.0012x over previous
#include <cuda_runtime.h>
#include <cuda_bf16.h>
#include <math.h>
#include <cstdint>

// ---------------- problem constants ----------------
#define NHEADS 8
#define HD 64
#define EMB 512
#define PS 16
#define GH 16
#define GW 44
#define SEQ 704            // GH*GW
#define NVIEW 6
#define MQ (NVIEW*SEQ)     // 4224
#define LM 16              // landmarks
#define KSEQ (5*SEQ)       // 3520
#define SCALE 0.125f       // 1/sqrt(64)

#define PE_C 256
#define IMG_H 256
#define IMG_W 704
#define K_PE (PE_C*PS*PS)  // 65536
#define K_X  (3*PS*PS)     // 768

#define MPAD 768           // 704 padded to 6x128
#define SPLITK 32
#define KSLICE (K_PE / SPLITK)   // 2048
#define KS 32                    // K per stage
#define NSTAGE (KSLICE / KS)     // 64

// smem tile geometry: rows stored with 40-element (80B) stride for
// conflict-free ldmatrix; 128 rows x 32 bf16 -> 10240 B per tile.
#define ROWB 80
#define TILEB (128 * ROWB)       // 10240
#define STAGEB (4 * TILEB)       // 40960 (Ahi, Alo, Bhi, Blo)

// ---------------- scratch (device globals, no cudaMalloc) ----------------
__device__ float g_maskf[SEQ];
__device__ float g_tokens[MQ * EMB];
__device__ float g_qkv[MQ * 3 * EMB];
__device__ float g_scratch[SPLITK * SEQ * EMB];
__device__ float g_pe_tok[SEQ * EMB];
__device__ float g_qn[NHEADS * SEQ * HD];
__device__ float g_kn[NHEADS * KSEQ * HD];
__device__ float g_vc[NHEADS * KSEQ * HD];
__device__ float g_qL[NHEADS * LM * HD];
__device__ float g_kL[NHEADS * LM * HD];
__device__ float g_a1[NHEADS * SEQ * LM];
__device__ float g_a2[NHEADS * LM * KSEQ];
__device__ float g_a2v[NHEADS * LM * HD];
__device__ float g_xout[SEQ * EMB];

// bf16 hi/lo split operands for pe GEMM
__device__ __nv_bfloat16 g_Ahi[(size_t)MPAD * K_PE];
__device__ __nv_bfloat16 g_Alo[(size_t)MPAD * K_PE];
__device__ __nv_bfloat16 g_Bhi[(size_t)EMB * K_PE];
__device__ __nv_bfloat16 g_Blo[(size_t)EMB * K_PE];

// ======================= PTX helpers (compute_103-safe) =======================
__device__ __forceinline__ uint32_t smem_u32(const void* p) {
    uint32_t a;
    asm("{ .reg .u64 t; cvta.to.shared.u64 t, %1; cvt.u32.u64 %0, t; }"
        : "=r"(a) : "l"(p));
    return a;
}

#define CP_ASYNC16(sp, gp) \
    asm volatile("cp.async.cg.shared.global [%0], [%1], 16;\n" :: "r"(sp), "l"(gp) : "memory")
#define CP_COMMIT() asm volatile("cp.async.commit_group;\n" ::: "memory")
#define CP_WAIT(n)  asm volatile("cp.async.wait_group %0;\n" :: "n"(n) : "memory")

#define LDSM4(r, addr) \
    asm volatile("ldmatrix.sync.aligned.m8n8.x4.shared.b16 {%0,%1,%2,%3}, [%4];" \
        : "=r"((r)[0]), "=r"((r)[1]), "=r"((r)[2]), "=r"((r)[3]) : "r"(addr))
#define LDSM2(r, addr) \
    asm volatile("ldmatrix.sync.aligned.m8n8.x2.shared.b16 {%0,%1}, [%2];" \
        : "=r"((r)[0]), "=r"((r)[1]) : "r"(addr))

#define MMA16816(d, a, b) \
    asm volatile("mma.sync.aligned.m16n8k16.row.col.f32.bf16.bf16.f32 " \
        "{%0,%1,%2,%3}, {%4,%5,%6,%7}, {%8,%9}, {%0,%1,%2,%3};" \
        : "+f"((d)[0]), "+f"((d)[1]), "+f"((d)[2]), "+f"((d)[3]) \
        : "r"((a)[0]), "r"((a)[1]), "r"((a)[2]), "r"((a)[3]), "r"((b)[0]), "r"((b)[1]))

// ---------------- patch mask: 16x16 avg pool > 0 ----------------
__global__ void mask_kernel(const float* __restrict__ mask_map, float* __restrict__ maskf) {
    int p = blockIdx.x;
    int gh = p / GW, gw = p % GW;
    int i = threadIdx.x >> 4, j = threadIdx.x & 15;
    float v = mask_map[(gh * PS + i) * IMG_W + gw * PS + j];
    __shared__ float red[256];
    red[threadIdx.x] = v;
    __syncthreads();
    for (int off = 128; off > 0; off >>= 1) {
        if (threadIdx.x < off) red[threadIdx.x] += red[threadIdx.x + off];
        __syncthreads();
    }
    if (threadIdx.x == 0) maskf[p] = (red[0] > 0.0f) ? 1.0f : 0.0f;
}

// ---------------- bf16 hi/lo conversion kernels ----------------
__device__ __forceinline__ void split4(float4 v, uint2& hi, uint2& lo) {
    __nv_bfloat16 h0 = __float2bfloat16(v.x);
    __nv_bfloat16 h1 = __float2bfloat16(v.y);
    __nv_bfloat16 h2 = __float2bfloat16(v.z);
    __nv_bfloat16 h3 = __float2bfloat16(v.w);
    __nv_bfloat16 l0 = __float2bfloat16(v.x - __bfloat162float(h0));
    __nv_bfloat16 l1 = __float2bfloat16(v.y - __bfloat162float(h1));
    __nv_bfloat16 l2 = __float2bfloat16(v.z - __bfloat162float(h2));
    __nv_bfloat16 l3 = __float2bfloat16(v.w - __bfloat162float(h3));
    __nv_bfloat162 ph0; ph0.x = h0; ph0.y = h1;
    __nv_bfloat162 ph1; ph1.x = h2; ph1.y = h3;
    __nv_bfloat162 pl0; pl0.x = l0; pl0.y = l1;
    __nv_bfloat162 pl1; pl1.x = l2; pl1.y = l3;
    hi.x = *reinterpret_cast<uint32_t*>(&ph0);
    hi.y = *reinterpret_cast<uint32_t*>(&ph1);
    lo.x = *reinterpret_cast<uint32_t*>(&pl0);
    lo.y = *reinterpret_cast<uint32_t*>(&pl1);
}

// A = im2col(pe[ft]) -> [MPAD][K_PE], rows >= SEQ zero
__global__ void conv_a_kernel(const float* __restrict__ pe, const int* __restrict__ ftag) {
    size_t idx = (size_t)blockIdx.x * 256 + threadIdx.x;   // one per 4 elems
    int m = (int)(idx >> 14);               // K_PE/4 = 16384 per row
    int kq = ((int)idx & 16383) << 2;
    float4 v = make_float4(0.f, 0.f, 0.f, 0.f);
    if (m < SEQ) {
        int c = kq >> 8, rem = kq & 255, i = rem >> 4, j = rem & 15;
        int gh = m / GW, gw = m % GW;
        const float* src = pe + (size_t)ftag[0] * PE_C * IMG_H * IMG_W
                              + ((size_t)c * IMG_H + gh * PS + i) * IMG_W + gw * PS + j;
        v = *(const float4*)src;
    }
    uint2 hi, lo;
    split4(v, hi, lo);
    size_t off = (size_t)m * K_PE + kq;
    *(uint2*)(g_Ahi + off) = hi;
    *(uint2*)(g_Alo + off) = lo;
}

// B = conv_pe_w (512 x 65536) straight split
__global__ void conv_b_kernel(const float* __restrict__ w) {
    size_t idx = (size_t)blockIdx.x * 256 + threadIdx.x;
    size_t off = idx << 2;
    float4 v = *(const float4*)(w + off);
    uint2 hi, lo;
    split4(v, hi, lo);
    *(uint2*)(g_Bhi + off) = hi;
    *(uint2*)(g_Blo + off) = lo;
}

// ---------------- pe GEMM via mma.sync bf16 (3-pass hi/lo) ----------------
// CTA tile M=128, N=128, K-stage 32, double-buffered cp.async, split-K=32.
// 8 warps: warp_m (2) x warp_n (4); each warp 64x32, 4x4 m16n8k16 tiles.
__device__ __forceinline__ void load_stage(uint32_t smbuf, int m0, int n0, int koff, int tid) {
#pragma unroll
    for (int it = 0; it < 8; it++) {
        int f = it * 256 + tid;        // 0..2047 chunks of 16B
        int tile = f >> 9;             // 0:Ahi 1:Alo 2:Bhi 3:Blo (512 chunks each)
        int idx = f & 511;
        int row = idx >> 2;            // 0..127
        int q = idx & 3;               // 16B chunk in 64B row
        const __nv_bfloat16* g;
        int r0;
        if (tile == 0)      { g = g_Ahi; r0 = m0; }
        else if (tile == 1) { g = g_Alo; r0 = m0; }
        else if (tile == 2) { g = g_Bhi; r0 = n0; }
        else                { g = g_Blo; r0 = n0; }
        const __nv_bfloat16* gp = g + (size_t)(r0 + row) * K_PE + koff + q * 8;
        uint32_t sp = smbuf + tile * TILEB + row * ROWB + q * 16;
        CP_ASYNC16(sp, gp);
    }
    CP_COMMIT();
}

__global__ void __launch_bounds__(256, 2) pe_gemm_kernel() {
    extern __shared__ __align__(128) char dsm[];
    const uint32_t base = smem_u32(dsm);
    const int tid = threadIdx.x;
    const int wid = tid >> 5, lane = tid & 31;
    const int warp_m = wid >> 2;            // 0..1
    const int warp_n = wid & 3;             // 0..3
    const int n0 = blockIdx.x * 128;
    const int m0 = blockIdx.y * 128;
    const int z  = blockIdx.z;
    const int kbase = z * KSLICE;

    float acc[4][4][4];
#pragma unroll
    for (int i = 0; i < 4; i++)
#pragma unroll
        for (int j = 0; j < 4; j++)
#pragma unroll
            for (int c = 0; c < 4; c++) acc[i][j][c] = 0.0f;

    // per-lane ldmatrix address offsets (within a tile)
    const uint32_t a_off = (uint32_t)((warp_m * 64 + (lane & 15)) * ROWB + ((lane >> 4) << 4));
    const uint32_t b_off = (uint32_t)((warp_n * 32 + (lane & 7)) * ROWB + (((lane >> 3) & 1) << 4));

    load_stage(base, m0, n0, kbase, tid);

#pragma unroll 1
    for (int s = 0; s < NSTAGE; s++) {
        uint32_t cb = base + (s & 1) * STAGEB;
        if (s + 1 < NSTAGE) {
            load_stage(base + ((s + 1) & 1) * STAGEB, m0, n0, kbase + (s + 1) * KS, tid);
            CP_WAIT(1);
        } else {
            CP_WAIT(0);
        }
        __syncthreads();

        const uint32_t Ah = cb;
        const uint32_t Al = cb + TILEB;
        const uint32_t Bh = cb + 2 * TILEB;
        const uint32_t Bl = cb + 3 * TILEB;

#pragma unroll
        for (int ks = 0; ks < 2; ks++) {
            uint32_t kb = ks * 32;   // 16 bf16 = 32B per k-step
            uint32_t bh[4][2], bl[4][2];
#pragma unroll
            for (int nt = 0; nt < 4; nt++) {
                uint32_t boff = b_off + nt * 8 * ROWB + kb;
                LDSM2(bh[nt], Bh + boff);
                LDSM2(bl[nt], Bl + boff);
            }
#pragma unroll
            for (int mt = 0; mt < 4; mt++) {
                uint32_t ah[4], al[4];
                uint32_t aoff = a_off + mt * 16 * ROWB + kb;
                LDSM4(ah, Ah + aoff);
                LDSM4(al, Al + aoff);
#pragma unroll
                for (int nt = 0; nt < 4; nt++) {
                    MMA16816(acc[mt][nt], ah, bh[nt]);
                    MMA16816(acc[mt][nt], ah, bl[nt]);
                    MMA16816(acc[mt][nt], al, bh[nt]);
                }
            }
        }
        __syncthreads();
    }

    // epilogue: d0,d1 -> (row, col..col+1); d2,d3 -> (row+8, col..col+1)
    float* out = g_scratch + (size_t)z * SEQ * EMB;
    const int rbase = m0 + warp_m * 64 + (lane >> 2);
    const int cbase = n0 + warp_n * 32 + ((lane & 3) << 1);
#pragma unroll
    for (int mt = 0; mt < 4; mt++) {
#pragma unroll
        for (int nt = 0; nt < 4; nt++) {
            int r0 = rbase + mt * 16;
            int c  = cbase + nt * 8;
            if (r0 < SEQ)
                *(float2*)(out + (size_t)r0 * EMB + c) = make_float2(acc[mt][nt][0], acc[mt][nt][1]);
            if (r0 + 8 < SEQ)
                *(float2*)(out + (size_t)(r0 + 8) * EMB + c) = make_float2(acc[mt][nt][2], acc[mt][nt][3]);
        }
    }
}

// ---------------- canonical 128x128x8 FFMA SGEMM (x-embed / QKV / out-proj) ----------------
template<int MODE>
__global__ void __launch_bounds__(256, 2)
sgemm_k(const float* __restrict__ A, const float* __restrict__ B,
        float* __restrict__ C, const float* __restrict__ bias,
        const float* __restrict__ maskf,
        int M, int N, int Ktot, int imgC)
{
    __shared__ float As[8][128];
    __shared__ float Bs[8][128];

    const int tid = threadIdx.x;
    const int m0 = blockIdx.y * 128;
    const int n0 = blockIdx.x * 128;

    const int aM = tid >> 1;
    const int aQ = (tid & 1) << 2;
    const int bN = tid >> 1;
    const int bQ = (tid & 1) << 2;
    const int trow = (tid >> 4) << 3;
    const int tcol = (tid & 15) << 3;

    float acc[8][8];
#pragma unroll
    for (int i = 0; i < 8; i++)
#pragma unroll
        for (int j = 0; j < 8; j++) acc[i][j] = 0.0f;

    const int am = m0 + aM;
    const bool mvalid = (am < M);

    const float* arow = A;
    if (MODE == 1 && mvalid) {
        int v = am / SEQ;
        int s = am % SEQ;
        int gh = s / GW, gw = s % GW;
        arow = A + ((size_t)(v * imgC) * IMG_H + gh * PS) * IMG_W + gw * PS;
    }
    const float* Bp = B + (size_t)(n0 + bN) * Ktot + bQ;
    const float* Ap = (MODE == 0) ? (A + (size_t)am * Ktot + aQ) : nullptr;

    for (int kk = 0; kk < Ktot; kk += 8) {
        float4 av = make_float4(0.f, 0.f, 0.f, 0.f);
        if (MODE == 0) {
            if (mvalid) av = *(const float4*)Ap;
            Ap += 8;
        } else {
            if (mvalid) {
                int k = kk + aQ;
                int c = k >> 8;
                int rem = k & 255;
                int i = rem >> 4, j = rem & 15;
                av = *(const float4*)(arow + ((size_t)c * IMG_H + i) * IMG_W + j);
            }
        }
        As[aQ + 0][aM] = av.x;
        As[aQ + 1][aM] = av.y;
        As[aQ + 2][aM] = av.z;
        As[aQ + 3][aM] = av.w;

        float4 bv = *(const float4*)Bp;
        Bp += 8;
        Bs[bQ + 0][bN] = bv.x;
        Bs[bQ + 1][bN] = bv.y;
        Bs[bQ + 2][bN] = bv.z;
        Bs[bQ + 3][bN] = bv.w;

        __syncthreads();
#pragma unroll
        for (int k = 0; k < 8; k++) {
            float4 a0 = *(const float4*)&As[k][trow];
            float4 a1 = *(const float4*)&As[k][trow + 4];
            float4 b0 = *(const float4*)&Bs[k][tcol];
            float4 b1 = *(const float4*)&Bs[k][tcol + 4];
            float ar[8] = {a0.x, a0.y, a0.z, a0.w, a1.x, a1.y, a1.z, a1.w};
            float br[8] = {b0.x, b0.y, b0.z, b0.w, b1.x, b1.y, b1.z, b1.w};
#pragma unroll
            for (int i = 0; i < 8; i++)
#pragma unroll
                for (int j = 0; j < 8; j++) acc[i][j] += ar[i] * br[j];
        }
        __syncthreads();
    }

#pragma unroll
    for (int i = 0; i < 8; i++) {
        int m = m0 + trow + i;
        if (m >= M) break;
        float mk = (maskf != nullptr) ? maskf[m % SEQ] : 1.0f;
        float* crow = C + (size_t)m * N + n0 + tcol;
#pragma unroll
        for (int j = 0; j < 8; j += 4) {
            float4 r;
            r.x = (acc[i][j + 0] + bias[n0 + tcol + j + 0]) * mk;
            r.y = (acc[i][j + 1] + bias[n0 + tcol + j + 1]) * mk;
            r.z = (acc[i][j + 2] + bias[n0 + tcol + j + 2]) * mk;
            r.w = (acc[i][j + 3] + bias[n0 + tcol + j + 3]) * mk;
            *(float4*)(crow + j) = r;
        }
    }
}

// ---------------- reduce split-K pe partials + bias + mask ----------------
__global__ void reduce_pe_kernel(const float* __restrict__ bias,
                                 const float* __restrict__ maskf) {
    int idx = blockIdx.x * blockDim.x + threadIdx.x;
    if (idx >= SEQ * EMB) return;
    int n = idx % EMB;
    int m = idx / EMB;
    float acc = bias[n];
#pragma unroll
    for (int z = 0; z < SPLITK; z++) acc += g_scratch[(size_t)z * SEQ * EMB + idx];
    g_pe_tok[idx] = acc * maskf[m];
}

// ---------------- q/k prep, landmarks, attention core ----------------
__device__ __forceinline__ float block64_sum(float v, float* red2) {
    for (int off = 16; off > 0; off >>= 1)
        v += __shfl_xor_sync(0xffffffffu, v, off);
    if ((threadIdx.x & 31) == 0) red2[threadIdx.x >> 5] = v;
    __syncthreads();
    return red2[0] + red2[1];
}

__global__ void prep_q_kernel(const int* __restrict__ ftag) {
    int s = blockIdx.x, h = blockIdx.y, e = threadIdx.x;
    int ft = ftag[0];
    float val = g_qkv[((size_t)(ft * SEQ + s)) * (3 * EMB) + h * (3 * HD) + e]
              + g_pe_tok[(size_t)s * EMB + h * HD + e];
    __shared__ float red2[2];
    float tot = block64_sum(val * val, red2);
    float denom = fmaxf(sqrtf(tot), 1e-12f);
    g_qn[((size_t)h * SEQ + s) * HD + e] = val / denom;
}

__global__ void prep_k_kernel(const int* __restrict__ ftag) {
    int t = blockIdx.x, h = blockIdx.y, e = threadIdx.x;
    int ft = ftag[0];
    int vi = t / SEQ;
    int view = (vi < ft) ? vi : vi + 1;
    int s = t % SEQ;
    size_t base = ((size_t)(view * SEQ + s)) * (3 * EMB) + h * (3 * HD);
    float kval = g_qkv[base + HD + e];
    float vval = g_qkv[base + 2 * HD + e];
    __shared__ float red2[2];
    float tot = block64_sum(kval * kval, red2);
    float denom = fmaxf(sqrtf(tot), 1e-12f);
    g_kn[((size_t)h * KSEQ + t) * HD + e] = kval / denom;
    g_vc[((size_t)h * KSEQ + t) * HD + e] = vval;
}

__global__ void landmark_kernel(const float* __restrict__ src, float* __restrict__ dst, int seg) {
    int l = blockIdx.x, h = blockIdx.y, e = threadIdx.x;
    int S = LM * seg;
    const float* p = src + ((size_t)h * S + (size_t)l * seg) * HD + e;
    float acc = 0.f;
    for (int r = 0; r < seg; r++) acc += p[(size_t)r * HD];
    dst[((size_t)h * LM + l) * HD + e] = acc / (float)seg;
}

__global__ void a1_kernel() {
    int warp = threadIdx.x >> 5, lane = threadIdx.x & 31;
    int s = blockIdx.x * 4 + warp;
    int h = blockIdx.y;
    const float* qp = g_qn + ((size_t)h * SEQ + s) * HD;
    float q0 = qp[lane], q1 = qp[lane + 32];
    float lg[LM];
#pragma unroll
    for (int l = 0; l < LM; l++) {
        const float* kp = g_kL + ((size_t)h * LM + l) * HD;
        float p = q0 * kp[lane] + q1 * kp[lane + 32];
        for (int off = 16; off > 0; off >>= 1)
            p += __shfl_xor_sync(0xffffffffu, p, off);
        lg[l] = p * SCALE;
    }
    float mx = lg[0];
#pragma unroll
    for (int l = 1; l < LM; l++) mx = fmaxf(mx, lg[l]);
    float sum = 0.f;
#pragma unroll
    for (int l = 0; l < LM; l++) { lg[l] = expf(lg[l] - mx); sum += lg[l]; }
    float inv = 1.0f / sum;
    if (lane < LM)
        g_a1[((size_t)h * SEQ + s) * LM + lane] = lg[lane] * inv;
}

__global__ void a2_kernel() {
    int l = blockIdx.x, h = blockIdx.y, tid = threadIdx.x;
    __shared__ float sq[HD];
    __shared__ float lg[KSEQ];
    __shared__ float red[256];
    if (tid < HD) sq[tid] = g_qL[((size_t)h * LM + l) * HD + tid];
    __syncthreads();

    for (int t = tid; t < KSEQ; t += 256) {
        const float* kp = g_kn + ((size_t)h * KSEQ + t) * HD;
        float d = 0.f;
#pragma unroll
        for (int e = 0; e < HD; e += 4) {
            float4 kv = *(const float4*)(kp + e);
            d += kv.x * sq[e] + kv.y * sq[e + 1] + kv.z * sq[e + 2] + kv.w * sq[e + 3];
        }
        lg[t] = d * SCALE;
    }
    __syncthreads();

    float lmax = -1e30f;
    for (int t = tid; t < KSEQ; t += 256) lmax = fmaxf(lmax, lg[t]);
    red[tid] = lmax;
    __syncthreads();
    for (int off = 128; off > 0; off >>= 1) {
        if (tid < off) red[tid] = fmaxf(red[tid], red[tid + off]);
        __syncthreads();
    }
    float gmax = red[0];
    __syncthreads();

    float lsum = 0.f;
    for (int t = tid; t < KSEQ; t += 256) {
        float e = expf(lg[t] - gmax);
        lg[t] = e;
        lsum += e;
    }
    red[tid] = lsum;
    __syncthreads();
    for (int off = 128; off > 0; off >>= 1) {
        if (tid < off) red[tid] += red[tid + off];
        __syncthreads();
    }
    float inv = 1.0f / red[0];
    float* out = g_a2 + ((size_t)h * LM + l) * KSEQ;
    for (int t = tid; t < KSEQ; t += 256) out[t] = lg[t] * inv;
}

__global__ void a2v_kernel() {
    int l = blockIdx.x, h = blockIdx.y, e = threadIdx.x;
    const float* ar = g_a2 + ((size_t)h * LM + l) * KSEQ;
    const float* vp = g_vc + (size_t)h * KSEQ * HD + e;
    float acc = 0.f;
#pragma unroll 4
    for (int t = 0; t < KSEQ; t++) acc += ar[t] * vp[(size_t)t * HD];
    g_a2v[((size_t)h * LM + l) * HD + e] = acc;
}

__global__ void vals_kernel() {
    int s = blockIdx.x;
    int h = threadIdx.x >> 6;
    int e = threadIdx.x & 63;
    const float* ap = g_a1 + ((size_t)h * SEQ + s) * LM;
    const float* bp = g_a2v + (size_t)h * LM * HD + e;
    float acc = 0.f;
#pragma unroll
    for (int l = 0; l < LM; l++) acc += ap[l] * bp[(size_t)l * HD];
    g_xout[(size_t)s * EMB + h * HD + e] = acc;
}

// ---------------- launch ----------------
extern "C" void kernel_launch(void* const* d_in, const int* in_sizes, int n_in,
                              void* d_out, int out_size) {
    const float* x         = (const float*)d_in[0];
    const float* pe        = (const float*)d_in[1];
    const float* mask_map  = (const float*)d_in[2];
    const float* conv_in_w = (const float*)d_in[3];
    const float* conv_in_b = (const float*)d_in[4];
    const float* conv_pe_w = (const float*)d_in[5];
    const float* conv_pe_b = (const float*)d_in[6];
    const float* qkv_w     = (const float*)d_in[7];
    const float* qkv_b     = (const float*)d_in[8];
    const float* o_w       = (const float*)d_in[9];
    const float* o_b       = (const float*)d_in[10];
    const int*   ftag      = (const int*)d_in[11];

    float* maskf_p;   cudaGetSymbolAddress((void**)&maskf_p,   g_maskf);
    float* tokens_p;  cudaGetSymbolAddress((void**)&tokens_p,  g_tokens);
    float* qkv_p;     cudaGetSymbolAddress((void**)&qkv_p,     g_qkv);
    float* xout_p;    cudaGetSymbolAddress((void**)&xout_p,    g_xout);
    float* qn_p;      cudaGetSymbolAddress((void**)&qn_p,      g_qn);
    float* kn_p;      cudaGetSymbolAddress((void**)&kn_p,      g_kn);
    float* qL_p;      cudaGetSymbolAddress((void**)&qL_p,      g_qL);
    float* kL_p;      cudaGetSymbolAddress((void**)&kL_p,      g_kL);

    // 1. patch mask
    mask_kernel<<<SEQ, 256>>>(mask_map, maskf_p);

    // 2. bf16 hi/lo conversion of pe im2col (A) and conv_pe_w (B)
    conv_a_kernel<<<(MPAD * (K_PE / 4)) / 256, 256>>>(pe, ftag);
    conv_b_kernel<<<(int)(((size_t)EMB * K_PE / 4) / 256), 256>>>(conv_pe_w);

    // 3. pe GEMM via mma.sync bf16 (3-pass, split-K=32 into g_scratch)
    static int smem_set = 0;
    if (!smem_set) {
        cudaFuncSetAttribute(pe_gemm_kernel, cudaFuncAttributeMaxDynamicSharedMemorySize, 2 * STAGEB);
        smem_set = 1;
    }
    pe_gemm_kernel<<<dim3(EMB / 128, MPAD / 128, SPLITK), 256, 2 * STAGEB>>>();

    // 4. reduce split-K + bias + mask -> pe_tok
    reduce_pe_kernel<<<(SEQ * EMB + 255) / 256, 256>>>(conv_pe_b, maskf_p);

    // 5. x patch embed -> tokens (4224 x 512, K=768)
    sgemm_k<1><<<dim3(EMB / 128, MQ / 128, 1), 256>>>(
        x, conv_in_w, tokens_p, conv_in_b, maskf_p, MQ, EMB, K_X, 3);

    // 6. QKV: tokens @ qkv_w^T + b  (4224 x 1536, K=512)
    sgemm_k<0><<<dim3((3 * EMB) / 128, MQ / 128, 1), 256>>>(
        tokens_p, qkv_w, qkv_p, qkv_b, nullptr, MQ, 3 * EMB, EMB, 0);

    // 7. normalized q (+pe) and k, raw v gather
    prep_q_kernel<<<dim3(SEQ, NHEADS), HD>>>(ftag);
    prep_k_kernel<<<dim3(KSEQ, NHEADS), HD>>>(ftag);

    // 8. landmarks
    landmark_kernel<<<dim3(LM, NHEADS), HD>>>(qn_p, qL_p, SEQ / LM);
    landmark_kernel<<<dim3(LM, NHEADS), HD>>>(kn_p, kL_p, KSEQ / LM);

    // 9. attention core
    a1_kernel<<<dim3(SEQ / 4, NHEADS), 128>>>();
    a2_kernel<<<dim3(LM, NHEADS), 256>>>();
    a2v_kernel<<<dim3(LM, NHEADS), HD>>>();
    vals_kernel<<<SEQ, EMB>>>();

    // 10. output projection -> d_out (704 x 512)
    sgemm_k<0><<<dim3(EMB / 128, (SEQ + 127) / 128, 1), 256>>>(
        xout_p, o_w, (float*)d_out, o_b, nullptr, SEQ, EMB, EMB, 0);
}

// round 12
// speedup vs baseline: 1.3595x; 1.3578x over previous
#include <cuda_runtime.h>
#include <cuda_bf16.h>
#include <math.h>
#include <cstdint>

// ---------------- problem constants ----------------
#define NHEADS 8
#define HD 64
#define EMB 512
#define PS 16
#define GH 16
#define GW 44
#define SEQ 704            // GH*GW
#define NVIEW 6
#define MQ (NVIEW*SEQ)     // 4224
#define LM 16              // landmarks
#define KSEQ (5*SEQ)       // 3520
#define SCALE 0.125f       // 1/sqrt(64)

#define PE_C 256
#define IMG_H 256
#define IMG_W 704
#define K_PE (PE_C*PS*PS)  // 65536
#define K_X  (3*PS*PS)     // 768

#define MPAD 768           // 704 padded to 6x128
#define SPLITK 32
#define KSLICE (K_PE / SPLITK)   // 2048
#define KS 32                    // K per stage

// smem tile geometry: rows stored with 40-element (80B) stride for
// conflict-free ldmatrix; 128 rows x 32 bf16 -> 10240 B per tile.
#define ROWB 80
#define TILEB (128 * ROWB)       // 10240
#define STAGEB (4 * TILEB)       // 40960 (Ahi, Alo, Bhi, Blo)

// ---------------- scratch (device globals, no cudaMalloc) ----------------
__device__ float g_maskf[SEQ];
__device__ float g_qkv[MQ * 3 * EMB];
__device__ float g_scratch[SPLITK * SEQ * EMB];
__device__ float g_pe_tok[SEQ * EMB];
__device__ float g_qn[NHEADS * SEQ * HD];
__device__ float g_kn[NHEADS * KSEQ * HD];
__device__ float g_vc[NHEADS * KSEQ * HD];
__device__ float g_qL[NHEADS * LM * HD];
__device__ float g_kL[NHEADS * LM * HD];
__device__ float g_a1[NHEADS * SEQ * LM];
__device__ float g_a2[NHEADS * LM * KSEQ];
__device__ float g_a2v[NHEADS * LM * HD];
__device__ float g_xout[SEQ * EMB];

// bf16 hi/lo split operands
__device__ __nv_bfloat16 g_Ahi[(size_t)MPAD * K_PE];       // pe im2col
__device__ __nv_bfloat16 g_Alo[(size_t)MPAD * K_PE];
__device__ __nv_bfloat16 g_Bhi[(size_t)EMB * K_PE];        // conv_pe_w
__device__ __nv_bfloat16 g_Blo[(size_t)EMB * K_PE];
__device__ __nv_bfloat16 g_Axhi[(size_t)MQ * K_X];         // x im2col
__device__ __nv_bfloat16 g_Axlo[(size_t)MQ * K_X];
__device__ __nv_bfloat16 g_Bxhi[(size_t)EMB * K_X];        // conv_in_w
__device__ __nv_bfloat16 g_Bxlo[(size_t)EMB * K_X];
__device__ __nv_bfloat16 g_Tokhi[(size_t)MQ * EMB];        // tokens (x-embed out)
__device__ __nv_bfloat16 g_Toklo[(size_t)MQ * EMB];
__device__ __nv_bfloat16 g_Bqhi[(size_t)(3 * EMB) * EMB];  // qkv_w
__device__ __nv_bfloat16 g_Bqlo[(size_t)(3 * EMB) * EMB];

// ======================= PTX helpers (compute_103-safe) =======================
__device__ __forceinline__ uint32_t smem_u32(const void* p) {
    uint32_t a;
    asm("{ .reg .u64 t; cvta.to.shared.u64 t, %1; cvt.u32.u64 %0, t; }"
        : "=r"(a) : "l"(p));
    return a;
}

#define CP_ASYNC16(sp, gp) \
    asm volatile("cp.async.cg.shared.global [%0], [%1], 16;\n" :: "r"(sp), "l"(gp) : "memory")
#define CP_COMMIT() asm volatile("cp.async.commit_group;\n" ::: "memory")
#define CP_WAIT(n)  asm volatile("cp.async.wait_group %0;\n" :: "n"(n) : "memory")

#define LDSM4(r, addr) \
    asm volatile("ldmatrix.sync.aligned.m8n8.x4.shared.b16 {%0,%1,%2,%3}, [%4];" \
        : "=r"((r)[0]), "=r"((r)[1]), "=r"((r)[2]), "=r"((r)[3]) : "r"(addr))
#define LDSM2(r, addr) \
    asm volatile("ldmatrix.sync.aligned.m8n8.x2.shared.b16 {%0,%1}, [%2];" \
        : "=r"((r)[0]), "=r"((r)[1]) : "r"(addr))

#define MMA16816(d, a, b) \
    asm volatile("mma.sync.aligned.m16n8k16.row.col.f32.bf16.bf16.f32 " \
        "{%0,%1,%2,%3}, {%4,%5,%6,%7}, {%8,%9}, {%0,%1,%2,%3};" \
        : "+f"((d)[0]), "+f"((d)[1]), "+f"((d)[2]), "+f"((d)[3]) \
        : "r"((a)[0]), "r"((a)[1]), "r"((a)[2]), "r"((a)[3]), "r"((b)[0]), "r"((b)[1]))

// ---------------- patch mask: 16x16 avg pool > 0 ----------------
__global__ void mask_kernel(const float* __restrict__ mask_map, float* __restrict__ maskf) {
    int p = blockIdx.x;
    int gh = p / GW, gw = p % GW;
    int i = threadIdx.x >> 4, j = threadIdx.x & 15;
    float v = mask_map[(gh * PS + i) * IMG_W + gw * PS + j];
    __shared__ float red[256];
    red[threadIdx.x] = v;
    __syncthreads();
    for (int off = 128; off > 0; off >>= 1) {
        if (threadIdx.x < off) red[threadIdx.x] += red[threadIdx.x + off];
        __syncthreads();
    }
    if (threadIdx.x == 0) maskf[p] = (red[0] > 0.0f) ? 1.0f : 0.0f;
}

// ---------------- bf16 hi/lo conversion kernels ----------------
__device__ __forceinline__ void split4(float4 v, uint2& hi, uint2& lo) {
    __nv_bfloat16 h0 = __float2bfloat16(v.x);
    __nv_bfloat16 h1 = __float2bfloat16(v.y);
    __nv_bfloat16 h2 = __float2bfloat16(v.z);
    __nv_bfloat16 h3 = __float2bfloat16(v.w);
    __nv_bfloat16 l0 = __float2bfloat16(v.x - __bfloat162float(h0));
    __nv_bfloat16 l1 = __float2bfloat16(v.y - __bfloat162float(h1));
    __nv_bfloat16 l2 = __float2bfloat16(v.z - __bfloat162float(h2));
    __nv_bfloat16 l3 = __float2bfloat16(v.w - __bfloat162float(h3));
    __nv_bfloat162 ph0; ph0.x = h0; ph0.y = h1;
    __nv_bfloat162 ph1; ph1.x = h2; ph1.y = h3;
    __nv_bfloat162 pl0; pl0.x = l0; pl0.y = l1;
    __nv_bfloat162 pl1; pl1.x = l2; pl1.y = l3;
    hi.x = *reinterpret_cast<uint32_t*>(&ph0);
    hi.y = *reinterpret_cast<uint32_t*>(&ph1);
    lo.x = *reinterpret_cast<uint32_t*>(&pl0);
    lo.y = *reinterpret_cast<uint32_t*>(&pl1);
}

// pe A = im2col(pe[ft]) -> [MPAD][K_PE], rows >= SEQ zero
__global__ void conv_a_kernel(const float* __restrict__ pe, const int* __restrict__ ftag) {
    size_t idx = (size_t)blockIdx.x * 256 + threadIdx.x;
    int m = (int)(idx >> 14);               // K_PE/4 = 16384 chunks per row
    int kq = ((int)idx & 16383) << 2;
    float4 v = make_float4(0.f, 0.f, 0.f, 0.f);
    if (m < SEQ) {
        int c = kq >> 8, rem = kq & 255, i = rem >> 4, j = rem & 15;
        int gh = m / GW, gw = m % GW;
        const float* src = pe + (size_t)ftag[0] * PE_C * IMG_H * IMG_W
                              + ((size_t)c * IMG_H + gh * PS + i) * IMG_W + gw * PS + j;
        v = *(const float4*)src;
    }
    uint2 hi, lo;
    split4(v, hi, lo);
    size_t off = (size_t)m * K_PE + kq;
    *(uint2*)(g_Ahi + off) = hi;
    *(uint2*)(g_Alo + off) = lo;
}

// x A = im2col(x, all 6 views) -> [MQ][K_X]
__global__ void conv_ax_kernel(const float* __restrict__ x) {
    size_t idx = (size_t)blockIdx.x * 256 + threadIdx.x;  // per 4 elems
    int m = (int)(idx / (K_X / 4));
    int kq = ((int)(idx % (K_X / 4))) << 2;
    int c = kq >> 8, rem = kq & 255, i = rem >> 4, j = rem & 15;
    int v6 = m / SEQ, s = m % SEQ;
    int gh = s / GW, gw = s % GW;
    const float* src = x + (((size_t)(v6 * 3 + c)) * IMG_H + gh * PS + i) * IMG_W + gw * PS + j;
    float4 v = *(const float4*)src;
    uint2 hi, lo;
    split4(v, hi, lo);
    size_t off = (size_t)m * K_X + kq;
    *(uint2*)(g_Axhi + off) = hi;
    *(uint2*)(g_Axlo + off) = lo;
}

// generic weight split: row-major [n][k] fp32 -> bf16 hi/lo
__global__ void conv_w_kernel(const float* __restrict__ w,
                              __nv_bfloat16* __restrict__ whi,
                              __nv_bfloat16* __restrict__ wlo) {
    size_t idx = (size_t)blockIdx.x * 256 + threadIdx.x;
    size_t off = idx << 2;
    float4 v = *(const float4*)(w + off);
    uint2 hi, lo;
    split4(v, hi, lo);
    *(uint2*)(whi + off) = hi;
    *(uint2*)(wlo + off) = lo;
}

// ---------------- unified bf16 3-pass mma GEMM ----------------
// CTA tile M=128, N=128, K-stage 32, double-buffered cp.async.
// EPI 0: write fp32 to outf + z*SEQ*Nld, rows guarded by Mvalid (pe split-K)
// EPI 1: (acc+bias)*mask -> bf16 hi/lo outputs (x-embed -> tokens)
// EPI 2: acc+bias -> fp32 (QKV)
__device__ __forceinline__ void load_stage_g(
    uint32_t smbuf,
    const __nv_bfloat16* __restrict__ Ahi, const __nv_bfloat16* __restrict__ Alo,
    const __nv_bfloat16* __restrict__ Bhi, const __nv_bfloat16* __restrict__ Blo,
    int m0, int n0, int koff, int Ktot, int tid)
{
#pragma unroll
    for (int it = 0; it < 8; it++) {
        int f = it * 256 + tid;        // 0..2047 chunks of 16B
        int tile = f >> 9;             // 0:Ahi 1:Alo 2:Bhi 3:Blo
        int idx = f & 511;
        int row = idx >> 2;
        int q = idx & 3;
        const __nv_bfloat16* g;
        int r0;
        if (tile == 0)      { g = Ahi; r0 = m0; }
        else if (tile == 1) { g = Alo; r0 = m0; }
        else if (tile == 2) { g = Bhi; r0 = n0; }
        else                { g = Blo; r0 = n0; }
        const __nv_bfloat16* gp = g + (size_t)(r0 + row) * Ktot + koff + q * 8;
        uint32_t sp = smbuf + tile * TILEB + row * ROWB + q * 16;
        CP_ASYNC16(sp, gp);
    }
    CP_COMMIT();
}

template<int EPI>
__global__ void __launch_bounds__(256, 2) mma_gemm(
    const __nv_bfloat16* __restrict__ Ahi, const __nv_bfloat16* __restrict__ Alo,
    const __nv_bfloat16* __restrict__ Bhi, const __nv_bfloat16* __restrict__ Blo,
    int Ktot, int kslice,
    float* __restrict__ outf,
    __nv_bfloat16* __restrict__ outhi, __nv_bfloat16* __restrict__ outlo,
    const float* __restrict__ bias, const float* __restrict__ maskf,
    int Nld, int Mvalid)
{
    extern __shared__ __align__(128) char dsm[];
    const uint32_t base = smem_u32(dsm);
    const int tid = threadIdx.x;
    const int wid = tid >> 5, lane = tid & 31;
    const int warp_m = wid >> 2;
    const int warp_n = wid & 3;
    const int n0 = blockIdx.x * 128;
    const int m0 = blockIdx.y * 128;
    const int kbase = blockIdx.z * kslice;
    const int nstage = kslice / KS;

    float acc[4][4][4];
#pragma unroll
    for (int i = 0; i < 4; i++)
#pragma unroll
        for (int j = 0; j < 4; j++)
#pragma unroll
            for (int c = 0; c < 4; c++) acc[i][j][c] = 0.0f;

    const uint32_t a_off = (uint32_t)((warp_m * 64 + (lane & 15)) * ROWB + ((lane >> 4) << 4));
    const uint32_t b_off = (uint32_t)((warp_n * 32 + (lane & 7)) * ROWB + (((lane >> 3) & 1) << 4));

    load_stage_g(base, Ahi, Alo, Bhi, Blo, m0, n0, kbase, Ktot, tid);

#pragma unroll 1
    for (int s = 0; s < nstage; s++) {
        uint32_t cb = base + (s & 1) * STAGEB;
        if (s + 1 < nstage) {
            load_stage_g(base + ((s + 1) & 1) * STAGEB, Ahi, Alo, Bhi, Blo,
                         m0, n0, kbase + (s + 1) * KS, Ktot, tid);
            CP_WAIT(1);
        } else {
            CP_WAIT(0);
        }
        __syncthreads();

        const uint32_t Ah = cb;
        const uint32_t Al = cb + TILEB;
        const uint32_t Bh = cb + 2 * TILEB;
        const uint32_t Bl = cb + 3 * TILEB;

#pragma unroll
        for (int ks = 0; ks < 2; ks++) {
            uint32_t kb = ks * 32;
            uint32_t bh[4][2], bl[4][2];
#pragma unroll
            for (int nt = 0; nt < 4; nt++) {
                uint32_t boff = b_off + nt * 8 * ROWB + kb;
                LDSM2(bh[nt], Bh + boff);
                LDSM2(bl[nt], Bl + boff);
            }
#pragma unroll
            for (int mt = 0; mt < 4; mt++) {
                uint32_t ah[4], al[4];
                uint32_t aoff = a_off + mt * 16 * ROWB + kb;
                LDSM4(ah, Ah + aoff);
                LDSM4(al, Al + aoff);
#pragma unroll
                for (int nt = 0; nt < 4; nt++) {
                    MMA16816(acc[mt][nt], ah, bh[nt]);
                    MMA16816(acc[mt][nt], ah, bl[nt]);
                    MMA16816(acc[mt][nt], al, bh[nt]);
                }
            }
        }
        __syncthreads();
    }

    // epilogue
    float* out = outf;
    if (EPI == 0) out += (size_t)blockIdx.z * SEQ * (size_t)Nld;
    const int rbase = m0 + warp_m * 64 + (lane >> 2);
    const int cbase = n0 + warp_n * 32 + ((lane & 3) << 1);
#pragma unroll
    for (int mt = 0; mt < 4; mt++) {
#pragma unroll
        for (int nt = 0; nt < 4; nt++) {
            int r0 = rbase + mt * 16;
            int r1 = r0 + 8;
            int c  = cbase + nt * 8;
            if (EPI == 0) {
                if (r0 < Mvalid)
                    *(float2*)(out + (size_t)r0 * Nld + c) = make_float2(acc[mt][nt][0], acc[mt][nt][1]);
                if (r1 < Mvalid)
                    *(float2*)(out + (size_t)r1 * Nld + c) = make_float2(acc[mt][nt][2], acc[mt][nt][3]);
            } else if (EPI == 1) {
                float b0 = bias[c], b1 = bias[c + 1];
                float mk0 = maskf[r0 % SEQ];
                float mk1 = maskf[r1 % SEQ];
                float v0 = (acc[mt][nt][0] + b0) * mk0;
                float v1 = (acc[mt][nt][1] + b1) * mk0;
                float v2 = (acc[mt][nt][2] + b0) * mk1;
                float v3 = (acc[mt][nt][3] + b1) * mk1;
                __nv_bfloat16 h0 = __float2bfloat16(v0), h1 = __float2bfloat16(v1);
                __nv_bfloat16 h2 = __float2bfloat16(v2), h3 = __float2bfloat16(v3);
                __nv_bfloat162 hh0; hh0.x = h0; hh0.y = h1;
                __nv_bfloat162 hh1; hh1.x = h2; hh1.y = h3;
                __nv_bfloat162 ll0;
                ll0.x = __float2bfloat16(v0 - __bfloat162float(h0));
                ll0.y = __float2bfloat16(v1 - __bfloat162float(h1));
                __nv_bfloat162 ll1;
                ll1.x = __float2bfloat16(v2 - __bfloat162float(h2));
                ll1.y = __float2bfloat16(v3 - __bfloat162float(h3));
                *(__nv_bfloat162*)(outhi + (size_t)r0 * Nld + c) = hh0;
                *(__nv_bfloat162*)(outlo + (size_t)r0 * Nld + c) = ll0;
                *(__nv_bfloat162*)(outhi + (size_t)r1 * Nld + c) = hh1;
                *(__nv_bfloat162*)(outlo + (size_t)r1 * Nld + c) = ll1;
            } else {
                float b0 = bias[c], b1 = bias[c + 1];
                *(float2*)(outf + (size_t)r0 * Nld + c) =
                    make_float2(acc[mt][nt][0] + b0, acc[mt][nt][1] + b1);
                *(float2*)(outf + (size_t)r1 * Nld + c) =
                    make_float2(acc[mt][nt][2] + b0, acc[mt][nt][3] + b1);
            }
        }
    }
}

// ---------------- fp32 FFMA SGEMM (out-proj only) ----------------
__global__ void __launch_bounds__(256, 2)
sgemm_f32(const float* __restrict__ A, const float* __restrict__ B,
          float* __restrict__ C, const float* __restrict__ bias,
          int M, int N, int Ktot)
{
    __shared__ float As[8][128];
    __shared__ float Bs[8][128];

    const int tid = threadIdx.x;
    const int m0 = blockIdx.y * 128;
    const int n0 = blockIdx.x * 128;

    const int aM = tid >> 1;
    const int aQ = (tid & 1) << 2;
    const int trow = (tid >> 4) << 3;
    const int tcol = (tid & 15) << 3;

    float acc[8][8];
#pragma unroll
    for (int i = 0; i < 8; i++)
#pragma unroll
        for (int j = 0; j < 8; j++) acc[i][j] = 0.0f;

    const int am = m0 + aM;
    const bool mvalid = (am < M);
    const float* Bp = B + (size_t)(n0 + aM) * Ktot + aQ;
    const float* Ap = A + (size_t)am * Ktot + aQ;

    for (int kk = 0; kk < Ktot; kk += 8) {
        float4 av = make_float4(0.f, 0.f, 0.f, 0.f);
        if (mvalid) av = *(const float4*)Ap;
        Ap += 8;
        As[aQ + 0][aM] = av.x;
        As[aQ + 1][aM] = av.y;
        As[aQ + 2][aM] = av.z;
        As[aQ + 3][aM] = av.w;

        float4 bv = *(const float4*)Bp;
        Bp += 8;
        Bs[aQ + 0][aM] = bv.x;
        Bs[aQ + 1][aM] = bv.y;
        Bs[aQ + 2][aM] = bv.z;
        Bs[aQ + 3][aM] = bv.w;

        __syncthreads();
#pragma unroll
        for (int k = 0; k < 8; k++) {
            float4 a0 = *(const float4*)&As[k][trow];
            float4 a1 = *(const float4*)&As[k][trow + 4];
            float4 b0 = *(const float4*)&Bs[k][tcol];
            float4 b1 = *(const float4*)&Bs[k][tcol + 4];
            float ar[8] = {a0.x, a0.y, a0.z, a0.w, a1.x, a1.y, a1.z, a1.w};
            float br[8] = {b0.x, b0.y, b0.z, b0.w, b1.x, b1.y, b1.z, b1.w};
#pragma unroll
            for (int i = 0; i < 8; i++)
#pragma unroll
                for (int j = 0; j < 8; j++) acc[i][j] += ar[i] * br[j];
        }
        __syncthreads();
    }

#pragma unroll
    for (int i = 0; i < 8; i++) {
        int m = m0 + trow + i;
        if (m >= M) break;
        float* crow = C + (size_t)m * N + n0 + tcol;
#pragma unroll
        for (int j = 0; j < 8; j += 4) {
            float4 r;
            r.x = acc[i][j + 0] + bias[n0 + tcol + j + 0];
            r.y = acc[i][j + 1] + bias[n0 + tcol + j + 1];
            r.z = acc[i][j + 2] + bias[n0 + tcol + j + 2];
            r.w = acc[i][j + 3] + bias[n0 + tcol + j + 3];
            *(float4*)(crow + j) = r;
        }
    }
}

// ---------------- reduce split-K pe partials + bias + mask ----------------
__global__ void reduce_pe_kernel(const float* __restrict__ bias,
                                 const float* __restrict__ maskf) {
    int idx = blockIdx.x * blockDim.x + threadIdx.x;
    if (idx >= SEQ * EMB) return;
    int n = idx % EMB;
    int m = idx / EMB;
    float acc = bias[n];
#pragma unroll
    for (int z = 0; z < SPLITK; z++) acc += g_scratch[(size_t)z * SEQ * EMB + idx];
    g_pe_tok[idx] = acc * maskf[m];
}

// ---------------- q/k prep, landmarks, attention core ----------------
__device__ __forceinline__ float block64_sum(float v, float* red2) {
    for (int off = 16; off > 0; off >>= 1)
        v += __shfl_xor_sync(0xffffffffu, v, off);
    if ((threadIdx.x & 31) == 0) red2[threadIdx.x >> 5] = v;
    __syncthreads();
    return red2[0] + red2[1];
}

__global__ void prep_q_kernel(const int* __restrict__ ftag) {
    int s = blockIdx.x, h = blockIdx.y, e = threadIdx.x;
    int ft = ftag[0];
    float val = g_qkv[((size_t)(ft * SEQ + s)) * (3 * EMB) + h * (3 * HD) + e]
              + g_pe_tok[(size_t)s * EMB + h * HD + e];
    __shared__ float red2[2];
    float tot = block64_sum(val * val, red2);
    float denom = fmaxf(sqrtf(tot), 1e-12f);
    g_qn[((size_t)h * SEQ + s) * HD + e] = val / denom;
}

__global__ void prep_k_kernel(const int* __restrict__ ftag) {
    int t = blockIdx.x, h = blockIdx.y, e = threadIdx.x;
    int ft = ftag[0];
    int vi = t / SEQ;
    int view = (vi < ft) ? vi : vi + 1;
    int s = t % SEQ;
    size_t base = ((size_t)(view * SEQ + s)) * (3 * EMB) + h * (3 * HD);
    float kval = g_qkv[base + HD + e];
    float vval = g_qkv[base + 2 * HD + e];
    __shared__ float red2[2];
    float tot = block64_sum(kval * kval, red2);
    float denom = fmaxf(sqrtf(tot), 1e-12f);
    g_kn[((size_t)h * KSEQ + t) * HD + e] = kval / denom;
    g_vc[((size_t)h * KSEQ + t) * HD + e] = vval;
}

__global__ void landmark_kernel(const float* __restrict__ src, float* __restrict__ dst, int seg) {
    int l = blockIdx.x, h = blockIdx.y, e = threadIdx.x;
    int S = LM * seg;
    const float* p = src + ((size_t)h * S + (size_t)l * seg) * HD + e;
    float acc = 0.f;
    for (int r = 0; r < seg; r++) acc += p[(size_t)r * HD];
    dst[((size_t)h * LM + l) * HD + e] = acc / (float)seg;
}

__global__ void a1_kernel() {
    int warp = threadIdx.x >> 5, lane = threadIdx.x & 31;
    int s = blockIdx.x * 4 + warp;
    int h = blockIdx.y;
    const float* qp = g_qn + ((size_t)h * SEQ + s) * HD;
    float q0 = qp[lane], q1 = qp[lane + 32];
    float lg[LM];
#pragma unroll
    for (int l = 0; l < LM; l++) {
        const float* kp = g_kL + ((size_t)h * LM + l) * HD;
        float p = q0 * kp[lane] + q1 * kp[lane + 32];
        for (int off = 16; off > 0; off >>= 1)
            p += __shfl_xor_sync(0xffffffffu, p, off);
        lg[l] = p * SCALE;
    }
    float mx = lg[0];
#pragma unroll
    for (int l = 1; l < LM; l++) mx = fmaxf(mx, lg[l]);
    float sum = 0.f;
#pragma unroll
    for (int l = 0; l < LM; l++) { lg[l] = expf(lg[l] - mx); sum += lg[l]; }
    float inv = 1.0f / sum;
    if (lane < LM)
        g_a1[((size_t)h * SEQ + s) * LM + lane] = lg[lane] * inv;
}

__global__ void a2_kernel() {
    int l = blockIdx.x, h = blockIdx.y, tid = threadIdx.x;
    __shared__ float sq[HD];
    __shared__ float lg[KSEQ];
    __shared__ float red[256];
    if (tid < HD) sq[tid] = g_qL[((size_t)h * LM + l) * HD + tid];
    __syncthreads();

    for (int t = tid; t < KSEQ; t += 256) {
        const float* kp = g_kn + ((size_t)h * KSEQ + t) * HD;
        float d = 0.f;
#pragma unroll
        for (int e = 0; e < HD; e += 4) {
            float4 kv = *(const float4*)(kp + e);
            d += kv.x * sq[e] + kv.y * sq[e + 1] + kv.z * sq[e + 2] + kv.w * sq[e + 3];
        }
        lg[t] = d * SCALE;
    }
    __syncthreads();

    float lmax = -1e30f;
    for (int t = tid; t < KSEQ; t += 256) lmax = fmaxf(lmax, lg[t]);
    red[tid] = lmax;
    __syncthreads();
    for (int off = 128; off > 0; off >>= 1) {
        if (tid < off) red[tid] = fmaxf(red[tid], red[tid + off]);
        __syncthreads();
    }
    float gmax = red[0];
    __syncthreads();

    float lsum = 0.f;
    for (int t = tid; t < KSEQ; t += 256) {
        float e = expf(lg[t] - gmax);
        lg[t] = e;
        lsum += e;
    }
    red[tid] = lsum;
    __syncthreads();
    for (int off = 128; off > 0; off >>= 1) {
        if (tid < off) red[tid] += red[tid + off];
        __syncthreads();
    }
    float inv = 1.0f / red[0];
    float* out = g_a2 + ((size_t)h * LM + l) * KSEQ;
    for (int t = tid; t < KSEQ; t += 256) out[t] = lg[t] * inv;
}

// a2v: 256 threads, 4-way partial over K
__global__ void a2v_kernel() {
    int l = blockIdx.x, h = blockIdx.y;
    int e = threadIdx.x & 63;
    int part = threadIdx.x >> 6;          // 0..3
    const float* ar = g_a2 + ((size_t)h * LM + l) * KSEQ;
    const float* vp = g_vc + (size_t)h * KSEQ * HD + e;
    float acc = 0.f;
    int t0 = part * (KSEQ / 4), t1 = t0 + (KSEQ / 4);
#pragma unroll 4
    for (int t = t0; t < t1; t++) acc += ar[t] * vp[(size_t)t * HD];
    __shared__ float red[4][HD];
    red[part][e] = acc;
    __syncthreads();
    if (part == 0)
        g_a2v[((size_t)h * LM + l) * HD + e] =
            red[0][e] + red[1][e] + red[2][e] + red[3][e];
}

__global__ void vals_kernel() {
    int s = blockIdx.x;
    int h = threadIdx.x >> 6;
    int e = threadIdx.x & 63;
    const float* ap = g_a1 + ((size_t)h * SEQ + s) * LM;
    const float* bp = g_a2v + (size_t)h * LM * HD + e;
    float acc = 0.f;
#pragma unroll
    for (int l = 0; l < LM; l++) acc += ap[l] * bp[(size_t)l * HD];
    g_xout[(size_t)s * EMB + h * HD + e] = acc;
}

// ---------------- launch ----------------
extern "C" void kernel_launch(void* const* d_in, const int* in_sizes, int n_in,
                              void* d_out, int out_size) {
    const float* x         = (const float*)d_in[0];
    const float* pe        = (const float*)d_in[1];
    const float* mask_map  = (const float*)d_in[2];
    const float* conv_in_w = (const float*)d_in[3];
    const float* conv_in_b = (const float*)d_in[4];
    const float* conv_pe_w = (const float*)d_in[5];
    const float* conv_pe_b = (const float*)d_in[6];
    const float* qkv_w     = (const float*)d_in[7];
    const float* qkv_b     = (const float*)d_in[8];
    const float* o_w       = (const float*)d_in[9];
    const float* o_b       = (const float*)d_in[10];
    const int*   ftag      = (const int*)d_in[11];

    float* maskf_p;   cudaGetSymbolAddress((void**)&maskf_p,   g_maskf);
    float* qkv_p;     cudaGetSymbolAddress((void**)&qkv_p,     g_qkv);
    float* scratch_p; cudaGetSymbolAddress((void**)&scratch_p, g_scratch);
    float* xout_p;    cudaGetSymbolAddress((void**)&xout_p,    g_xout);
    float* qn_p;      cudaGetSymbolAddress((void**)&qn_p,      g_qn);
    float* kn_p;      cudaGetSymbolAddress((void**)&kn_p,      g_kn);
    float* qL_p;      cudaGetSymbolAddress((void**)&qL_p,      g_qL);
    float* kL_p;      cudaGetSymbolAddress((void**)&kL_p,      g_kL);
    __nv_bfloat16 *Ahi_p, *Alo_p, *Bhi_p, *Blo_p;
    cudaGetSymbolAddress((void**)&Ahi_p, g_Ahi);
    cudaGetSymbolAddress((void**)&Alo_p, g_Alo);
    cudaGetSymbolAddress((void**)&Bhi_p, g_Bhi);
    cudaGetSymbolAddress((void**)&Blo_p, g_Blo);
    __nv_bfloat16 *Axhi_p, *Axlo_p, *Bxhi_p, *Bxlo_p;
    cudaGetSymbolAddress((void**)&Axhi_p, g_Axhi);
    cudaGetSymbolAddress((void**)&Axlo_p, g_Axlo);
    cudaGetSymbolAddress((void**)&Bxhi_p, g_Bxhi);
    cudaGetSymbolAddress((void**)&Bxlo_p, g_Bxlo);
    __nv_bfloat16 *Tokhi_p, *Toklo_p, *Bqhi_p, *Bqlo_p;
    cudaGetSymbolAddress((void**)&Tokhi_p, g_Tokhi);
    cudaGetSymbolAddress((void**)&Toklo_p, g_Toklo);
    cudaGetSymbolAddress((void**)&Bqhi_p, g_Bqhi);
    cudaGetSymbolAddress((void**)&Bqlo_p, g_Bqlo);

    static int inited = 0;
    if (!inited) {
        cudaFuncSetAttribute(mma_gemm<0>, cudaFuncAttributeMaxDynamicSharedMemorySize, 2 * STAGEB);
        cudaFuncSetAttribute(mma_gemm<1>, cudaFuncAttributeMaxDynamicSharedMemorySize, 2 * STAGEB);
        cudaFuncSetAttribute(mma_gemm<2>, cudaFuncAttributeMaxDynamicSharedMemorySize, 2 * STAGEB);
        inited = 1;
    }

    // 1. patch mask
    mask_kernel<<<SEQ, 256>>>(mask_map, maskf_p);

    // 2. operand conversions
    conv_a_kernel<<<(MPAD * (K_PE / 4)) / 256, 256>>>(pe, ftag);
    conv_w_kernel<<<(int)(((size_t)EMB * K_PE / 4) / 256), 256>>>(conv_pe_w, Bhi_p, Blo_p);
    conv_ax_kernel<<<(MQ * (K_X / 4)) / 256, 256>>>(x);
    conv_w_kernel<<<(EMB * K_X / 4) / 256, 256>>>(conv_in_w, Bxhi_p, Bxlo_p);
    conv_w_kernel<<<(3 * EMB * EMB / 4) / 256, 256>>>(qkv_w, Bqhi_p, Bqlo_p);

    // 3. pe GEMM (split-K=32 into g_scratch)
    mma_gemm<0><<<dim3(EMB / 128, MPAD / 128, SPLITK), 256, 2 * STAGEB>>>(
        Ahi_p, Alo_p, Bhi_p, Blo_p, K_PE, KSLICE,
        scratch_p, nullptr, nullptr, nullptr, nullptr, EMB, SEQ);

    // 4. reduce split-K + bias + mask -> pe_tok
    reduce_pe_kernel<<<(SEQ * EMB + 255) / 256, 256>>>(conv_pe_b, maskf_p);

    // 5. x patch embed -> tokens as bf16 hi/lo (bias + mask in epilogue)
    mma_gemm<1><<<dim3(EMB / 128, MQ / 128, 1), 256, 2 * STAGEB>>>(
        Axhi_p, Axlo_p, Bxhi_p, Bxlo_p, K_X, K_X,
        nullptr, Tokhi_p, Toklo_p, conv_in_b, maskf_p, EMB, MQ);

    // 6. QKV: tokens @ qkv_w^T + b -> fp32 g_qkv
    mma_gemm<2><<<dim3((3 * EMB) / 128, MQ / 128, 1), 256, 2 * STAGEB>>>(
        Tokhi_p, Toklo_p, Bqhi_p, Bqlo_p, EMB, EMB,
        qkv_p, nullptr, nullptr, qkv_b, nullptr, 3 * EMB, MQ);

    // 7. normalized q (+pe) and k, raw v gather
    prep_q_kernel<<<dim3(SEQ, NHEADS), HD>>>(ftag);
    prep_k_kernel<<<dim3(KSEQ, NHEADS), HD>>>(ftag);

    // 8. landmarks
    landmark_kernel<<<dim3(LM, NHEADS), HD>>>(qn_p, qL_p, SEQ / LM);
    landmark_kernel<<<dim3(LM, NHEADS), HD>>>(kn_p, kL_p, KSEQ / LM);

    // 9. attention core
    a1_kernel<<<dim3(SEQ / 4, NHEADS), 128>>>();
    a2_kernel<<<dim3(LM, NHEADS), 256>>>();
    a2v_kernel<<<dim3(LM, NHEADS), 256>>>();
    vals_kernel<<<SEQ, EMB>>>();

    // 10. output projection -> d_out (704 x 512)
    sgemm_f32<<<dim3(EMB / 128, (SEQ + 127) / 128, 1), 256>>>(
        xout_p, o_w, (float*)d_out, o_b, SEQ, EMB, EMB);
}

// round 13
// speedup vs baseline: 1.3595x; 1.0000x over previous
#include <cuda_runtime.h>
#include <cuda_bf16.h>
#include <math.h>
#include <cstdint>

// ---------------- problem constants ----------------
#define NHEADS 8
#define HD 64
#define EMB 512
#define PS 16
#define GH 16
#define GW 44
#define SEQ 704            // GH*GW
#define NVIEW 6
#define MQ (NVIEW*SEQ)     // 4224
#define LM 16              // landmarks
#define KSEQ (5*SEQ)       // 3520
#define SCALE 0.125f       // 1/sqrt(64)

#define PE_C 256
#define IMG_H 256
#define IMG_W 704
#define K_PE (PE_C*PS*PS)  // 65536
#define K_X  (3*PS*PS)     // 768

#define MPAD 768           // 704 padded to 6x128
#define SPLITK 32
#define KSLICE (K_PE / SPLITK)   // 2048
#define KS 32                    // K per stage

// smem tile geometry: rows stored with 40-element (80B) stride for
// conflict-free ldmatrix; 128 rows x 32 bf16 -> 10240 B per tile.
#define ROWB 80
#define TILEB (128 * ROWB)       // 10240
#define STAGEB (4 * TILEB)       // 40960 (Ahi, Alo, Bhi, Blo)

// ---------------- scratch (device globals, no cudaMalloc) ----------------
__device__ float g_maskf[SEQ];
__device__ float g_qkv[MQ * 3 * EMB];
__device__ float g_scratch[SPLITK * SEQ * EMB];
__device__ float g_pe_tok[SEQ * EMB];
__device__ float g_qn[NHEADS * SEQ * HD];
__device__ float g_kn[NHEADS * KSEQ * HD];
__device__ float g_vc[NHEADS * KSEQ * HD];
__device__ float g_qL[NHEADS * LM * HD];
__device__ float g_kL[NHEADS * LM * HD];
__device__ float g_a1[NHEADS * SEQ * LM];
__device__ float g_a2[NHEADS * LM * KSEQ];
__device__ float g_a2v[NHEADS * LM * HD];
__device__ float g_xout[SEQ * EMB];

// bf16 hi/lo split operands
__device__ __nv_bfloat16 g_Ahi[(size_t)MPAD * K_PE];       // pe im2col
__device__ __nv_bfloat16 g_Alo[(size_t)MPAD * K_PE];
__device__ __nv_bfloat16 g_Bhi[(size_t)EMB * K_PE];        // conv_pe_w
__device__ __nv_bfloat16 g_Blo[(size_t)EMB * K_PE];
__device__ __nv_bfloat16 g_Axhi[(size_t)MQ * K_X];         // x im2col
__device__ __nv_bfloat16 g_Axlo[(size_t)MQ * K_X];
__device__ __nv_bfloat16 g_Bxhi[(size_t)EMB * K_X];        // conv_in_w
__device__ __nv_bfloat16 g_Bxlo[(size_t)EMB * K_X];
__device__ __nv_bfloat16 g_Tokhi[(size_t)MQ * EMB];        // tokens (x-embed out)
__device__ __nv_bfloat16 g_Toklo[(size_t)MQ * EMB];
__device__ __nv_bfloat16 g_Bqhi[(size_t)(3 * EMB) * EMB];  // qkv_w
__device__ __nv_bfloat16 g_Bqlo[(size_t)(3 * EMB) * EMB];

// ======================= PTX helpers (compute_103-safe) =======================
__device__ __forceinline__ uint32_t smem_u32(const void* p) {
    uint32_t a;
    asm("{ .reg .u64 t; cvta.to.shared.u64 t, %1; cvt.u32.u64 %0, t; }"
        : "=r"(a) : "l"(p));
    return a;
}

#define CP_ASYNC16(sp, gp) \
    asm volatile("cp.async.cg.shared.global [%0], [%1], 16;\n" :: "r"(sp), "l"(gp) : "memory")
#define CP_COMMIT() asm volatile("cp.async.commit_group;\n" ::: "memory")
#define CP_WAIT(n)  asm volatile("cp.async.wait_group %0;\n" :: "n"(n) : "memory")

#define LDSM4(r, addr) \
    asm volatile("ldmatrix.sync.aligned.m8n8.x4.shared.b16 {%0,%1,%2,%3}, [%4];" \
        : "=r"((r)[0]), "=r"((r)[1]), "=r"((r)[2]), "=r"((r)[3]) : "r"(addr))
#define LDSM2(r, addr) \
    asm volatile("ldmatrix.sync.aligned.m8n8.x2.shared.b16 {%0,%1}, [%2];" \
        : "=r"((r)[0]), "=r"((r)[1]) : "r"(addr))

#define MMA16816(d, a, b) \
    asm volatile("mma.sync.aligned.m16n8k16.row.col.f32.bf16.bf16.f32 " \
        "{%0,%1,%2,%3}, {%4,%5,%6,%7}, {%8,%9}, {%0,%1,%2,%3};" \
        : "+f"((d)[0]), "+f"((d)[1]), "+f"((d)[2]), "+f"((d)[3]) \
        : "r"((a)[0]), "r"((a)[1]), "r"((a)[2]), "r"((a)[3]), "r"((b)[0]), "r"((b)[1]))

// ---------------- patch mask: 16x16 avg pool > 0 ----------------
__global__ void mask_kernel(const float* __restrict__ mask_map, float* __restrict__ maskf) {
    int p = blockIdx.x;
    int gh = p / GW, gw = p % GW;
    int i = threadIdx.x >> 4, j = threadIdx.x & 15;
    float v = mask_map[(gh * PS + i) * IMG_W + gw * PS + j];
    __shared__ float red[256];
    red[threadIdx.x] = v;
    __syncthreads();
    for (int off = 128; off > 0; off >>= 1) {
        if (threadIdx.x < off) red[threadIdx.x] += red[threadIdx.x + off];
        __syncthreads();
    }
    if (threadIdx.x == 0) maskf[p] = (red[0] > 0.0f) ? 1.0f : 0.0f;
}

// ---------------- bf16 hi/lo conversion kernels ----------------
__device__ __forceinline__ void split4(float4 v, uint2& hi, uint2& lo) {
    __nv_bfloat16 h0 = __float2bfloat16(v.x);
    __nv_bfloat16 h1 = __float2bfloat16(v.y);
    __nv_bfloat16 h2 = __float2bfloat16(v.z);
    __nv_bfloat16 h3 = __float2bfloat16(v.w);
    __nv_bfloat16 l0 = __float2bfloat16(v.x - __bfloat162float(h0));
    __nv_bfloat16 l1 = __float2bfloat16(v.y - __bfloat162float(h1));
    __nv_bfloat16 l2 = __float2bfloat16(v.z - __bfloat162float(h2));
    __nv_bfloat16 l3 = __float2bfloat16(v.w - __bfloat162float(h3));
    __nv_bfloat162 ph0; ph0.x = h0; ph0.y = h1;
    __nv_bfloat162 ph1; ph1.x = h2; ph1.y = h3;
    __nv_bfloat162 pl0; pl0.x = l0; pl0.y = l1;
    __nv_bfloat162 pl1; pl1.x = l2; pl1.y = l3;
    hi.x = *reinterpret_cast<uint32_t*>(&ph0);
    hi.y = *reinterpret_cast<uint32_t*>(&ph1);
    lo.x = *reinterpret_cast<uint32_t*>(&pl0);
    lo.y = *reinterpret_cast<uint32_t*>(&pl1);
}

// pe A = im2col(pe[ft]) -> [MPAD][K_PE], rows >= SEQ zero
__global__ void conv_a_kernel(const float* __restrict__ pe, const int* __restrict__ ftag) {
    size_t idx = (size_t)blockIdx.x * 256 + threadIdx.x;
    int m = (int)(idx >> 14);               // K_PE/4 = 16384 chunks per row
    int kq = ((int)idx & 16383) << 2;
    float4 v = make_float4(0.f, 0.f, 0.f, 0.f);
    if (m < SEQ) {
        int c = kq >> 8, rem = kq & 255, i = rem >> 4, j = rem & 15;
        int gh = m / GW, gw = m % GW;
        const float* src = pe + (size_t)ftag[0] * PE_C * IMG_H * IMG_W
                              + ((size_t)c * IMG_H + gh * PS + i) * IMG_W + gw * PS + j;
        v = *(const float4*)src;
    }
    uint2 hi, lo;
    split4(v, hi, lo);
    size_t off = (size_t)m * K_PE + kq;
    *(uint2*)(g_Ahi + off) = hi;
    *(uint2*)(g_Alo + off) = lo;
}

// x A = im2col(x, all 6 views) -> [MQ][K_X]
__global__ void conv_ax_kernel(const float* __restrict__ x) {
    size_t idx = (size_t)blockIdx.x * 256 + threadIdx.x;  // per 4 elems
    int m = (int)(idx / (K_X / 4));
    int kq = ((int)(idx % (K_X / 4))) << 2;
    int c = kq >> 8, rem = kq & 255, i = rem >> 4, j = rem & 15;
    int v6 = m / SEQ, s = m % SEQ;
    int gh = s / GW, gw = s % GW;
    const float* src = x + (((size_t)(v6 * 3 + c)) * IMG_H + gh * PS + i) * IMG_W + gw * PS + j;
    float4 v = *(const float4*)src;
    uint2 hi, lo;
    split4(v, hi, lo);
    size_t off = (size_t)m * K_X + kq;
    *(uint2*)(g_Axhi + off) = hi;
    *(uint2*)(g_Axlo + off) = lo;
}

// generic weight split: row-major [n][k] fp32 -> bf16 hi/lo
__global__ void conv_w_kernel(const float* __restrict__ w,
                              __nv_bfloat16* __restrict__ whi,
                              __nv_bfloat16* __restrict__ wlo) {
    size_t idx = (size_t)blockIdx.x * 256 + threadIdx.x;
    size_t off = idx << 2;
    float4 v = *(const float4*)(w + off);
    uint2 hi, lo;
    split4(v, hi, lo);
    *(uint2*)(whi + off) = hi;
    *(uint2*)(wlo + off) = lo;
}

// ---------------- unified bf16 3-pass mma GEMM ----------------
// CTA tile M=128, N=128, K-stage 32, double-buffered cp.async.
// EPI 0: write fp32 to outf + z*SEQ*Nld, rows guarded by Mvalid (pe split-K)
// EPI 1: (acc+bias)*mask -> bf16 hi/lo outputs (x-embed -> tokens)
// EPI 2: acc+bias -> fp32 (QKV)
__device__ __forceinline__ void load_stage_g(
    uint32_t smbuf,
    const __nv_bfloat16* __restrict__ Ahi, const __nv_bfloat16* __restrict__ Alo,
    const __nv_bfloat16* __restrict__ Bhi, const __nv_bfloat16* __restrict__ Blo,
    int m0, int n0, int koff, int Ktot, int tid)
{
#pragma unroll
    for (int it = 0; it < 8; it++) {
        int f = it * 256 + tid;        // 0..2047 chunks of 16B
        int tile = f >> 9;             // 0:Ahi 1:Alo 2:Bhi 3:Blo
        int idx = f & 511;
        int row = idx >> 2;
        int q = idx & 3;
        const __nv_bfloat16* g;
        int r0;
        if (tile == 0)      { g = Ahi; r0 = m0; }
        else if (tile == 1) { g = Alo; r0 = m0; }
        else if (tile == 2) { g = Bhi; r0 = n0; }
        else                { g = Blo; r0 = n0; }
        const __nv_bfloat16* gp = g + (size_t)(r0 + row) * Ktot + koff + q * 8;
        uint32_t sp = smbuf + tile * TILEB + row * ROWB + q * 16;
        CP_ASYNC16(sp, gp);
    }
    CP_COMMIT();
}

template<int EPI>
__global__ void __launch_bounds__(256, 2) mma_gemm(
    const __nv_bfloat16* __restrict__ Ahi, const __nv_bfloat16* __restrict__ Alo,
    const __nv_bfloat16* __restrict__ Bhi, const __nv_bfloat16* __restrict__ Blo,
    int Ktot, int kslice,
    float* __restrict__ outf,
    __nv_bfloat16* __restrict__ outhi, __nv_bfloat16* __restrict__ outlo,
    const float* __restrict__ bias, const float* __restrict__ maskf,
    int Nld, int Mvalid)
{
    extern __shared__ __align__(128) char dsm[];
    const uint32_t base = smem_u32(dsm);
    const int tid = threadIdx.x;
    const int wid = tid >> 5, lane = tid & 31;
    const int warp_m = wid >> 2;
    const int warp_n = wid & 3;
    const int n0 = blockIdx.x * 128;
    const int m0 = blockIdx.y * 128;
    const int kbase = blockIdx.z * kslice;
    const int nstage = kslice / KS;

    float acc[4][4][4];
#pragma unroll
    for (int i = 0; i < 4; i++)
#pragma unroll
        for (int j = 0; j < 4; j++)
#pragma unroll
            for (int c = 0; c < 4; c++) acc[i][j][c] = 0.0f;

    const uint32_t a_off = (uint32_t)((warp_m * 64 + (lane & 15)) * ROWB + ((lane >> 4) << 4));
    const uint32_t b_off = (uint32_t)((warp_n * 32 + (lane & 7)) * ROWB + (((lane >> 3) & 1) << 4));

    load_stage_g(base, Ahi, Alo, Bhi, Blo, m0, n0, kbase, Ktot, tid);

#pragma unroll 1
    for (int s = 0; s < nstage; s++) {
        uint32_t cb = base + (s & 1) * STAGEB;
        if (s + 1 < nstage) {
            load_stage_g(base + ((s + 1) & 1) * STAGEB, Ahi, Alo, Bhi, Blo,
                         m0, n0, kbase + (s + 1) * KS, Ktot, tid);
            CP_WAIT(1);
        } else {
            CP_WAIT(0);
        }
        __syncthreads();

        const uint32_t Ah = cb;
        const uint32_t Al = cb + TILEB;
        const uint32_t Bh = cb + 2 * TILEB;
        const uint32_t Bl = cb + 3 * TILEB;

#pragma unroll
        for (int ks = 0; ks < 2; ks++) {
            uint32_t kb = ks * 32;
            uint32_t bh[4][2], bl[4][2];
#pragma unroll
            for (int nt = 0; nt < 4; nt++) {
                uint32_t boff = b_off + nt * 8 * ROWB + kb;
                LDSM2(bh[nt], Bh + boff);
                LDSM2(bl[nt], Bl + boff);
            }
#pragma unroll
            for (int mt = 0; mt < 4; mt++) {
                uint32_t ah[4], al[4];
                uint32_t aoff = a_off + mt * 16 * ROWB + kb;
                LDSM4(ah, Ah + aoff);
                LDSM4(al, Al + aoff);
#pragma unroll
                for (int nt = 0; nt < 4; nt++) {
                    MMA16816(acc[mt][nt], ah, bh[nt]);
                    MMA16816(acc[mt][nt], ah, bl[nt]);
                    MMA16816(acc[mt][nt], al, bh[nt]);
                }
            }
        }
        __syncthreads();
    }

    // epilogue
    float* out = outf;
    if (EPI == 0) out += (size_t)blockIdx.z * SEQ * (size_t)Nld;
    const int rbase = m0 + warp_m * 64 + (lane >> 2);
    const int cbase = n0 + warp_n * 32 + ((lane & 3) << 1);
#pragma unroll
    for (int mt = 0; mt < 4; mt++) {
#pragma unroll
        for (int nt = 0; nt < 4; nt++) {
            int r0 = rbase + mt * 16;
            int r1 = r0 + 8;
            int c  = cbase + nt * 8;
            if (EPI == 0) {
                if (r0 < Mvalid)
                    *(float2*)(out + (size_t)r0 * Nld + c) = make_float2(acc[mt][nt][0], acc[mt][nt][1]);
                if (r1 < Mvalid)
                    *(float2*)(out + (size_t)r1 * Nld + c) = make_float2(acc[mt][nt][2], acc[mt][nt][3]);
            } else if (EPI == 1) {
                float b0 = bias[c], b1 = bias[c + 1];
                float mk0 = maskf[r0 % SEQ];
                float mk1 = maskf[r1 % SEQ];
                float v0 = (acc[mt][nt][0] + b0) * mk0;
                float v1 = (acc[mt][nt][1] + b1) * mk0;
                float v2 = (acc[mt][nt][2] + b0) * mk1;
                float v3 = (acc[mt][nt][3] + b1) * mk1;
                __nv_bfloat16 h0 = __float2bfloat16(v0), h1 = __float2bfloat16(v1);
                __nv_bfloat16 h2 = __float2bfloat16(v2), h3 = __float2bfloat16(v3);
                __nv_bfloat162 hh0; hh0.x = h0; hh0.y = h1;
                __nv_bfloat162 hh1; hh1.x = h2; hh1.y = h3;
                __nv_bfloat162 ll0;
                ll0.x = __float2bfloat16(v0 - __bfloat162float(h0));
                ll0.y = __float2bfloat16(v1 - __bfloat162float(h1));
                __nv_bfloat162 ll1;
                ll1.x = __float2bfloat16(v2 - __bfloat162float(h2));
                ll1.y = __float2bfloat16(v3 - __bfloat162float(h3));
                *(__nv_bfloat162*)(outhi + (size_t)r0 * Nld + c) = hh0;
                *(__nv_bfloat162*)(outlo + (size_t)r0 * Nld + c) = ll0;
                *(__nv_bfloat162*)(outhi + (size_t)r1 * Nld + c) = hh1;
                *(__nv_bfloat162*)(outlo + (size_t)r1 * Nld + c) = ll1;
            } else {
                float b0 = bias[c], b1 = bias[c + 1];
                *(float2*)(outf + (size_t)r0 * Nld + c) =
                    make_float2(acc[mt][nt][0] + b0, acc[mt][nt][1] + b1);
                *(float2*)(outf + (size_t)r1 * Nld + c) =
                    make_float2(acc[mt][nt][2] + b0, acc[mt][nt][3] + b1);
            }
        }
    }
}

// ---------------- fp32 FFMA SGEMM (out-proj only) ----------------
__global__ void __launch_bounds__(256, 2)
sgemm_f32(const float* __restrict__ A, const float* __restrict__ B,
          float* __restrict__ C, const float* __restrict__ bias,
          int M, int N, int Ktot)
{
    __shared__ float As[8][128];
    __shared__ float Bs[8][128];

    const int tid = threadIdx.x;
    const int m0 = blockIdx.y * 128;
    const int n0 = blockIdx.x * 128;

    const int aM = tid >> 1;
    const int aQ = (tid & 1) << 2;
    const int trow = (tid >> 4) << 3;
    const int tcol = (tid & 15) << 3;

    float acc[8][8];
#pragma unroll
    for (int i = 0; i < 8; i++)
#pragma unroll
        for (int j = 0; j < 8; j++) acc[i][j] = 0.0f;

    const int am = m0 + aM;
    const bool mvalid = (am < M);
    const float* Bp = B + (size_t)(n0 + aM) * Ktot + aQ;
    const float* Ap = A + (size_t)am * Ktot + aQ;

    for (int kk = 0; kk < Ktot; kk += 8) {
        float4 av = make_float4(0.f, 0.f, 0.f, 0.f);
        if (mvalid) av = *(const float4*)Ap;
        Ap += 8;
        As[aQ + 0][aM] = av.x;
        As[aQ + 1][aM] = av.y;
        As[aQ + 2][aM] = av.z;
        As[aQ + 3][aM] = av.w;

        float4 bv = *(const float4*)Bp;
        Bp += 8;
        Bs[aQ + 0][aM] = bv.x;
        Bs[aQ + 1][aM] = bv.y;
        Bs[aQ + 2][aM] = bv.z;
        Bs[aQ + 3][aM] = bv.w;

        __syncthreads();
#pragma unroll
        for (int k = 0; k < 8; k++) {
            float4 a0 = *(const float4*)&As[k][trow];
            float4 a1 = *(const float4*)&As[k][trow + 4];
            float4 b0 = *(const float4*)&Bs[k][tcol];
            float4 b1 = *(const float4*)&Bs[k][tcol + 4];
            float ar[8] = {a0.x, a0.y, a0.z, a0.w, a1.x, a1.y, a1.z, a1.w};
            float br[8] = {b0.x, b0.y, b0.z, b0.w, b1.x, b1.y, b1.z, b1.w};
#pragma unroll
            for (int i = 0; i < 8; i++)
#pragma unroll
                for (int j = 0; j < 8; j++) acc[i][j] += ar[i] * br[j];
        }
        __syncthreads();
    }

#pragma unroll
    for (int i = 0; i < 8; i++) {
        int m = m0 + trow + i;
        if (m >= M) break;
        float* crow = C + (size_t)m * N + n0 + tcol;
#pragma unroll
        for (int j = 0; j < 8; j += 4) {
            float4 r;
            r.x = acc[i][j + 0] + bias[n0 + tcol + j + 0];
            r.y = acc[i][j + 1] + bias[n0 + tcol + j + 1];
            r.z = acc[i][j + 2] + bias[n0 + tcol + j + 2];
            r.w = acc[i][j + 3] + bias[n0 + tcol + j + 3];
            *(float4*)(crow + j) = r;
        }
    }
}

// ---------------- reduce split-K pe partials + bias + mask ----------------
__global__ void reduce_pe_kernel(const float* __restrict__ bias,
                                 const float* __restrict__ maskf) {
    int idx = blockIdx.x * blockDim.x + threadIdx.x;
    if (idx >= SEQ * EMB) return;
    int n = idx % EMB;
    int m = idx / EMB;
    float acc = bias[n];
#pragma unroll
    for (int z = 0; z < SPLITK; z++) acc += g_scratch[(size_t)z * SEQ * EMB + idx];
    g_pe_tok[idx] = acc * maskf[m];
}

// ---------------- q/k prep, landmarks, attention core ----------------
__device__ __forceinline__ float block64_sum(float v, float* red2) {
    for (int off = 16; off > 0; off >>= 1)
        v += __shfl_xor_sync(0xffffffffu, v, off);
    if ((threadIdx.x & 31) == 0) red2[threadIdx.x >> 5] = v;
    __syncthreads();
    return red2[0] + red2[1];
}

__global__ void prep_q_kernel(const int* __restrict__ ftag) {
    int s = blockIdx.x, h = blockIdx.y, e = threadIdx.x;
    int ft = ftag[0];
    float val = g_qkv[((size_t)(ft * SEQ + s)) * (3 * EMB) + h * (3 * HD) + e]
              + g_pe_tok[(size_t)s * EMB + h * HD + e];
    __shared__ float red2[2];
    float tot = block64_sum(val * val, red2);
    float denom = fmaxf(sqrtf(tot), 1e-12f);
    g_qn[((size_t)h * SEQ + s) * HD + e] = val / denom;
}

__global__ void prep_k_kernel(const int* __restrict__ ftag) {
    int t = blockIdx.x, h = blockIdx.y, e = threadIdx.x;
    int ft = ftag[0];
    int vi = t / SEQ;
    int view = (vi < ft) ? vi : vi + 1;
    int s = t % SEQ;
    size_t base = ((size_t)(view * SEQ + s)) * (3 * EMB) + h * (3 * HD);
    float kval = g_qkv[base + HD + e];
    float vval = g_qkv[base + 2 * HD + e];
    __shared__ float red2[2];
    float tot = block64_sum(kval * kval, red2);
    float denom = fmaxf(sqrtf(tot), 1e-12f);
    g_kn[((size_t)h * KSEQ + t) * HD + e] = kval / denom;
    g_vc[((size_t)h * KSEQ + t) * HD + e] = vval;
}

__global__ void landmark_kernel(const float* __restrict__ src, float* __restrict__ dst, int seg) {
    int l = blockIdx.x, h = blockIdx.y, e = threadIdx.x;
    int S = LM * seg;
    const float* p = src + ((size_t)h * S + (size_t)l * seg) * HD + e;
    float acc = 0.f;
    for (int r = 0; r < seg; r++) acc += p[(size_t)r * HD];
    dst[((size_t)h * LM + l) * HD + e] = acc / (float)seg;
}

__global__ void a1_kernel() {
    int warp = threadIdx.x >> 5, lane = threadIdx.x & 31;
    int s = blockIdx.x * 4 + warp;
    int h = blockIdx.y;
    const float* qp = g_qn + ((size_t)h * SEQ + s) * HD;
    float q0 = qp[lane], q1 = qp[lane + 32];
    float lg[LM];
#pragma unroll
    for (int l = 0; l < LM; l++) {
        const float* kp = g_kL + ((size_t)h * LM + l) * HD;
        float p = q0 * kp[lane] + q1 * kp[lane + 32];
        for (int off = 16; off > 0; off >>= 1)
            p += __shfl_xor_sync(0xffffffffu, p, off);
        lg[l] = p * SCALE;
    }
    float mx = lg[0];
#pragma unroll
    for (int l = 1; l < LM; l++) mx = fmaxf(mx, lg[l]);
    float sum = 0.f;
#pragma unroll
    for (int l = 0; l < LM; l++) { lg[l] = expf(lg[l] - mx); sum += lg[l]; }
    float inv = 1.0f / sum;
    if (lane < LM)
        g_a1[((size_t)h * SEQ + s) * LM + lane] = lg[lane] * inv;
}

__global__ void a2_kernel() {
    int l = blockIdx.x, h = blockIdx.y, tid = threadIdx.x;
    __shared__ float sq[HD];
    __shared__ float lg[KSEQ];
    __shared__ float red[256];
    if (tid < HD) sq[tid] = g_qL[((size_t)h * LM + l) * HD + tid];
    __syncthreads();

    for (int t = tid; t < KSEQ; t += 256) {
        const float* kp = g_kn + ((size_t)h * KSEQ + t) * HD;
        float d = 0.f;
#pragma unroll
        for (int e = 0; e < HD; e += 4) {
            float4 kv = *(const float4*)(kp + e);
            d += kv.x * sq[e] + kv.y * sq[e + 1] + kv.z * sq[e + 2] + kv.w * sq[e + 3];
        }
        lg[t] = d * SCALE;
    }
    __syncthreads();

    float lmax = -1e30f;
    for (int t = tid; t < KSEQ; t += 256) lmax = fmaxf(lmax, lg[t]);
    red[tid] = lmax;
    __syncthreads();
    for (int off = 128; off > 0; off >>= 1) {
        if (tid < off) red[tid] = fmaxf(red[tid], red[tid + off]);
        __syncthreads();
    }
    float gmax = red[0];
    __syncthreads();

    float lsum = 0.f;
    for (int t = tid; t < KSEQ; t += 256) {
        float e = expf(lg[t] - gmax);
        lg[t] = e;
        lsum += e;
    }
    red[tid] = lsum;
    __syncthreads();
    for (int off = 128; off > 0; off >>= 1) {
        if (tid < off) red[tid] += red[tid + off];
        __syncthreads();
    }
    float inv = 1.0f / red[0];
    float* out = g_a2 + ((size_t)h * LM + l) * KSEQ;
    for (int t = tid; t < KSEQ; t += 256) out[t] = lg[t] * inv;
}

// a2v: 256 threads, 4-way partial over K
__global__ void a2v_kernel() {
    int l = blockIdx.x, h = blockIdx.y;
    int e = threadIdx.x & 63;
    int part = threadIdx.x >> 6;          // 0..3
    const float* ar = g_a2 + ((size_t)h * LM + l) * KSEQ;
    const float* vp = g_vc + (size_t)h * KSEQ * HD + e;
    float acc = 0.f;
    int t0 = part * (KSEQ / 4), t1 = t0 + (KSEQ / 4);
#pragma unroll 4
    for (int t = t0; t < t1; t++) acc += ar[t] * vp[(size_t)t * HD];
    __shared__ float red[4][HD];
    red[part][e] = acc;
    __syncthreads();
    if (part == 0)
        g_a2v[((size_t)h * LM + l) * HD + e] =
            red[0][e] + red[1][e] + red[2][e] + red[3][e];
}

__global__ void vals_kernel() {
    int s = blockIdx.x;
    int h = threadIdx.x >> 6;
    int e = threadIdx.x & 63;
    const float* ap = g_a1 + ((size_t)h * SEQ + s) * LM;
    const float* bp = g_a2v + (size_t)h * LM * HD + e;
    float acc = 0.f;
#pragma unroll
    for (int l = 0; l < LM; l++) acc += ap[l] * bp[(size_t)l * HD];
    g_xout[(size_t)s * EMB + h * HD + e] = acc;
}

// ---------------- launch ----------------
extern "C" void kernel_launch(void* const* d_in, const int* in_sizes, int n_in,
                              void* d_out, int out_size) {
    const float* x         = (const float*)d_in[0];
    const float* pe        = (const float*)d_in[1];
    const float* mask_map  = (const float*)d_in[2];
    const float* conv_in_w = (const float*)d_in[3];
    const float* conv_in_b = (const float*)d_in[4];
    const float* conv_pe_w = (const float*)d_in[5];
    const float* conv_pe_b = (const float*)d_in[6];
    const float* qkv_w     = (const float*)d_in[7];
    const float* qkv_b     = (const float*)d_in[8];
    const float* o_w       = (const float*)d_in[9];
    const float* o_b       = (const float*)d_in[10];
    const int*   ftag      = (const int*)d_in[11];

    float* maskf_p;   cudaGetSymbolAddress((void**)&maskf_p,   g_maskf);
    float* qkv_p;     cudaGetSymbolAddress((void**)&qkv_p,     g_qkv);
    float* scratch_p; cudaGetSymbolAddress((void**)&scratch_p, g_scratch);
    float* xout_p;    cudaGetSymbolAddress((void**)&xout_p,    g_xout);
    float* qn_p;      cudaGetSymbolAddress((void**)&qn_p,      g_qn);
    float* kn_p;      cudaGetSymbolAddress((void**)&kn_p,      g_kn);
    float* qL_p;      cudaGetSymbolAddress((void**)&qL_p,      g_qL);
    float* kL_p;      cudaGetSymbolAddress((void**)&kL_p,      g_kL);
    __nv_bfloat16 *Ahi_p, *Alo_p, *Bhi_p, *Blo_p;
    cudaGetSymbolAddress((void**)&Ahi_p, g_Ahi);
    cudaGetSymbolAddress((void**)&Alo_p, g_Alo);
    cudaGetSymbolAddress((void**)&Bhi_p, g_Bhi);
    cudaGetSymbolAddress((void**)&Blo_p, g_Blo);
    __nv_bfloat16 *Axhi_p, *Axlo_p, *Bxhi_p, *Bxlo_p;
    cudaGetSymbolAddress((void**)&Axhi_p, g_Axhi);
    cudaGetSymbolAddress((void**)&Axlo_p, g_Axlo);
    cudaGetSymbolAddress((void**)&Bxhi_p, g_Bxhi);
    cudaGetSymbolAddress((void**)&Bxlo_p, g_Bxlo);
    __nv_bfloat16 *Tokhi_p, *Toklo_p, *Bqhi_p, *Bqlo_p;
    cudaGetSymbolAddress((void**)&Tokhi_p, g_Tokhi);
    cudaGetSymbolAddress((void**)&Toklo_p, g_Toklo);
    cudaGetSymbolAddress((void**)&Bqhi_p, g_Bqhi);
    cudaGetSymbolAddress((void**)&Bqlo_p, g_Bqlo);

    static int inited = 0;
    if (!inited) {
        cudaFuncSetAttribute(mma_gemm<0>, cudaFuncAttributeMaxDynamicSharedMemorySize, 2 * STAGEB);
        cudaFuncSetAttribute(mma_gemm<1>, cudaFuncAttributeMaxDynamicSharedMemorySize, 2 * STAGEB);
        cudaFuncSetAttribute(mma_gemm<2>, cudaFuncAttributeMaxDynamicSharedMemorySize, 2 * STAGEB);
        inited = 1;
    }

    // 1. patch mask
    mask_kernel<<<SEQ, 256>>>(mask_map, maskf_p);

    // 2. operand conversions
    conv_a_kernel<<<(MPAD * (K_PE / 4)) / 256, 256>>>(pe, ftag);
    conv_w_kernel<<<(int)(((size_t)EMB * K_PE / 4) / 256), 256>>>(conv_pe_w, Bhi_p, Blo_p);
    conv_ax_kernel<<<(MQ * (K_X / 4)) / 256, 256>>>(x);
    conv_w_kernel<<<(EMB * K_X / 4) / 256, 256>>>(conv_in_w, Bxhi_p, Bxlo_p);
    conv_w_kernel<<<(3 * EMB * EMB / 4) / 256, 256>>>(qkv_w, Bqhi_p, Bqlo_p);

    // 3. pe GEMM (split-K=32 into g_scratch)
    mma_gemm<0><<<dim3(EMB / 128, MPAD / 128, SPLITK), 256, 2 * STAGEB>>>(
        Ahi_p, Alo_p, Bhi_p, Blo_p, K_PE, KSLICE,
        scratch_p, nullptr, nullptr, nullptr, nullptr, EMB, SEQ);

    // 4. reduce split-K + bias + mask -> pe_tok
    reduce_pe_kernel<<<(SEQ * EMB + 255) / 256, 256>>>(conv_pe_b, maskf_p);

    // 5. x patch embed -> tokens as bf16 hi/lo (bias + mask in epilogue)
    mma_gemm<1><<<dim3(EMB / 128, MQ / 128, 1), 256, 2 * STAGEB>>>(
        Axhi_p, Axlo_p, Bxhi_p, Bxlo_p, K_X, K_X,
        nullptr, Tokhi_p, Toklo_p, conv_in_b, maskf_p, EMB, MQ);

    // 6. QKV: tokens @ qkv_w^T + b -> fp32 g_qkv
    mma_gemm<2><<<dim3((3 * EMB) / 128, MQ / 128, 1), 256, 2 * STAGEB>>>(
        Tokhi_p, Toklo_p, Bqhi_p, Bqlo_p, EMB, EMB,
        qkv_p, nullptr, nullptr, qkv_b, nullptr, 3 * EMB, MQ);

    // 7. normalized q (+pe) and k, raw v gather
    prep_q_kernel<<<dim3(SEQ, NHEADS), HD>>>(ftag);
    prep_k_kernel<<<dim3(KSEQ, NHEADS), HD>>>(ftag);

    // 8. landmarks
    landmark_kernel<<<dim3(LM, NHEADS), HD>>>(qn_p, qL_p, SEQ / LM);
    landmark_kernel<<<dim3(LM, NHEADS), HD>>>(kn_p, kL_p, KSEQ / LM);

    // 9. attention core
    a1_kernel<<<dim3(SEQ / 4, NHEADS), 128>>>();
    a2_kernel<<<dim3(LM, NHEADS), 256>>>();
    a2v_kernel<<<dim3(LM, NHEADS), 256>>>();
    vals_kernel<<<SEQ, EMB>>>();

    // 10. output projection -> d_out (704 x 512)
    sgemm_f32<<<dim3(EMB / 128, (SEQ + 127) / 128, 1), 256>>>(
        xout_p, o_w, (float*)d_out, o_b, SEQ, EMB, EMB);
}

// round 15
// speedup vs baseline: 1.4195x; 1.0441x over previous
#include <cuda_runtime.h>
#include <cuda_bf16.h>
#include <math.h>
#include <cstdint>

// ---------------- problem constants ----------------
#define NHEADS 8
#define HD 64
#define EMB 512
#define PS 16
#define GH 16
#define GW 44
#define SEQ 704            // GH*GW
#define NVIEW 6
#define MQ (NVIEW*SEQ)     // 4224
#define LM 16              // landmarks
#define KSEQ (5*SEQ)       // 3520
#define SCALE 0.125f       // 1/sqrt(64)

#define PE_C 256
#define IMG_H 256
#define IMG_W 704
#define K_PE (PE_C*PS*PS)  // 65536
#define K_X  (3*PS*PS)     // 768

#define MPAD 768           // 704 padded to 6x128
#define SPLITK 32
#define KSLICE (K_PE / SPLITK)   // 2048
#define KS 32                    // K per stage

// smem tile geometry: rows stored with 40-element (80B) stride for
// conflict-free ldmatrix; row = 32 bf16 (64B data + 16B pad).
#define ROWB 80
#define TILEB (128 * ROWB)       // 10240  (128-row tile)
#define STAGEB (4 * TILEB)       // 40960  (Ahi, Alo, Bhi, Blo) 128x128 kernel

// big-tile (M128 x N256) stage layout
#define BTILE_A TILEB                 // 10240 per A tile (128 rows)
#define BTILE_B (256 * ROWB)          // 20480 per B tile (256 rows)
#define BSTAGE (2 * BTILE_A + 2 * BTILE_B)   // 61440

// ---------------- scratch (device globals, no cudaMalloc) ----------------
__device__ float g_maskf[SEQ];
__device__ float g_qkv[MQ * 3 * EMB];
__device__ float g_scratch[SPLITK * SEQ * EMB];
__device__ float g_pe_tok[SEQ * EMB];
__device__ float g_qn[NHEADS * SEQ * HD];
__device__ float g_kn[NHEADS * KSEQ * HD];
__device__ float g_vc[NHEADS * KSEQ * HD];
__device__ float g_qL[NHEADS * LM * HD];
__device__ float g_kL[NHEADS * LM * HD];
__device__ float g_a1[NHEADS * SEQ * LM];
__device__ float g_a2[NHEADS * LM * KSEQ];
__device__ float g_a2v[NHEADS * LM * HD];

// bf16 hi/lo split operands
__device__ __nv_bfloat16 g_Ahi[(size_t)MPAD * K_PE];       // pe im2col
__device__ __nv_bfloat16 g_Alo[(size_t)MPAD * K_PE];
__device__ __nv_bfloat16 g_Bhi[(size_t)EMB * K_PE];        // conv_pe_w
__device__ __nv_bfloat16 g_Blo[(size_t)EMB * K_PE];
__device__ __nv_bfloat16 g_Axhi[(size_t)MQ * K_X];         // x im2col
__device__ __nv_bfloat16 g_Axlo[(size_t)MQ * K_X];
__device__ __nv_bfloat16 g_Bxhi[(size_t)EMB * K_X];        // conv_in_w
__device__ __nv_bfloat16 g_Bxlo[(size_t)EMB * K_X];
__device__ __nv_bfloat16 g_Tokhi[(size_t)MQ * EMB];        // tokens (x-embed out)
__device__ __nv_bfloat16 g_Toklo[(size_t)MQ * EMB];
__device__ __nv_bfloat16 g_Bqhi[(size_t)(3 * EMB) * EMB];  // qkv_w
__device__ __nv_bfloat16 g_Bqlo[(size_t)(3 * EMB) * EMB];
__device__ __nv_bfloat16 g_Xohi[(size_t)MPAD * EMB];       // attention out (pad rows stay 0)
__device__ __nv_bfloat16 g_Xolo[(size_t)MPAD * EMB];
__device__ __nv_bfloat16 g_Bohi[(size_t)EMB * EMB];        // o_w
__device__ __nv_bfloat16 g_Bolo[(size_t)EMB * EMB];

// ======================= PTX helpers (compute_103-safe) =======================
__device__ __forceinline__ uint32_t smem_u32(const void* p) {
    uint32_t a;
    asm("{ .reg .u64 t; cvta.to.shared.u64 t, %1; cvt.u32.u64 %0, t; }"
        : "=r"(a) : "l"(p));
    return a;
}

#define CP_ASYNC16(sp, gp) \
    asm volatile("cp.async.cg.shared.global [%0], [%1], 16;\n" :: "r"(sp), "l"(gp) : "memory")
#define CP_COMMIT() asm volatile("cp.async.commit_group;\n" ::: "memory")
#define CP_WAIT(n)  asm volatile("cp.async.wait_group %0;\n" :: "n"(n) : "memory")

#define LDSM4(r, addr) \
    asm volatile("ldmatrix.sync.aligned.m8n8.x4.shared.b16 {%0,%1,%2,%3}, [%4];" \
        : "=r"((r)[0]), "=r"((r)[1]), "=r"((r)[2]), "=r"((r)[3]) : "r"(addr))
#define LDSM2(r, addr) \
    asm volatile("ldmatrix.sync.aligned.m8n8.x2.shared.b16 {%0,%1}, [%2];" \
        : "=r"((r)[0]), "=r"((r)[1]) : "r"(addr))

#define MMA16816(d, a, b) \
    asm volatile("mma.sync.aligned.m16n8k16.row.col.f32.bf16.bf16.f32 " \
        "{%0,%1,%2,%3}, {%4,%5,%6,%7}, {%8,%9}, {%0,%1,%2,%3};" \
        : "+f"((d)[0]), "+f"((d)[1]), "+f"((d)[2]), "+f"((d)[3]) \
        : "r"((a)[0]), "r"((a)[1]), "r"((a)[2]), "r"((a)[3]), "r"((b)[0]), "r"((b)[1]))

// ---------------- patch mask: 16x16 avg pool > 0 ----------------
__global__ void mask_kernel(const float* __restrict__ mask_map, float* __restrict__ maskf) {
    int p = blockIdx.x;
    int gh = p / GW, gw = p % GW;
    int i = threadIdx.x >> 4, j = threadIdx.x & 15;
    float v = mask_map[(gh * PS + i) * IMG_W + gw * PS + j];
    __shared__ float red[256];
    red[threadIdx.x] = v;
    __syncthreads();
    for (int off = 128; off > 0; off >>= 1) {
        if (threadIdx.x < off) red[threadIdx.x] += red[threadIdx.x + off];
        __syncthreads();
    }
    if (threadIdx.x == 0) maskf[p] = (red[0] > 0.0f) ? 1.0f : 0.0f;
}

// ---------------- bf16 hi/lo conversion kernels ----------------
__device__ __forceinline__ void split4(float4 v, uint2& hi, uint2& lo) {
    __nv_bfloat16 h0 = __float2bfloat16(v.x);
    __nv_bfloat16 h1 = __float2bfloat16(v.y);
    __nv_bfloat16 h2 = __float2bfloat16(v.z);
    __nv_bfloat16 h3 = __float2bfloat16(v.w);
    __nv_bfloat16 l0 = __float2bfloat16(v.x - __bfloat162float(h0));
    __nv_bfloat16 l1 = __float2bfloat16(v.y - __bfloat162float(h1));
    __nv_bfloat16 l2 = __float2bfloat16(v.z - __bfloat162float(h2));
    __nv_bfloat16 l3 = __float2bfloat16(v.w - __bfloat162float(h3));
    __nv_bfloat162 ph0; ph0.x = h0; ph0.y = h1;
    __nv_bfloat162 ph1; ph1.x = h2; ph1.y = h3;
    __nv_bfloat162 pl0; pl0.x = l0; pl0.y = l1;
    __nv_bfloat162 pl1; pl1.x = l2; pl1.y = l3;
    hi.x = *reinterpret_cast<uint32_t*>(&ph0);
    hi.y = *reinterpret_cast<uint32_t*>(&ph1);
    lo.x = *reinterpret_cast<uint32_t*>(&pl0);
    lo.y = *reinterpret_cast<uint32_t*>(&pl1);
}

// pe A = im2col(pe[ft]) -> [MPAD][K_PE], rows >= SEQ zero
__global__ void conv_a_kernel(const float* __restrict__ pe, const int* __restrict__ ftag) {
    size_t idx = (size_t)blockIdx.x * 256 + threadIdx.x;
    int m = (int)(idx >> 14);               // K_PE/4 = 16384 chunks per row
    int kq = ((int)idx & 16383) << 2;
    float4 v = make_float4(0.f, 0.f, 0.f, 0.f);
    if (m < SEQ) {
        int c = kq >> 8, rem = kq & 255, i = rem >> 4, j = rem & 15;
        int gh = m / GW, gw = m % GW;
        const float* src = pe + (size_t)ftag[0] * PE_C * IMG_H * IMG_W
                              + ((size_t)c * IMG_H + gh * PS + i) * IMG_W + gw * PS + j;
        v = *(const float4*)src;
    }
    uint2 hi, lo;
    split4(v, hi, lo);
    size_t off = (size_t)m * K_PE + kq;
    *(uint2*)(g_Ahi + off) = hi;
    *(uint2*)(g_Alo + off) = lo;
}

// x A = im2col(x, all 6 views) -> [MQ][K_X]
__global__ void conv_ax_kernel(const float* __restrict__ x) {
    size_t idx = (size_t)blockIdx.x * 256 + threadIdx.x;  // per 4 elems
    int m = (int)(idx / (K_X / 4));
    int kq = ((int)(idx % (K_X / 4))) << 2;
    int c = kq >> 8, rem = kq & 255, i = rem >> 4, j = rem & 15;
    int v6 = m / SEQ, s = m % SEQ;
    int gh = s / GW, gw = s % GW;
    const float* src = x + (((size_t)(v6 * 3 + c)) * IMG_H + gh * PS + i) * IMG_W + gw * PS + j;
    float4 v = *(const float4*)src;
    uint2 hi, lo;
    split4(v, hi, lo);
    size_t off = (size_t)m * K_X + kq;
    *(uint2*)(g_Axhi + off) = hi;
    *(uint2*)(g_Axlo + off) = lo;
}

// generic weight split: row-major [n][k] fp32 -> bf16 hi/lo
__global__ void conv_w_kernel(const float* __restrict__ w,
                              __nv_bfloat16* __restrict__ whi,
                              __nv_bfloat16* __restrict__ wlo) {
    size_t idx = (size_t)blockIdx.x * 256 + threadIdx.x;
    size_t off = idx << 2;
    float4 v = *(const float4*)(w + off);
    uint2 hi, lo;
    split4(v, hi, lo);
    *(uint2*)(whi + off) = hi;
    *(uint2*)(wlo + off) = lo;
}

// =====================================================================
// pe GEMM (big tile): 512 threads, CTA tile M128 x N256, K-stage 32,
// double-buffered cp.async, 3-pass bf16 hi/lo, split-K into g_scratch.
// warps: warp_m (2) x warp_n (8); warp tile 64x32 (4x4 m16n8k16).
// Data chunks per stage: A 512 + A 512 + B 1024 + B 1024 = 3072 (16B each).
// =====================================================================
__device__ __forceinline__ void load_stage_big(uint32_t smbuf, int m0, int n0,
                                               int koff, int tid) {
#pragma unroll
    for (int it = 0; it < 6; it++) {
        int f = it * 512 + tid;                 // 0..3071 data chunks of 16B
        const __nv_bfloat16* g;
        int r0, local;
        uint32_t rbase;
        if (f < 512)       { g = g_Ahi; r0 = m0; local = f;        rbase = 0; }
        else if (f < 1024) { g = g_Alo; r0 = m0; local = f - 512;  rbase = BTILE_A; }
        else if (f < 2048) { g = g_Bhi; r0 = n0; local = f - 1024; rbase = 2 * BTILE_A; }
        else               { g = g_Blo; r0 = n0; local = f - 2048; rbase = 2 * BTILE_A + BTILE_B; }
        int row = local >> 2;                   // 4 chunks (64B) per row
        int q = local & 3;
        const __nv_bfloat16* gp = g + (size_t)(r0 + row) * K_PE + koff + q * 8;
        uint32_t sp = smbuf + rbase + row * ROWB + q * 16;
        CP_ASYNC16(sp, gp);
    }
    CP_COMMIT();
}

__global__ void __launch_bounds__(512, 1) pe_gemm_big() {
    extern __shared__ __align__(128) char dsm[];
    const uint32_t base = smem_u32(dsm);
    const int tid = threadIdx.x;
    const int wid = tid >> 5, lane = tid & 31;
    const int warp_m = wid >> 3;            // 0..1
    const int warp_n = wid & 7;             // 0..7
    const int n0 = blockIdx.x * 256;
    const int m0 = blockIdx.y * 128;
    const int z  = blockIdx.z;
    const int kbase = z * KSLICE;
    const int nstage = KSLICE / KS;         // 64

    float acc[4][4][4];
#pragma unroll
    for (int i = 0; i < 4; i++)
#pragma unroll
        for (int j = 0; j < 4; j++)
#pragma unroll
            for (int c = 0; c < 4; c++) acc[i][j][c] = 0.0f;

    const uint32_t a_off = (uint32_t)((warp_m * 64 + (lane & 15)) * ROWB + ((lane >> 4) << 4));
    const uint32_t b_off = (uint32_t)((warp_n * 32 + (lane & 7)) * ROWB + (((lane >> 3) & 1) << 4));

    load_stage_big(base, m0, n0, kbase, tid);

#pragma unroll 1
    for (int s = 0; s < nstage; s++) {
        uint32_t cb = base + (s & 1) * BSTAGE;
        if (s + 1 < nstage) {
            load_stage_big(base + ((s + 1) & 1) * BSTAGE, m0, n0, kbase + (s + 1) * KS, tid);
            CP_WAIT(1);
        } else {
            CP_WAIT(0);
        }
        __syncthreads();

        const uint32_t Ah = cb;
        const uint32_t Al = cb + BTILE_A;
        const uint32_t Bh = cb + 2 * BTILE_A;
        const uint32_t Bl = cb + 2 * BTILE_A + BTILE_B;

#pragma unroll
        for (int ks = 0; ks < 2; ks++) {
            uint32_t kb = ks * 32;
            uint32_t bh[4][2], bl[4][2];
#pragma unroll
            for (int nt = 0; nt < 4; nt++) {
                uint32_t boff = b_off + nt * 8 * ROWB + kb;
                LDSM2(bh[nt], Bh + boff);
                LDSM2(bl[nt], Bl + boff);
            }
#pragma unroll
            for (int mt = 0; mt < 4; mt++) {
                uint32_t ah[4], al[4];
                uint32_t aoff = a_off + mt * 16 * ROWB + kb;
                LDSM4(ah, Ah + aoff);
                LDSM4(al, Al + aoff);
#pragma unroll
                for (int nt = 0; nt < 4; nt++) {
                    MMA16816(acc[mt][nt], ah, bh[nt]);
                    MMA16816(acc[mt][nt], ah, bl[nt]);
                    MMA16816(acc[mt][nt], al, bh[nt]);
                }
            }
        }
        __syncthreads();
    }

    float* out = g_scratch + (size_t)z * SEQ * EMB;
    const int rbase = m0 + warp_m * 64 + (lane >> 2);
    const int cbase = n0 + warp_n * 32 + ((lane & 3) << 1);
#pragma unroll
    for (int mt = 0; mt < 4; mt++) {
#pragma unroll
        for (int nt = 0; nt < 4; nt++) {
            int r0 = rbase + mt * 16;
            int r1 = r0 + 8;
            int c  = cbase + nt * 8;
            if (r0 < SEQ)
                *(float2*)(out + (size_t)r0 * EMB + c) = make_float2(acc[mt][nt][0], acc[mt][nt][1]);
            if (r1 < SEQ)
                *(float2*)(out + (size_t)r1 * EMB + c) = make_float2(acc[mt][nt][2], acc[mt][nt][3]);
        }
    }
}

// ---------------- unified bf16 3-pass mma GEMM (128x128 tile) ----------------
// EPI 1: (acc+bias)*mask -> bf16 hi/lo outputs (x-embed -> tokens)
// EPI 2: acc+bias -> fp32, rows < Mvalid only (QKV, out-proj)
__device__ __forceinline__ void load_stage_g(
    uint32_t smbuf,
    const __nv_bfloat16* __restrict__ Ahi, const __nv_bfloat16* __restrict__ Alo,
    const __nv_bfloat16* __restrict__ Bhi, const __nv_bfloat16* __restrict__ Blo,
    int m0, int n0, int koff, int Ktot, int tid)
{
#pragma unroll
    for (int it = 0; it < 8; it++) {
        int f = it * 256 + tid;        // 0..2047 chunks of 16B
        int tile = f >> 9;             // 0:Ahi 1:Alo 2:Bhi 3:Blo
        int idx = f & 511;
        int row = idx >> 2;
        int q = idx & 3;
        const __nv_bfloat16* g;
        int r0;
        if (tile == 0)      { g = Ahi; r0 = m0; }
        else if (tile == 1) { g = Alo; r0 = m0; }
        else if (tile == 2) { g = Bhi; r0 = n0; }
        else                { g = Blo; r0 = n0; }
        const __nv_bfloat16* gp = g + (size_t)(r0 + row) * Ktot + koff + q * 8;
        uint32_t sp = smbuf + tile * TILEB + row * ROWB + q * 16;
        CP_ASYNC16(sp, gp);
    }
    CP_COMMIT();
}

template<int EPI>
__global__ void __launch_bounds__(256, 2) mma_gemm(
    const __nv_bfloat16* __restrict__ Ahi, const __nv_bfloat16* __restrict__ Alo,
    const __nv_bfloat16* __restrict__ Bhi, const __nv_bfloat16* __restrict__ Blo,
    int Ktot,
    float* __restrict__ outf,
    __nv_bfloat16* __restrict__ outhi, __nv_bfloat16* __restrict__ outlo,
    const float* __restrict__ bias, const float* __restrict__ maskf,
    int Nld, int Mvalid)
{
    extern __shared__ __align__(128) char dsm[];
    const uint32_t base = smem_u32(dsm);
    const int tid = threadIdx.x;
    const int wid = tid >> 5, lane = tid & 31;
    const int warp_m = wid >> 2;
    const int warp_n = wid & 3;
    const int n0 = blockIdx.x * 128;
    const int m0 = blockIdx.y * 128;
    const int nstage = Ktot / KS;

    float acc[4][4][4];
#pragma unroll
    for (int i = 0; i < 4; i++)
#pragma unroll
        for (int j = 0; j < 4; j++)
#pragma unroll
            for (int c = 0; c < 4; c++) acc[i][j][c] = 0.0f;

    const uint32_t a_off = (uint32_t)((warp_m * 64 + (lane & 15)) * ROWB + ((lane >> 4) << 4));
    const uint32_t b_off = (uint32_t)((warp_n * 32 + (lane & 7)) * ROWB + (((lane >> 3) & 1) << 4));

    load_stage_g(base, Ahi, Alo, Bhi, Blo, m0, n0, 0, Ktot, tid);

#pragma unroll 1
    for (int s = 0; s < nstage; s++) {
        uint32_t cb = base + (s & 1) * STAGEB;
        if (s + 1 < nstage) {
            load_stage_g(base + ((s + 1) & 1) * STAGEB, Ahi, Alo, Bhi, Blo,
                         m0, n0, (s + 1) * KS, Ktot, tid);
            CP_WAIT(1);
        } else {
            CP_WAIT(0);
        }
        __syncthreads();

        const uint32_t Ah = cb;
        const uint32_t Al = cb + TILEB;
        const uint32_t Bh = cb + 2 * TILEB;
        const uint32_t Bl = cb + 3 * TILEB;

#pragma unroll
        for (int ks = 0; ks < 2; ks++) {
            uint32_t kb = ks * 32;
            uint32_t bh[4][2], bl[4][2];
#pragma unroll
            for (int nt = 0; nt < 4; nt++) {
                uint32_t boff = b_off + nt * 8 * ROWB + kb;
                LDSM2(bh[nt], Bh + boff);
                LDSM2(bl[nt], Bl + boff);
            }
#pragma unroll
            for (int mt = 0; mt < 4; mt++) {
                uint32_t ah[4], al[4];
                uint32_t aoff = a_off + mt * 16 * ROWB + kb;
                LDSM4(ah, Ah + aoff);
                LDSM4(al, Al + aoff);
#pragma unroll
                for (int nt = 0; nt < 4; nt++) {
                    MMA16816(acc[mt][nt], ah, bh[nt]);
                    MMA16816(acc[mt][nt], ah, bl[nt]);
                    MMA16816(acc[mt][nt], al, bh[nt]);
                }
            }
        }
        __syncthreads();
    }

    const int rbase = m0 + warp_m * 64 + (lane >> 2);
    const int cbase = n0 + warp_n * 32 + ((lane & 3) << 1);
#pragma unroll
    for (int mt = 0; mt < 4; mt++) {
#pragma unroll
        for (int nt = 0; nt < 4; nt++) {
            int r0 = rbase + mt * 16;
            int r1 = r0 + 8;
            int c  = cbase + nt * 8;
            if (EPI == 1) {
                float b0 = bias[c], b1 = bias[c + 1];
                float mk0 = maskf[r0 % SEQ];
                float mk1 = maskf[r1 % SEQ];
                float v0 = (acc[mt][nt][0] + b0) * mk0;
                float v1 = (acc[mt][nt][1] + b1) * mk0;
                float v2 = (acc[mt][nt][2] + b0) * mk1;
                float v3 = (acc[mt][nt][3] + b1) * mk1;
                __nv_bfloat16 h0 = __float2bfloat16(v0), h1 = __float2bfloat16(v1);
                __nv_bfloat16 h2 = __float2bfloat16(v2), h3 = __float2bfloat16(v3);
                __nv_bfloat162 hh0; hh0.x = h0; hh0.y = h1;
                __nv_bfloat162 hh1; hh1.x = h2; hh1.y = h3;
                __nv_bfloat162 ll0;
                ll0.x = __float2bfloat16(v0 - __bfloat162float(h0));
                ll0.y = __float2bfloat16(v1 - __bfloat162float(h1));
                __nv_bfloat162 ll1;
                ll1.x = __float2bfloat16(v2 - __bfloat162float(h2));
                ll1.y = __float2bfloat16(v3 - __bfloat162float(h3));
                *(__nv_bfloat162*)(outhi + (size_t)r0 * Nld + c) = hh0;
                *(__nv_bfloat162*)(outlo + (size_t)r0 * Nld + c) = ll0;
                *(__nv_bfloat162*)(outhi + (size_t)r1 * Nld + c) = hh1;
                *(__nv_bfloat162*)(outlo + (size_t)r1 * Nld + c) = ll1;
            } else {
                float b0 = bias[c], b1 = bias[c + 1];
                if (r0 < Mvalid)
                    *(float2*)(outf + (size_t)r0 * Nld + c) =
                        make_float2(acc[mt][nt][0] + b0, acc[mt][nt][1] + b1);
                if (r1 < Mvalid)
                    *(float2*)(outf + (size_t)r1 * Nld + c) =
                        make_float2(acc[mt][nt][2] + b0, acc[mt][nt][3] + b1);
            }
        }
    }
}

// ---------------- reduce split-K pe partials + bias + mask ----------------
__global__ void reduce_pe_kernel(const float* __restrict__ bias,
                                 const float* __restrict__ maskf) {
    int idx = blockIdx.x * blockDim.x + threadIdx.x;
    if (idx >= SEQ * EMB) return;
    int n = idx % EMB;
    int m = idx / EMB;
    float acc = bias[n];
#pragma unroll
    for (int z = 0; z < SPLITK; z++) acc += g_scratch[(size_t)z * SEQ * EMB + idx];
    g_pe_tok[idx] = acc * maskf[m];
}

// ---------------- q/k prep, landmarks, attention core ----------------
__device__ __forceinline__ float block64_sum(float v, float* red2) {
    for (int off = 16; off > 0; off >>= 1)
        v += __shfl_xor_sync(0xffffffffu, v, off);
    if ((threadIdx.x & 31) == 0) red2[threadIdx.x >> 5] = v;
    __syncthreads();
    return red2[0] + red2[1];
}

__global__ void prep_q_kernel(const int* __restrict__ ftag) {
    int s = blockIdx.x, h = blockIdx.y, e = threadIdx.x;
    int ft = ftag[0];
    float val = g_qkv[((size_t)(ft * SEQ + s)) * (3 * EMB) + h * (3 * HD) + e]
              + g_pe_tok[(size_t)s * EMB + h * HD + e];
    __shared__ float red2[2];
    float tot = block64_sum(val * val, red2);
    float denom = fmaxf(sqrtf(tot), 1e-12f);
    g_qn[((size_t)h * SEQ + s) * HD + e] = val / denom;
}

__global__ void prep_k_kernel(const int* __restrict__ ftag) {
    int t = blockIdx.x, h = blockIdx.y, e = threadIdx.x;
    int ft = ftag[0];
    int vi = t / SEQ;
    int view = (vi < ft) ? vi : vi + 1;
    int s = t % SEQ;
    size_t base = ((size_t)(view * SEQ + s)) * (3 * EMB) + h * (3 * HD);
    float kval = g_qkv[base + HD + e];
    float vval = g_qkv[base + 2 * HD + e];
    __shared__ float red2[2];
    float tot = block64_sum(kval * kval, red2);
    float denom = fmaxf(sqrtf(tot), 1e-12f);
    g_kn[((size_t)h * KSEQ + t) * HD + e] = kval / denom;
    g_vc[((size_t)h * KSEQ + t) * HD + e] = vval;
}

__global__ void landmark_kernel(const float* __restrict__ src, float* __restrict__ dst, int seg) {
    int l = blockIdx.x, h = blockIdx.y, e = threadIdx.x;
    int S = LM * seg;
    const float* p = src + ((size_t)h * S + (size_t)l * seg) * HD + e;
    float acc = 0.f;
    for (int r = 0; r < seg; r++) acc += p[(size_t)r * HD];
    dst[((size_t)h * LM + l) * HD + e] = acc / (float)seg;
}

__global__ void a1_kernel() {
    int warp = threadIdx.x >> 5, lane = threadIdx.x & 31;
    int s = blockIdx.x * 4 + warp;
    int h = blockIdx.y;
    const float* qp = g_qn + ((size_t)h * SEQ + s) * HD;
    float q0 = qp[lane], q1 = qp[lane + 32];
    float lg[LM];
#pragma unroll
    for (int l = 0; l < LM; l++) {
        const float* kp = g_kL + ((size_t)h * LM + l) * HD;
        float p = q0 * kp[lane] + q1 * kp[lane + 32];
        for (int off = 16; off > 0; off >>= 1)
            p += __shfl_xor_sync(0xffffffffu, p, off);
        lg[l] = p * SCALE;
    }
    float mx = lg[0];
#pragma unroll
    for (int l = 1; l < LM; l++) mx = fmaxf(mx, lg[l]);
    float sum = 0.f;
#pragma unroll
    for (int l = 0; l < LM; l++) { lg[l] = expf(lg[l] - mx); sum += lg[l]; }
    float inv = 1.0f / sum;
    if (lane < LM)
        g_a1[((size_t)h * SEQ + s) * LM + lane] = lg[lane] * inv;
}

__global__ void a2_kernel() {
    int l = blockIdx.x, h = blockIdx.y, tid = threadIdx.x;
    __shared__ float sq[HD];
    __shared__ float lg[KSEQ];
    __shared__ float red[256];
    if (tid < HD) sq[tid] = g_qL[((size_t)h * LM + l) * HD + tid];
    __syncthreads();

    for (int t = tid; t < KSEQ; t += 256) {
        const float* kp = g_kn + ((size_t)h * KSEQ + t) * HD;
        float d = 0.f;
#pragma unroll
        for (int e = 0; e < HD; e += 4) {
            float4 kv = *(const float4*)(kp + e);
            d += kv.x * sq[e] + kv.y * sq[e + 1] + kv.z * sq[e + 2] + kv.w * sq[e + 3];
        }
        lg[t] = d * SCALE;
    }
    __syncthreads();

    float lmax = -1e30f;
    for (int t = tid; t < KSEQ; t += 256) lmax = fmaxf(lmax, lg[t]);
    red[tid] = lmax;
    __syncthreads();
    for (int off = 128; off > 0; off >>= 1) {
        if (tid < off) red[tid] = fmaxf(red[tid], red[tid + off]);
        __syncthreads();
    }
    float gmax = red[0];
    __syncthreads();

    float lsum = 0.f;
    for (int t = tid; t < KSEQ; t += 256) {
        float e = expf(lg[t] - gmax);
        lg[t] = e;
        lsum += e;
    }
    red[tid] = lsum;
    __syncthreads();
    for (int off = 128; off > 0; off >>= 1) {
        if (tid < off) red[tid] += red[tid + off];
        __syncthreads();
    }
    float inv = 1.0f / red[0];
    float* out = g_a2 + ((size_t)h * LM + l) * KSEQ;
    for (int t = tid; t < KSEQ; t += 256) out[t] = lg[t] * inv;
}

// a2v: 256 threads, 4-way partial over K
__global__ void a2v_kernel() {
    int l = blockIdx.x, h = blockIdx.y;
    int e = threadIdx.x & 63;
    int part = threadIdx.x >> 6;          // 0..3
    const float* ar = g_a2 + ((size_t)h * LM + l) * KSEQ;
    const float* vp = g_vc + (size_t)h * KSEQ * HD + e;
    float acc = 0.f;
    int t0 = part * (KSEQ / 4), t1 = t0 + (KSEQ / 4);
#pragma unroll 4
    for (int t = t0; t < t1; t++) acc += ar[t] * vp[(size_t)t * HD];
    __shared__ float red[4][HD];
    red[part][e] = acc;
    __syncthreads();
    if (part == 0)
        g_a2v[((size_t)h * LM + l) * HD + e] =
            red[0][e] + red[1][e] + red[2][e] + red[3][e];
}

// vals = a1 @ a2v -> bf16 hi/lo (input A of out-proj GEMM)
__global__ void vals_kernel() {
    int s = blockIdx.x;
    int h = threadIdx.x >> 6;
    int e = threadIdx.x & 63;
    const float* ap = g_a1 + ((size_t)h * SEQ + s) * LM;
    const float* bp = g_a2v + (size_t)h * LM * HD + e;
    float acc = 0.f;
#pragma unroll
    for (int l = 0; l < LM; l++) acc += ap[l] * bp[(size_t)l * HD];
    __nv_bfloat16 hv = __float2bfloat16(acc);
    size_t off = (size_t)s * EMB + h * HD + e;
    g_Xohi[off] = hv;
    g_Xolo[off] = __float2bfloat16(acc - __bfloat162float(hv));
}

// ---------------- launch ----------------
extern "C" void kernel_launch(void* const* d_in, const int* in_sizes, int n_in,
                              void* d_out, int out_size) {
    const float* x         = (const float*)d_in[0];
    const float* pe        = (const float*)d_in[1];
    const float* mask_map  = (const float*)d_in[2];
    const float* conv_in_w = (const float*)d_in[3];
    const float* conv_in_b = (const float*)d_in[4];
    const float* conv_pe_w = (const float*)d_in[5];
    const float* conv_pe_b = (const float*)d_in[6];
    const float* qkv_w     = (const float*)d_in[7];
    const float* qkv_b     = (const float*)d_in[8];
    const float* o_w       = (const float*)d_in[9];
    const float* o_b       = (const float*)d_in[10];
    const int*   ftag      = (const int*)d_in[11];

    float* maskf_p;   cudaGetSymbolAddress((void**)&maskf_p,   g_maskf);
    float* qkv_p;     cudaGetSymbolAddress((void**)&qkv_p,     g_qkv);
    float* qn_p;      cudaGetSymbolAddress((void**)&qn_p,      g_qn);
    float* kn_p;      cudaGetSymbolAddress((void**)&kn_p,      g_kn);
    float* qL_p;      cudaGetSymbolAddress((void**)&qL_p,      g_qL);
    float* kL_p;      cudaGetSymbolAddress((void**)&kL_p,      g_kL);
    __nv_bfloat16 *Bhi_p, *Blo_p;
    cudaGetSymbolAddress((void**)&Bhi_p, g_Bhi);
    cudaGetSymbolAddress((void**)&Blo_p, g_Blo);
    __nv_bfloat16 *Axhi_p, *Axlo_p, *Bxhi_p, *Bxlo_p;
    cudaGetSymbolAddress((void**)&Axhi_p, g_Axhi);
    cudaGetSymbolAddress((void**)&Axlo_p, g_Axlo);
    cudaGetSymbolAddress((void**)&Bxhi_p, g_Bxhi);
    cudaGetSymbolAddress((void**)&Bxlo_p, g_Bxlo);
    __nv_bfloat16 *Tokhi_p, *Toklo_p, *Bqhi_p, *Bqlo_p;
    cudaGetSymbolAddress((void**)&Tokhi_p, g_Tokhi);
    cudaGetSymbolAddress((void**)&Toklo_p, g_Toklo);
    cudaGetSymbolAddress((void**)&Bqhi_p, g_Bqhi);
    cudaGetSymbolAddress((void**)&Bqlo_p, g_Bqlo);
    __nv_bfloat16 *Xohi_p, *Xolo_p, *Bohi_p, *Bolo_p;
    cudaGetSymbolAddress((void**)&Xohi_p, g_Xohi);
    cudaGetSymbolAddress((void**)&Xolo_p, g_Xolo);
    cudaGetSymbolAddress((void**)&Bohi_p, g_Bohi);
    cudaGetSymbolAddress((void**)&Bolo_p, g_Bolo);

    static int inited = 0;
    if (!inited) {
        cudaFuncSetAttribute(pe_gemm_big, cudaFuncAttributeMaxDynamicSharedMemorySize, 2 * BSTAGE);
        cudaFuncSetAttribute(mma_gemm<1>, cudaFuncAttributeMaxDynamicSharedMemorySize, 2 * STAGEB);
        cudaFuncSetAttribute(mma_gemm<2>, cudaFuncAttributeMaxDynamicSharedMemorySize, 2 * STAGEB);
        inited = 1;
    }

    // 1. patch mask
    mask_kernel<<<SEQ, 256>>>(mask_map, maskf_p);

    // 2. operand conversions
    conv_a_kernel<<<(MPAD * (K_PE / 4)) / 256, 256>>>(pe, ftag);
    conv_w_kernel<<<(int)(((size_t)EMB * K_PE / 4) / 256), 256>>>(conv_pe_w, Bhi_p, Blo_p);
    conv_ax_kernel<<<(MQ * (K_X / 4)) / 256, 256>>>(x);
    conv_w_kernel<<<(EMB * K_X / 4) / 256, 256>>>(conv_in_w, Bxhi_p, Bxlo_p);
    conv_w_kernel<<<(3 * EMB * EMB / 4) / 256, 256>>>(qkv_w, Bqhi_p, Bqlo_p);
    conv_w_kernel<<<(EMB * EMB / 4) / 256, 256>>>(o_w, Bohi_p, Bolo_p);

    // 3. pe GEMM (big tile, split-K=32 into g_scratch)
    pe_gemm_big<<<dim3(EMB / 256, MPAD / 128, SPLITK), 512, 2 * BSTAGE>>>();

    // 4. reduce split-K + bias + mask -> pe_tok
    reduce_pe_kernel<<<(SEQ * EMB + 255) / 256, 256>>>(conv_pe_b, maskf_p);

    // 5. x patch embed -> tokens as bf16 hi/lo (bias + mask in epilogue)
    mma_gemm<1><<<dim3(EMB / 128, MQ / 128, 1), 256, 2 * STAGEB>>>(
        Axhi_p, Axlo_p, Bxhi_p, Bxlo_p, K_X,
        nullptr, Tokhi_p, Toklo_p, conv_in_b, maskf_p, EMB, MQ);

    // 6. QKV: tokens @ qkv_w^T + b -> fp32 g_qkv
    mma_gemm<2><<<dim3((3 * EMB) / 128, MQ / 128, 1), 256, 2 * STAGEB>>>(
        Tokhi_p, Toklo_p, Bqhi_p, Bqlo_p, EMB,
        qkv_p, nullptr, nullptr, qkv_b, nullptr, 3 * EMB, MQ);

    // 7. normalized q (+pe) and k, raw v gather
    prep_q_kernel<<<dim3(SEQ, NHEADS), HD>>>(ftag);
    prep_k_kernel<<<dim3(KSEQ, NHEADS), HD>>>(ftag);

    // 8. landmarks
    landmark_kernel<<<dim3(LM, NHEADS), HD>>>(qn_p, qL_p, SEQ / LM);
    landmark_kernel<<<dim3(LM, NHEADS), HD>>>(kn_p, kL_p, KSEQ / LM);

    // 9. attention core
    a1_kernel<<<dim3(SEQ / 4, NHEADS), 128>>>();
    a2_kernel<<<dim3(LM, NHEADS), 256>>>();
    a2v_kernel<<<dim3(LM, NHEADS), 256>>>();
    vals_kernel<<<SEQ, EMB>>>();

    // 10. output projection via mma (rows >= SEQ in pad are zero, writes guarded)
    mma_gemm<2><<<dim3(EMB / 128, MPAD / 128, 1), 256, 2 * STAGEB>>>(
        Xohi_p, Xolo_p, Bohi_p, Bolo_p, EMB,
        (float*)d_out, nullptr, nullptr, o_b, nullptr, EMB, SEQ);
}

// round 16
// speedup vs baseline: 1.4295x; 1.0071x over previous
#include <cuda_runtime.h>
#include <cuda_bf16.h>
#include <math.h>
#include <cstdint>

// ---------------- problem constants ----------------
#define NHEADS 8
#define HD 64
#define EMB 512
#define PS 16
#define GH 16
#define GW 44
#define SEQ 704            // GH*GW
#define NVIEW 6
#define MQ (NVIEW*SEQ)     // 4224
#define LM 16              // landmarks
#define KSEQ (5*SEQ)       // 3520
#define SCALE 0.125f       // 1/sqrt(64)

#define PE_C 256
#define IMG_H 256
#define IMG_W 704
#define K_PE (PE_C*PS*PS)  // 65536
#define K_X  (3*PS*PS)     // 768

#define MPAD 768           // 704 padded to 6x128
#define SPLITK 32
#define KSLICE (K_PE / SPLITK)   // 2048
#define KS 32                    // K per stage

// smem tile geometry: rows stored with 40-element (80B) stride for
// conflict-free ldmatrix; row = 32 bf16 (64B data + 16B pad).
#define ROWB 80
#define TILEB (128 * ROWB)       // 10240  (128-row tile)
#define STAGEB (4 * TILEB)       // 40960  (Ahi, Alo, Bhi, Blo) 128x128 kernel

// big-tile (M128 x N256) stage layout
#define BTILE_A TILEB                 // 10240 per A tile (128 rows)
#define BTILE_B (256 * ROWB)          // 20480 per B tile (256 rows)
#define BSTAGE (2 * BTILE_A + 2 * BTILE_B)   // 61440
#define NBUF 3                        // 3-stage ring, 184320 B smem

// ---------------- scratch (device globals, no cudaMalloc) ----------------
__device__ float g_maskf[SEQ];
__device__ float g_qkv[MQ * 3 * EMB];
__device__ float g_scratch[SPLITK * SEQ * EMB];
__device__ float g_pe_tok[SEQ * EMB];
__device__ float g_qn[NHEADS * SEQ * HD];
__device__ float g_kn[NHEADS * KSEQ * HD];
__device__ float g_vc[NHEADS * KSEQ * HD];
__device__ float g_qL[NHEADS * LM * HD];
__device__ float g_kL[NHEADS * LM * HD];
__device__ float g_a1[NHEADS * SEQ * LM];
__device__ float g_a2[NHEADS * LM * KSEQ];
__device__ float g_a2v[NHEADS * LM * HD];

// bf16 hi/lo split operands
__device__ __nv_bfloat16 g_Ahi[(size_t)MPAD * K_PE];       // pe im2col
__device__ __nv_bfloat16 g_Alo[(size_t)MPAD * K_PE];
__device__ __nv_bfloat16 g_Bhi[(size_t)EMB * K_PE];        // conv_pe_w
__device__ __nv_bfloat16 g_Blo[(size_t)EMB * K_PE];
__device__ __nv_bfloat16 g_Axhi[(size_t)MQ * K_X];         // x im2col
__device__ __nv_bfloat16 g_Axlo[(size_t)MQ * K_X];
__device__ __nv_bfloat16 g_Bxhi[(size_t)EMB * K_X];        // conv_in_w
__device__ __nv_bfloat16 g_Bxlo[(size_t)EMB * K_X];
__device__ __nv_bfloat16 g_Tokhi[(size_t)MQ * EMB];        // tokens (x-embed out)
__device__ __nv_bfloat16 g_Toklo[(size_t)MQ * EMB];
__device__ __nv_bfloat16 g_Bqhi[(size_t)(3 * EMB) * EMB];  // qkv_w
__device__ __nv_bfloat16 g_Bqlo[(size_t)(3 * EMB) * EMB];
__device__ __nv_bfloat16 g_Xohi[(size_t)MPAD * EMB];       // attention out (pad rows stay 0)
__device__ __nv_bfloat16 g_Xolo[(size_t)MPAD * EMB];
__device__ __nv_bfloat16 g_Bohi[(size_t)EMB * EMB];        // o_w
__device__ __nv_bfloat16 g_Bolo[(size_t)EMB * EMB];

// ======================= PTX helpers (compute_103-safe) =======================
__device__ __forceinline__ uint32_t smem_u32(const void* p) {
    uint32_t a;
    asm("{ .reg .u64 t; cvta.to.shared.u64 t, %1; cvt.u32.u64 %0, t; }"
        : "=r"(a) : "l"(p));
    return a;
}

#define CP_ASYNC16(sp, gp) \
    asm volatile("cp.async.cg.shared.global [%0], [%1], 16;\n" :: "r"(sp), "l"(gp) : "memory")
#define CP_COMMIT() asm volatile("cp.async.commit_group;\n" ::: "memory")
#define CP_WAIT(n)  asm volatile("cp.async.wait_group %0;\n" :: "n"(n) : "memory")

#define LDSM4(r, addr) \
    asm volatile("ldmatrix.sync.aligned.m8n8.x4.shared.b16 {%0,%1,%2,%3}, [%4];" \
        : "=r"((r)[0]), "=r"((r)[1]), "=r"((r)[2]), "=r"((r)[3]) : "r"(addr))
#define LDSM2(r, addr) \
    asm volatile("ldmatrix.sync.aligned.m8n8.x2.shared.b16 {%0,%1}, [%2];" \
        : "=r"((r)[0]), "=r"((r)[1]) : "r"(addr))

#define MMA16816(d, a, b) \
    asm volatile("mma.sync.aligned.m16n8k16.row.col.f32.bf16.bf16.f32 " \
        "{%0,%1,%2,%3}, {%4,%5,%6,%7}, {%8,%9}, {%0,%1,%2,%3};" \
        : "+f"((d)[0]), "+f"((d)[1]), "+f"((d)[2]), "+f"((d)[3]) \
        : "r"((a)[0]), "r"((a)[1]), "r"((a)[2]), "r"((a)[3]), "r"((b)[0]), "r"((b)[1]))

// ---------------- patch mask: 16x16 avg pool > 0 ----------------
__global__ void mask_kernel(const float* __restrict__ mask_map, float* __restrict__ maskf) {
    int p = blockIdx.x;
    int gh = p / GW, gw = p % GW;
    int i = threadIdx.x >> 4, j = threadIdx.x & 15;
    float v = mask_map[(gh * PS + i) * IMG_W + gw * PS + j];
    __shared__ float red[256];
    red[threadIdx.x] = v;
    __syncthreads();
    for (int off = 128; off > 0; off >>= 1) {
        if (threadIdx.x < off) red[threadIdx.x] += red[threadIdx.x + off];
        __syncthreads();
    }
    if (threadIdx.x == 0) maskf[p] = (red[0] > 0.0f) ? 1.0f : 0.0f;
}

// ---------------- bf16 hi/lo conversion kernels ----------------
__device__ __forceinline__ void split4(float4 v, uint2& hi, uint2& lo) {
    __nv_bfloat16 h0 = __float2bfloat16(v.x);
    __nv_bfloat16 h1 = __float2bfloat16(v.y);
    __nv_bfloat16 h2 = __float2bfloat16(v.z);
    __nv_bfloat16 h3 = __float2bfloat16(v.w);
    __nv_bfloat16 l0 = __float2bfloat16(v.x - __bfloat162float(h0));
    __nv_bfloat16 l1 = __float2bfloat16(v.y - __bfloat162float(h1));
    __nv_bfloat16 l2 = __float2bfloat16(v.z - __bfloat162float(h2));
    __nv_bfloat16 l3 = __float2bfloat16(v.w - __bfloat162float(h3));
    __nv_bfloat162 ph0; ph0.x = h0; ph0.y = h1;
    __nv_bfloat162 ph1; ph1.x = h2; ph1.y = h3;
    __nv_bfloat162 pl0; pl0.x = l0; pl0.y = l1;
    __nv_bfloat162 pl1; pl1.x = l2; pl1.y = l3;
    hi.x = *reinterpret_cast<uint32_t*>(&ph0);
    hi.y = *reinterpret_cast<uint32_t*>(&ph1);
    lo.x = *reinterpret_cast<uint32_t*>(&pl0);
    lo.y = *reinterpret_cast<uint32_t*>(&pl1);
}

// pe A = im2col(pe[ft]) -> [MPAD][K_PE], rows >= SEQ zero
__global__ void conv_a_kernel(const float* __restrict__ pe, const int* __restrict__ ftag) {
    size_t idx = (size_t)blockIdx.x * 256 + threadIdx.x;
    int m = (int)(idx >> 14);               // K_PE/4 = 16384 chunks per row
    int kq = ((int)idx & 16383) << 2;
    float4 v = make_float4(0.f, 0.f, 0.f, 0.f);
    if (m < SEQ) {
        int c = kq >> 8, rem = kq & 255, i = rem >> 4, j = rem & 15;
        int gh = m / GW, gw = m % GW;
        const float* src = pe + (size_t)ftag[0] * PE_C * IMG_H * IMG_W
                              + ((size_t)c * IMG_H + gh * PS + i) * IMG_W + gw * PS + j;
        v = *(const float4*)src;
    }
    uint2 hi, lo;
    split4(v, hi, lo);
    size_t off = (size_t)m * K_PE + kq;
    *(uint2*)(g_Ahi + off) = hi;
    *(uint2*)(g_Alo + off) = lo;
}

// x A = im2col(x, all 6 views) -> [MQ][K_X]
__global__ void conv_ax_kernel(const float* __restrict__ x) {
    size_t idx = (size_t)blockIdx.x * 256 + threadIdx.x;  // per 4 elems
    int m = (int)(idx / (K_X / 4));
    int kq = ((int)(idx % (K_X / 4))) << 2;
    int c = kq >> 8, rem = kq & 255, i = rem >> 4, j = rem & 15;
    int v6 = m / SEQ, s = m % SEQ;
    int gh = s / GW, gw = s % GW;
    const float* src = x + (((size_t)(v6 * 3 + c)) * IMG_H + gh * PS + i) * IMG_W + gw * PS + j;
    float4 v = *(const float4*)src;
    uint2 hi, lo;
    split4(v, hi, lo);
    size_t off = (size_t)m * K_X + kq;
    *(uint2*)(g_Axhi + off) = hi;
    *(uint2*)(g_Axlo + off) = lo;
}

// generic weight split: row-major [n][k] fp32 -> bf16 hi/lo
__global__ void conv_w_kernel(const float* __restrict__ w,
                              __nv_bfloat16* __restrict__ whi,
                              __nv_bfloat16* __restrict__ wlo) {
    size_t idx = (size_t)blockIdx.x * 256 + threadIdx.x;
    size_t off = idx << 2;
    float4 v = *(const float4*)(w + off);
    uint2 hi, lo;
    split4(v, hi, lo);
    *(uint2*)(whi + off) = hi;
    *(uint2*)(wlo + off) = lo;
}

// =====================================================================
// pe GEMM (big tile): 512 threads, CTA tile M128 x N256, K-stage 32,
// 3-stage cp.async ring (one __syncthreads per stage), 3-pass bf16
// hi/lo, split-K into g_scratch.
// warps: warp_m (2) x warp_n (8); warp tile 64x32 (4x4 m16n8k16).
// Data chunks per stage: A 512 + A 512 + B 1024 + B 1024 = 3072 (16B each).
// =====================================================================
__device__ __forceinline__ void load_stage_big(uint32_t smbuf, int m0, int n0,
                                               int koff, int tid) {
#pragma unroll
    for (int it = 0; it < 6; it++) {
        int f = it * 512 + tid;                 // 0..3071 data chunks of 16B
        const __nv_bfloat16* g;
        int r0, local;
        uint32_t rbase;
        if (f < 512)       { g = g_Ahi; r0 = m0; local = f;        rbase = 0; }
        else if (f < 1024) { g = g_Alo; r0 = m0; local = f - 512;  rbase = BTILE_A; }
        else if (f < 2048) { g = g_Bhi; r0 = n0; local = f - 1024; rbase = 2 * BTILE_A; }
        else               { g = g_Blo; r0 = n0; local = f - 2048; rbase = 2 * BTILE_A + BTILE_B; }
        int row = local >> 2;                   // 4 chunks (64B) per row
        int q = local & 3;
        const __nv_bfloat16* gp = g + (size_t)(r0 + row) * K_PE + koff + q * 8;
        uint32_t sp = smbuf + rbase + row * ROWB + q * 16;
        CP_ASYNC16(sp, gp);
    }
    CP_COMMIT();
}

__global__ void __launch_bounds__(512, 1) pe_gemm_big() {
    extern __shared__ __align__(128) char dsm[];
    const uint32_t base = smem_u32(dsm);
    const int tid = threadIdx.x;
    const int wid = tid >> 5, lane = tid & 31;
    const int warp_m = wid >> 3;            // 0..1
    const int warp_n = wid & 7;             // 0..7
    const int n0 = blockIdx.x * 256;
    const int m0 = blockIdx.y * 128;
    const int z  = blockIdx.z;
    const int kbase = z * KSLICE;
    const int nstage = KSLICE / KS;         // 64

    float acc[4][4][4];
#pragma unroll
    for (int i = 0; i < 4; i++)
#pragma unroll
        for (int j = 0; j < 4; j++)
#pragma unroll
            for (int c = 0; c < 4; c++) acc[i][j][c] = 0.0f;

    const uint32_t a_off = (uint32_t)((warp_m * 64 + (lane & 15)) * ROWB + ((lane >> 4) << 4));
    const uint32_t b_off = (uint32_t)((warp_n * 32 + (lane & 7)) * ROWB + (((lane >> 3) & 1) << 4));

    // prime ring with stages 0 and 1
    load_stage_big(base + 0 * BSTAGE, m0, n0, kbase + 0 * KS, tid);
    load_stage_big(base + 1 * BSTAGE, m0, n0, kbase + 1 * KS, tid);

    int cur = 0;   // ring slot of stage s
#pragma unroll 1
    for (int s = 0; s < nstage; s++) {
        // wait for stage s's group (leave s+1's in flight); last stage: drain all
        if (s == nstage - 1) { CP_WAIT(0); } else { CP_WAIT(1); }
        __syncthreads();
        // issue load for stage s+2 into the slot that held stage s-1.
        // Safe: every warp passed the barrier above, so all finished computing s-1.
        if (s + 2 < nstage) {
            int slot = (cur + 2) % NBUF;
            load_stage_big(base + slot * BSTAGE, m0, n0, kbase + (s + 2) * KS, tid);
        }

        const uint32_t cb = base + cur * BSTAGE;
        const uint32_t Ah = cb;
        const uint32_t Al = cb + BTILE_A;
        const uint32_t Bh = cb + 2 * BTILE_A;
        const uint32_t Bl = cb + 2 * BTILE_A + BTILE_B;

#pragma unroll
        for (int ks = 0; ks < 2; ks++) {
            uint32_t kb = ks * 32;
            uint32_t bh[4][2], bl[4][2];
#pragma unroll
            for (int nt = 0; nt < 4; nt++) {
                uint32_t boff = b_off + nt * 8 * ROWB + kb;
                LDSM2(bh[nt], Bh + boff);
                LDSM2(bl[nt], Bl + boff);
            }
#pragma unroll
            for (int mt = 0; mt < 4; mt++) {
                uint32_t ah[4], al[4];
                uint32_t aoff = a_off + mt * 16 * ROWB + kb;
                LDSM4(ah, Ah + aoff);
                LDSM4(al, Al + aoff);
#pragma unroll
                for (int nt = 0; nt < 4; nt++) {
                    MMA16816(acc[mt][nt], ah, bh[nt]);
                    MMA16816(acc[mt][nt], ah, bl[nt]);
                    MMA16816(acc[mt][nt], al, bh[nt]);
                }
            }
        }
        cur = (cur + 1) % NBUF;
    }

    float* out = g_scratch + (size_t)z * SEQ * EMB;
    const int rbase = m0 + warp_m * 64 + (lane >> 2);
    const int cbase = n0 + warp_n * 32 + ((lane & 3) << 1);
#pragma unroll
    for (int mt = 0; mt < 4; mt++) {
#pragma unroll
        for (int nt = 0; nt < 4; nt++) {
            int r0 = rbase + mt * 16;
            int r1 = r0 + 8;
            int c  = cbase + nt * 8;
            if (r0 < SEQ)
                *(float2*)(out + (size_t)r0 * EMB + c) = make_float2(acc[mt][nt][0], acc[mt][nt][1]);
            if (r1 < SEQ)
                *(float2*)(out + (size_t)r1 * EMB + c) = make_float2(acc[mt][nt][2], acc[mt][nt][3]);
        }
    }
}

// ---------------- unified bf16 3-pass mma GEMM (128x128 tile) ----------------
// EPI 1: (acc+bias)*mask -> bf16 hi/lo outputs (x-embed -> tokens)
// EPI 2: acc+bias -> fp32, rows < Mvalid only (QKV, out-proj)
__device__ __forceinline__ void load_stage_g(
    uint32_t smbuf,
    const __nv_bfloat16* __restrict__ Ahi, const __nv_bfloat16* __restrict__ Alo,
    const __nv_bfloat16* __restrict__ Bhi, const __nv_bfloat16* __restrict__ Blo,
    int m0, int n0, int koff, int Ktot, int tid)
{
#pragma unroll
    for (int it = 0; it < 8; it++) {
        int f = it * 256 + tid;        // 0..2047 chunks of 16B
        int tile = f >> 9;             // 0:Ahi 1:Alo 2:Bhi 3:Blo
        int idx = f & 511;
        int row = idx >> 2;
        int q = idx & 3;
        const __nv_bfloat16* g;
        int r0;
        if (tile == 0)      { g = Ahi; r0 = m0; }
        else if (tile == 1) { g = Alo; r0 = m0; }
        else if (tile == 2) { g = Bhi; r0 = n0; }
        else                { g = Blo; r0 = n0; }
        const __nv_bfloat16* gp = g + (size_t)(r0 + row) * Ktot + koff + q * 8;
        uint32_t sp = smbuf + tile * TILEB + row * ROWB + q * 16;
        CP_ASYNC16(sp, gp);
    }
    CP_COMMIT();
}

template<int EPI>
__global__ void __launch_bounds__(256, 2) mma_gemm(
    const __nv_bfloat16* __restrict__ Ahi, const __nv_bfloat16* __restrict__ Alo,
    const __nv_bfloat16* __restrict__ Bhi, const __nv_bfloat16* __restrict__ Blo,
    int Ktot,
    float* __restrict__ outf,
    __nv_bfloat16* __restrict__ outhi, __nv_bfloat16* __restrict__ outlo,
    const float* __restrict__ bias, const float* __restrict__ maskf,
    int Nld, int Mvalid)
{
    extern __shared__ __align__(128) char dsm[];
    const uint32_t base = smem_u32(dsm);
    const int tid = threadIdx.x;
    const int wid = tid >> 5, lane = tid & 31;
    const int warp_m = wid >> 2;
    const int warp_n = wid & 3;
    const int n0 = blockIdx.x * 128;
    const int m0 = blockIdx.y * 128;
    const int nstage = Ktot / KS;

    float acc[4][4][4];
#pragma unroll
    for (int i = 0; i < 4; i++)
#pragma unroll
        for (int j = 0; j < 4; j++)
#pragma unroll
            for (int c = 0; c < 4; c++) acc[i][j][c] = 0.0f;

    const uint32_t a_off = (uint32_t)((warp_m * 64 + (lane & 15)) * ROWB + ((lane >> 4) << 4));
    const uint32_t b_off = (uint32_t)((warp_n * 32 + (lane & 7)) * ROWB + (((lane >> 3) & 1) << 4));

    load_stage_g(base, Ahi, Alo, Bhi, Blo, m0, n0, 0, Ktot, tid);

#pragma unroll 1
    for (int s = 0; s < nstage; s++) {
        uint32_t cb = base + (s & 1) * STAGEB;
        if (s + 1 < nstage) {
            load_stage_g(base + ((s + 1) & 1) * STAGEB, Ahi, Alo, Bhi, Blo,
                         m0, n0, (s + 1) * KS, Ktot, tid);
            CP_WAIT(1);
        } else {
            CP_WAIT(0);
        }
        __syncthreads();

        const uint32_t Ah = cb;
        const uint32_t Al = cb + TILEB;
        const uint32_t Bh = cb + 2 * TILEB;
        const uint32_t Bl = cb + 3 * TILEB;

#pragma unroll
        for (int ks = 0; ks < 2; ks++) {
            uint32_t kb = ks * 32;
            uint32_t bh[4][2], bl[4][2];
#pragma unroll
            for (int nt = 0; nt < 4; nt++) {
                uint32_t boff = b_off + nt * 8 * ROWB + kb;
                LDSM2(bh[nt], Bh + boff);
                LDSM2(bl[nt], Bl + boff);
            }
#pragma unroll
            for (int mt = 0; mt < 4; mt++) {
                uint32_t ah[4], al[4];
                uint32_t aoff = a_off + mt * 16 * ROWB + kb;
                LDSM4(ah, Ah + aoff);
                LDSM4(al, Al + aoff);
#pragma unroll
                for (int nt = 0; nt < 4; nt++) {
                    MMA16816(acc[mt][nt], ah, bh[nt]);
                    MMA16816(acc[mt][nt], ah, bl[nt]);
                    MMA16816(acc[mt][nt], al, bh[nt]);
                }
            }
        }
        __syncthreads();
    }

    const int rbase = m0 + warp_m * 64 + (lane >> 2);
    const int cbase = n0 + warp_n * 32 + ((lane & 3) << 1);
#pragma unroll
    for (int mt = 0; mt < 4; mt++) {
#pragma unroll
        for (int nt = 0; nt < 4; nt++) {
            int r0 = rbase + mt * 16;
            int r1 = r0 + 8;
            int c  = cbase + nt * 8;
            if (EPI == 1) {
                float b0 = bias[c], b1 = bias[c + 1];
                float mk0 = maskf[r0 % SEQ];
                float mk1 = maskf[r1 % SEQ];
                float v0 = (acc[mt][nt][0] + b0) * mk0;
                float v1 = (acc[mt][nt][1] + b1) * mk0;
                float v2 = (acc[mt][nt][2] + b0) * mk1;
                float v3 = (acc[mt][nt][3] + b1) * mk1;
                __nv_bfloat16 h0 = __float2bfloat16(v0), h1 = __float2bfloat16(v1);
                __nv_bfloat16 h2 = __float2bfloat16(v2), h3 = __float2bfloat16(v3);
                __nv_bfloat162 hh0; hh0.x = h0; hh0.y = h1;
                __nv_bfloat162 hh1; hh1.x = h2; hh1.y = h3;
                __nv_bfloat162 ll0;
                ll0.x = __float2bfloat16(v0 - __bfloat162float(h0));
                ll0.y = __float2bfloat16(v1 - __bfloat162float(h1));
                __nv_bfloat162 ll1;
                ll1.x = __float2bfloat16(v2 - __bfloat162float(h2));
                ll1.y = __float2bfloat16(v3 - __bfloat162float(h3));
                *(__nv_bfloat162*)(outhi + (size_t)r0 * Nld + c) = hh0;
                *(__nv_bfloat162*)(outlo + (size_t)r0 * Nld + c) = ll0;
                *(__nv_bfloat162*)(outhi + (size_t)r1 * Nld + c) = hh1;
                *(__nv_bfloat162*)(outlo + (size_t)r1 * Nld + c) = ll1;
            } else {
                float b0 = bias[c], b1 = bias[c + 1];
                if (r0 < Mvalid)
                    *(float2*)(outf + (size_t)r0 * Nld + c) =
                        make_float2(acc[mt][nt][0] + b0, acc[mt][nt][1] + b1);
                if (r1 < Mvalid)
                    *(float2*)(outf + (size_t)r1 * Nld + c) =
                        make_float2(acc[mt][nt][2] + b0, acc[mt][nt][3] + b1);
            }
        }
    }
}

// ---------------- reduce split-K pe partials + bias + mask ----------------
__global__ void reduce_pe_kernel(const float* __restrict__ bias,
                                 const float* __restrict__ maskf) {
    int idx = blockIdx.x * blockDim.x + threadIdx.x;
    if (idx >= SEQ * EMB) return;
    int n = idx % EMB;
    int m = idx / EMB;
    float acc = bias[n];
#pragma unroll
    for (int z = 0; z < SPLITK; z++) acc += g_scratch[(size_t)z * SEQ * EMB + idx];
    g_pe_tok[idx] = acc * maskf[m];
}

// ---------------- q/k prep, landmarks, attention core ----------------
__device__ __forceinline__ float block64_sum(float v, float* red2) {
    for (int off = 16; off > 0; off >>= 1)
        v += __shfl_xor_sync(0xffffffffu, v, off);
    if ((threadIdx.x & 31) == 0) red2[threadIdx.x >> 5] = v;
    __syncthreads();
    return red2[0] + red2[1];
}

__global__ void prep_q_kernel(const int* __restrict__ ftag) {
    int s = blockIdx.x, h = blockIdx.y, e = threadIdx.x;
    int ft = ftag[0];
    float val = g_qkv[((size_t)(ft * SEQ + s)) * (3 * EMB) + h * (3 * HD) + e]
              + g_pe_tok[(size_t)s * EMB + h * HD + e];
    __shared__ float red2[2];
    float tot = block64_sum(val * val, red2);
    float denom = fmaxf(sqrtf(tot), 1e-12f);
    g_qn[((size_t)h * SEQ + s) * HD + e] = val / denom;
}

__global__ void prep_k_kernel(const int* __restrict__ ftag) {
    int t = blockIdx.x, h = blockIdx.y, e = threadIdx.x;
    int ft = ftag[0];
    int vi = t / SEQ;
    int view = (vi < ft) ? vi : vi + 1;
    int s = t % SEQ;
    size_t base = ((size_t)(view * SEQ + s)) * (3 * EMB) + h * (3 * HD);
    float kval = g_qkv[base + HD + e];
    float vval = g_qkv[base + 2 * HD + e];
    __shared__ float red2[2];
    float tot = block64_sum(kval * kval, red2);
    float denom = fmaxf(sqrtf(tot), 1e-12f);
    g_kn[((size_t)h * KSEQ + t) * HD + e] = kval / denom;
    g_vc[((size_t)h * KSEQ + t) * HD + e] = vval;
}

__global__ void landmark_kernel(const float* __restrict__ src, float* __restrict__ dst, int seg) {
    int l = blockIdx.x, h = blockIdx.y, e = threadIdx.x;
    int S = LM * seg;
    const float* p = src + ((size_t)h * S + (size_t)l * seg) * HD + e;
    float acc = 0.f;
    for (int r = 0; r < seg; r++) acc += p[(size_t)r * HD];
    dst[((size_t)h * LM + l) * HD + e] = acc / (float)seg;
}

__global__ void a1_kernel() {
    int warp = threadIdx.x >> 5, lane = threadIdx.x & 31;
    int s = blockIdx.x * 4 + warp;
    int h = blockIdx.y;
    const float* qp = g_qn + ((size_t)h * SEQ + s) * HD;
    float q0 = qp[lane], q1 = qp[lane + 32];
    float lg[LM];
#pragma unroll
    for (int l = 0; l < LM; l++) {
        const float* kp = g_kL + ((size_t)h * LM + l) * HD;
        float p = q0 * kp[lane] + q1 * kp[lane + 32];
        for (int off = 16; off > 0; off >>= 1)
            p += __shfl_xor_sync(0xffffffffu, p, off);
        lg[l] = p * SCALE;
    }
    float mx = lg[0];
#pragma unroll
    for (int l = 1; l < LM; l++) mx = fmaxf(mx, lg[l]);
    float sum = 0.f;
#pragma unroll
    for (int l = 0; l < LM; l++) { lg[l] = expf(lg[l] - mx); sum += lg[l]; }
    float inv = 1.0f / sum;
    if (lane < LM)
        g_a1[((size_t)h * SEQ + s) * LM + lane] = lg[lane] * inv;
}

__global__ void a2_kernel() {
    int l = blockIdx.x, h = blockIdx.y, tid = threadIdx.x;
    __shared__ float sq[HD];
    __shared__ float lg[KSEQ];
    __shared__ float red[256];
    if (tid < HD) sq[tid] = g_qL[((size_t)h * LM + l) * HD + tid];
    __syncthreads();

    for (int t = tid; t < KSEQ; t += 256) {
        const float* kp = g_kn + ((size_t)h * KSEQ + t) * HD;
        float d = 0.f;
#pragma unroll
        for (int e = 0; e < HD; e += 4) {
            float4 kv = *(const float4*)(kp + e);
            d += kv.x * sq[e] + kv.y * sq[e + 1] + kv.z * sq[e + 2] + kv.w * sq[e + 3];
        }
        lg[t] = d * SCALE;
    }
    __syncthreads();

    float lmax = -1e30f;
    for (int t = tid; t < KSEQ; t += 256) lmax = fmaxf(lmax, lg[t]);
    red[tid] = lmax;
    __syncthreads();
    for (int off = 128; off > 0; off >>= 1) {
        if (tid < off) red[tid] = fmaxf(red[tid], red[tid + off]);
        __syncthreads();
    }
    float gmax = red[0];
    __syncthreads();

    float lsum = 0.f;
    for (int t = tid; t < KSEQ; t += 256) {
        float e = expf(lg[t] - gmax);
        lg[t] = e;
        lsum += e;
    }
    red[tid] = lsum;
    __syncthreads();
    for (int off = 128; off > 0; off >>= 1) {
        if (tid < off) red[tid] += red[tid + off];
        __syncthreads();
    }
    float inv = 1.0f / red[0];
    float* out = g_a2 + ((size_t)h * LM + l) * KSEQ;
    for (int t = tid; t < KSEQ; t += 256) out[t] = lg[t] * inv;
}

// a2v: 256 threads, 4-way partial over K
__global__ void a2v_kernel() {
    int l = blockIdx.x, h = blockIdx.y;
    int e = threadIdx.x & 63;
    int part = threadIdx.x >> 6;          // 0..3
    const float* ar = g_a2 + ((size_t)h * LM + l) * KSEQ;
    const float* vp = g_vc + (size_t)h * KSEQ * HD + e;
    float acc = 0.f;
    int t0 = part * (KSEQ / 4), t1 = t0 + (KSEQ / 4);
#pragma unroll 4
    for (int t = t0; t < t1; t++) acc += ar[t] * vp[(size_t)t * HD];
    __shared__ float red[4][HD];
    red[part][e] = acc;
    __syncthreads();
    if (part == 0)
        g_a2v[((size_t)h * LM + l) * HD + e] =
            red[0][e] + red[1][e] + red[2][e] + red[3][e];
}

// vals = a1 @ a2v -> bf16 hi/lo (input A of out-proj GEMM)
__global__ void vals_kernel() {
    int s = blockIdx.x;
    int h = threadIdx.x >> 6;
    int e = threadIdx.x & 63;
    const float* ap = g_a1 + ((size_t)h * SEQ + s) * LM;
    const float* bp = g_a2v + (size_t)h * LM * HD + e;
    float acc = 0.f;
#pragma unroll
    for (int l = 0; l < LM; l++) acc += ap[l] * bp[(size_t)l * HD];
    __nv_bfloat16 hv = __float2bfloat16(acc);
    size_t off = (size_t)s * EMB + h * HD + e;
    g_Xohi[off] = hv;
    g_Xolo[off] = __float2bfloat16(acc - __bfloat162float(hv));
}

// ---------------- launch ----------------
extern "C" void kernel_launch(void* const* d_in, const int* in_sizes, int n_in,
                              void* d_out, int out_size) {
    const float* x         = (const float*)d_in[0];
    const float* pe        = (const float*)d_in[1];
    const float* mask_map  = (const float*)d_in[2];
    const float* conv_in_w = (const float*)d_in[3];
    const float* conv_in_b = (const float*)d_in[4];
    const float* conv_pe_w = (const float*)d_in[5];
    const float* conv_pe_b = (const float*)d_in[6];
    const float* qkv_w     = (const float*)d_in[7];
    const float* qkv_b     = (const float*)d_in[8];
    const float* o_w       = (const float*)d_in[9];
    const float* o_b       = (const float*)d_in[10];
    const int*   ftag      = (const int*)d_in[11];

    float* maskf_p;   cudaGetSymbolAddress((void**)&maskf_p,   g_maskf);
    float* qkv_p;     cudaGetSymbolAddress((void**)&qkv_p,     g_qkv);
    float* qn_p;      cudaGetSymbolAddress((void**)&qn_p,      g_qn);
    float* kn_p;      cudaGetSymbolAddress((void**)&kn_p,      g_kn);
    float* qL_p;      cudaGetSymbolAddress((void**)&qL_p,      g_qL);
    float* kL_p;      cudaGetSymbolAddress((void**)&kL_p,      g_kL);
    __nv_bfloat16 *Bhi_p, *Blo_p;
    cudaGetSymbolAddress((void**)&Bhi_p, g_Bhi);
    cudaGetSymbolAddress((void**)&Blo_p, g_Blo);
    __nv_bfloat16 *Axhi_p, *Axlo_p, *Bxhi_p, *Bxlo_p;
    cudaGetSymbolAddress((void**)&Axhi_p, g_Axhi);
    cudaGetSymbolAddress((void**)&Axlo_p, g_Axlo);
    cudaGetSymbolAddress((void**)&Bxhi_p, g_Bxhi);
    cudaGetSymbolAddress((void**)&Bxlo_p, g_Bxlo);
    __nv_bfloat16 *Tokhi_p, *Toklo_p, *Bqhi_p, *Bqlo_p;
    cudaGetSymbolAddress((void**)&Tokhi_p, g_Tokhi);
    cudaGetSymbolAddress((void**)&Toklo_p, g_Toklo);
    cudaGetSymbolAddress((void**)&Bqhi_p, g_Bqhi);
    cudaGetSymbolAddress((void**)&Bqlo_p, g_Bqlo);
    __nv_bfloat16 *Xohi_p, *Xolo_p, *Bohi_p, *Bolo_p;
    cudaGetSymbolAddress((void**)&Xohi_p, g_Xohi);
    cudaGetSymbolAddress((void**)&Xolo_p, g_Xolo);
    cudaGetSymbolAddress((void**)&Bohi_p, g_Bohi);
    cudaGetSymbolAddress((void**)&Bolo_p, g_Bolo);

    static int inited = 0;
    if (!inited) {
        cudaFuncSetAttribute(pe_gemm_big, cudaFuncAttributeMaxDynamicSharedMemorySize, NBUF * BSTAGE);
        cudaFuncSetAttribute(mma_gemm<1>, cudaFuncAttributeMaxDynamicSharedMemorySize, 2 * STAGEB);
        cudaFuncSetAttribute(mma_gemm<2>, cudaFuncAttributeMaxDynamicSharedMemorySize, 2 * STAGEB);
        inited = 1;
    }

    // 1. patch mask
    mask_kernel<<<SEQ, 256>>>(mask_map, maskf_p);

    // 2. operand conversions
    conv_a_kernel<<<(MPAD * (K_PE / 4)) / 256, 256>>>(pe, ftag);
    conv_w_kernel<<<(int)(((size_t)EMB * K_PE / 4) / 256), 256>>>(conv_pe_w, Bhi_p, Blo_p);
    conv_ax_kernel<<<(MQ * (K_X / 4)) / 256, 256>>>(x);
    conv_w_kernel<<<(EMB * K_X / 4) / 256, 256>>>(conv_in_w, Bxhi_p, Bxlo_p);
    conv_w_kernel<<<(3 * EMB * EMB / 4) / 256, 256>>>(qkv_w, Bqhi_p, Bqlo_p);
    conv_w_kernel<<<(EMB * EMB / 4) / 256, 256>>>(o_w, Bohi_p, Bolo_p);

    // 3. pe GEMM (big tile, 3-stage ring, split-K=32 into g_scratch)
    pe_gemm_big<<<dim3(EMB / 256, MPAD / 128, SPLITK), 512, NBUF * BSTAGE>>>();

    // 4. reduce split-K + bias + mask -> pe_tok
    reduce_pe_kernel<<<(SEQ * EMB + 255) / 256, 256>>>(conv_pe_b, maskf_p);

    // 5. x patch embed -> tokens as bf16 hi/lo (bias + mask in epilogue)
    mma_gemm<1><<<dim3(EMB / 128, MQ / 128, 1), 256, 2 * STAGEB>>>(
        Axhi_p, Axlo_p, Bxhi_p, Bxlo_p, K_X,
        nullptr, Tokhi_p, Toklo_p, conv_in_b, maskf_p, EMB, MQ);

    // 6. QKV: tokens @ qkv_w^T + b -> fp32 g_qkv
    mma_gemm<2><<<dim3((3 * EMB) / 128, MQ / 128, 1), 256, 2 * STAGEB>>>(
        Tokhi_p, Toklo_p, Bqhi_p, Bqlo_p, EMB,
        qkv_p, nullptr, nullptr, qkv_b, nullptr, 3 * EMB, MQ);

    // 7. normalized q (+pe) and k, raw v gather
    prep_q_kernel<<<dim3(SEQ, NHEADS), HD>>>(ftag);
    prep_k_kernel<<<dim3(KSEQ, NHEADS), HD>>>(ftag);

    // 8. landmarks
    landmark_kernel<<<dim3(LM, NHEADS), HD>>>(qn_p, qL_p, SEQ / LM);
    landmark_kernel<<<dim3(LM, NHEADS), HD>>>(kn_p, kL_p, KSEQ / LM);

    // 9. attention core
    a1_kernel<<<dim3(SEQ / 4, NHEADS), 128>>>();
    a2_kernel<<<dim3(LM, NHEADS), 256>>>();
    a2v_kernel<<<dim3(LM, NHEADS), 256>>>();
    vals_kernel<<<SEQ, EMB>>>();

    // 10. output projection via mma (rows >= SEQ in pad are zero, writes guarded)
    mma_gemm<2><<<dim3(EMB / 128, MPAD / 128, 1), 256, 2 * STAGEB>>>(
        Xohi_p, Xolo_p, Bohi_p, Bolo_p, EMB,
        (float*)d_out, nullptr, nullptr, o_b, nullptr, EMB, SEQ);
}

// round 17
// speedup vs baseline: 1.4612x; 1.0222x over previous
#include <cuda_runtime.h>
#include <cuda_bf16.h>
#include <math.h>
#include <cstdint>

// ---------------- problem constants ----------------
#define NHEADS 8
#define HD 64
#define EMB 512
#define PS 16
#define GH 16
#define GW 44
#define SEQ 704            // GH*GW
#define NVIEW 6
#define MQ (NVIEW*SEQ)     // 4224
#define LM 16              // landmarks
#define KSEQ (5*SEQ)       // 3520
#define SCALE 0.125f       // 1/sqrt(64)

#define PE_C 256
#define IMG_H 256
#define IMG_W 704
#define K_PE (PE_C*PS*PS)  // 65536
#define K_X  (3*PS*PS)     // 768

#define MPAD 768           // 704 padded to 6x128
#define SPLITK 32
#define KSLICE (K_PE / SPLITK)   // 2048
#define KS 32                    // K per stage

// smem tile geometry: rows stored with 40-element (80B) stride for
// conflict-free ldmatrix; row = 32 bf16 (64B data + 16B pad).
#define ROWB 80
#define TILEB (128 * ROWB)       // 10240  (128-row tile)
#define STAGEB (4 * TILEB)       // 40960  (Ahi, Alo, Bhi, Blo) 128x128 kernel

// big-tile (M128 x N256) stage layout
#define BTILE_A TILEB                 // 10240 per A tile (128 rows)
#define BTILE_B (256 * ROWB)          // 20480 per B tile (256 rows)
#define BSTAGE (2 * BTILE_A + 2 * BTILE_B)   // 61440
#define NBUF 3                        // 3-stage ring, 184320 B smem

// ---------------- scratch (device globals, no cudaMalloc) ----------------
__device__ float g_maskf[SEQ];
__device__ float g_qkv[MQ * 3 * EMB];
__device__ float g_scratch[SPLITK * SEQ * EMB];
__device__ float g_pe_tok[SEQ * EMB];
__device__ float g_qn[NHEADS * SEQ * HD];
__device__ float g_kn[NHEADS * KSEQ * HD];
__device__ float g_vc[NHEADS * KSEQ * HD];
__device__ float g_qL[NHEADS * LM * HD];
__device__ float g_kL[NHEADS * LM * HD];
__device__ float g_a1[NHEADS * SEQ * LM];
__device__ float g_a2[NHEADS * LM * KSEQ];
__device__ float g_a2v[NHEADS * LM * HD];

// bf16 hi/lo split operands
__device__ __nv_bfloat16 g_Ahi[(size_t)MPAD * K_PE];       // pe im2col
__device__ __nv_bfloat16 g_Alo[(size_t)MPAD * K_PE];
__device__ __nv_bfloat16 g_Bhi[(size_t)EMB * K_PE];        // conv_pe_w
__device__ __nv_bfloat16 g_Blo[(size_t)EMB * K_PE];
__device__ __nv_bfloat16 g_Axhi[(size_t)MQ * K_X];         // x im2col
__device__ __nv_bfloat16 g_Axlo[(size_t)MQ * K_X];
__device__ __nv_bfloat16 g_Bxhi[(size_t)EMB * K_X];        // conv_in_w
__device__ __nv_bfloat16 g_Bxlo[(size_t)EMB * K_X];
__device__ __nv_bfloat16 g_Tokhi[(size_t)MQ * EMB];        // tokens (x-embed out)
__device__ __nv_bfloat16 g_Toklo[(size_t)MQ * EMB];
__device__ __nv_bfloat16 g_Bqhi[(size_t)(3 * EMB) * EMB];  // qkv_w
__device__ __nv_bfloat16 g_Bqlo[(size_t)(3 * EMB) * EMB];
__device__ __nv_bfloat16 g_Xohi[(size_t)MPAD * EMB];       // attention out (pad rows stay 0)
__device__ __nv_bfloat16 g_Xolo[(size_t)MPAD * EMB];
__device__ __nv_bfloat16 g_Bohi[(size_t)EMB * EMB];        // o_w
__device__ __nv_bfloat16 g_Bolo[(size_t)EMB * EMB];

// ======================= PTX helpers (compute_103-safe) =======================
__device__ __forceinline__ uint32_t smem_u32(const void* p) {
    uint32_t a;
    asm("{ .reg .u64 t; cvta.to.shared.u64 t, %1; cvt.u32.u64 %0, t; }"
        : "=r"(a) : "l"(p));
    return a;
}

#define CP_ASYNC16(sp, gp) \
    asm volatile("cp.async.cg.shared.global [%0], [%1], 16;\n" :: "r"(sp), "l"(gp) : "memory")
#define CP_COMMIT() asm volatile("cp.async.commit_group;\n" ::: "memory")
#define CP_WAIT(n)  asm volatile("cp.async.wait_group %0;\n" :: "n"(n) : "memory")

#define LDSM4(r, addr) \
    asm volatile("ldmatrix.sync.aligned.m8n8.x4.shared.b16 {%0,%1,%2,%3}, [%4];" \
        : "=r"((r)[0]), "=r"((r)[1]), "=r"((r)[2]), "=r"((r)[3]) : "r"(addr))
#define LDSM2(r, addr) \
    asm volatile("ldmatrix.sync.aligned.m8n8.x2.shared.b16 {%0,%1}, [%2];" \
        : "=r"((r)[0]), "=r"((r)[1]) : "r"(addr))

#define MMA16816(d, a, b) \
    asm volatile("mma.sync.aligned.m16n8k16.row.col.f32.bf16.bf16.f32 " \
        "{%0,%1,%2,%3}, {%4,%5,%6,%7}, {%8,%9}, {%0,%1,%2,%3};" \
        : "+f"((d)[0]), "+f"((d)[1]), "+f"((d)[2]), "+f"((d)[3]) \
        : "r"((a)[0]), "r"((a)[1]), "r"((a)[2]), "r"((a)[3]), "r"((b)[0]), "r"((b)[1]))

// ---------------- patch mask: 16x16 avg pool > 0 ----------------
__global__ void mask_kernel(const float* __restrict__ mask_map, float* __restrict__ maskf) {
    int p = blockIdx.x;
    int gh = p / GW, gw = p % GW;
    int i = threadIdx.x >> 4, j = threadIdx.x & 15;
    float v = mask_map[(gh * PS + i) * IMG_W + gw * PS + j];
    __shared__ float red[256];
    red[threadIdx.x] = v;
    __syncthreads();
    for (int off = 128; off > 0; off >>= 1) {
        if (threadIdx.x < off) red[threadIdx.x] += red[threadIdx.x + off];
        __syncthreads();
    }
    if (threadIdx.x == 0) maskf[p] = (red[0] > 0.0f) ? 1.0f : 0.0f;
}

// ---------------- bf16 hi/lo conversion kernels ----------------
__device__ __forceinline__ void split4(float4 v, uint2& hi, uint2& lo) {
    __nv_bfloat16 h0 = __float2bfloat16(v.x);
    __nv_bfloat16 h1 = __float2bfloat16(v.y);
    __nv_bfloat16 h2 = __float2bfloat16(v.z);
    __nv_bfloat16 h3 = __float2bfloat16(v.w);
    __nv_bfloat16 l0 = __float2bfloat16(v.x - __bfloat162float(h0));
    __nv_bfloat16 l1 = __float2bfloat16(v.y - __bfloat162float(h1));
    __nv_bfloat16 l2 = __float2bfloat16(v.z - __bfloat162float(h2));
    __nv_bfloat16 l3 = __float2bfloat16(v.w - __bfloat162float(h3));
    __nv_bfloat162 ph0; ph0.x = h0; ph0.y = h1;
    __nv_bfloat162 ph1; ph1.x = h2; ph1.y = h3;
    __nv_bfloat162 pl0; pl0.x = l0; pl0.y = l1;
    __nv_bfloat162 pl1; pl1.x = l2; pl1.y = l3;
    hi.x = *reinterpret_cast<uint32_t*>(&ph0);
    hi.y = *reinterpret_cast<uint32_t*>(&ph1);
    lo.x = *reinterpret_cast<uint32_t*>(&pl0);
    lo.y = *reinterpret_cast<uint32_t*>(&pl1);
}

// pe A = im2col(pe[ft]) -> [MPAD][K_PE], rows >= SEQ zero
__global__ void conv_a_kernel(const float* __restrict__ pe, const int* __restrict__ ftag) {
    size_t idx = (size_t)blockIdx.x * 256 + threadIdx.x;
    int m = (int)(idx >> 14);               // K_PE/4 = 16384 chunks per row
    int kq = ((int)idx & 16383) << 2;
    float4 v = make_float4(0.f, 0.f, 0.f, 0.f);
    if (m < SEQ) {
        int c = kq >> 8, rem = kq & 255, i = rem >> 4, j = rem & 15;
        int gh = m / GW, gw = m % GW;
        const float* src = pe + (size_t)ftag[0] * PE_C * IMG_H * IMG_W
                              + ((size_t)c * IMG_H + gh * PS + i) * IMG_W + gw * PS + j;
        v = *(const float4*)src;
    }
    uint2 hi, lo;
    split4(v, hi, lo);
    size_t off = (size_t)m * K_PE + kq;
    *(uint2*)(g_Ahi + off) = hi;
    *(uint2*)(g_Alo + off) = lo;
}

// x A = im2col(x, all 6 views) -> [MQ][K_X]
__global__ void conv_ax_kernel(const float* __restrict__ x) {
    size_t idx = (size_t)blockIdx.x * 256 + threadIdx.x;  // per 4 elems
    int m = (int)(idx / (K_X / 4));
    int kq = ((int)(idx % (K_X / 4))) << 2;
    int c = kq >> 8, rem = kq & 255, i = rem >> 4, j = rem & 15;
    int v6 = m / SEQ, s = m % SEQ;
    int gh = s / GW, gw = s % GW;
    const float* src = x + (((size_t)(v6 * 3 + c)) * IMG_H + gh * PS + i) * IMG_W + gw * PS + j;
    float4 v = *(const float4*)src;
    uint2 hi, lo;
    split4(v, hi, lo);
    size_t off = (size_t)m * K_X + kq;
    *(uint2*)(g_Axhi + off) = hi;
    *(uint2*)(g_Axlo + off) = lo;
}

// generic weight split: row-major [n][k] fp32 -> bf16 hi/lo
__global__ void conv_w_kernel(const float* __restrict__ w,
                              __nv_bfloat16* __restrict__ whi,
                              __nv_bfloat16* __restrict__ wlo) {
    size_t idx = (size_t)blockIdx.x * 256 + threadIdx.x;
    size_t off = idx << 2;
    float4 v = *(const float4*)(w + off);
    uint2 hi, lo;
    split4(v, hi, lo);
    *(uint2*)(whi + off) = hi;
    *(uint2*)(wlo + off) = lo;
}

// =====================================================================
// pe GEMM (big tile): 512 threads, CTA tile M128 x N256, K-stage 32,
// 3-stage cp.async ring, 3 SEPARATED hi/lo passes (no back-to-back
// same-accumulator MMAs), split-K into g_scratch.
// warps: warp_m (2) x warp_n (8); warp tile 64x32 (4x4 m16n8k16).
// =====================================================================
__device__ __forceinline__ void load_stage_big(uint32_t smbuf, int m0, int n0,
                                               int koff, int tid) {
#pragma unroll
    for (int it = 0; it < 6; it++) {
        int f = it * 512 + tid;                 // 0..3071 data chunks of 16B
        const __nv_bfloat16* g;
        int r0, local;
        uint32_t rbase;
        if (f < 512)       { g = g_Ahi; r0 = m0; local = f;        rbase = 0; }
        else if (f < 1024) { g = g_Alo; r0 = m0; local = f - 512;  rbase = BTILE_A; }
        else if (f < 2048) { g = g_Bhi; r0 = n0; local = f - 1024; rbase = 2 * BTILE_A; }
        else               { g = g_Blo; r0 = n0; local = f - 2048; rbase = 2 * BTILE_A + BTILE_B; }
        int row = local >> 2;                   // 4 chunks (64B) per row
        int q = local & 3;
        const __nv_bfloat16* gp = g + (size_t)(r0 + row) * K_PE + koff + q * 8;
        uint32_t sp = smbuf + rbase + row * ROWB + q * 16;
        CP_ASYNC16(sp, gp);
    }
    CP_COMMIT();
}

__global__ void __launch_bounds__(512, 1) pe_gemm_big() {
    extern __shared__ __align__(128) char dsm[];
    const uint32_t base = smem_u32(dsm);
    const int tid = threadIdx.x;
    const int wid = tid >> 5, lane = tid & 31;
    const int warp_m = wid >> 3;            // 0..1
    const int warp_n = wid & 7;             // 0..7
    const int n0 = blockIdx.x * 256;
    const int m0 = blockIdx.y * 128;
    const int z  = blockIdx.z;
    const int kbase = z * KSLICE;
    const int nstage = KSLICE / KS;         // 64

    float acc[4][4][4];
#pragma unroll
    for (int i = 0; i < 4; i++)
#pragma unroll
        for (int j = 0; j < 4; j++)
#pragma unroll
            for (int c = 0; c < 4; c++) acc[i][j][c] = 0.0f;

    const uint32_t a_off = (uint32_t)((warp_m * 64 + (lane & 15)) * ROWB + ((lane >> 4) << 4));
    const uint32_t b_off = (uint32_t)((warp_n * 32 + (lane & 7)) * ROWB + (((lane >> 3) & 1) << 4));

    // prime ring with stages 0 and 1
    load_stage_big(base + 0 * BSTAGE, m0, n0, kbase + 0 * KS, tid);
    load_stage_big(base + 1 * BSTAGE, m0, n0, kbase + 1 * KS, tid);

    int cur = 0;   // ring slot of stage s
#pragma unroll 1
    for (int s = 0; s < nstage; s++) {
        if (s == nstage - 1) { CP_WAIT(0); } else { CP_WAIT(1); }
        __syncthreads();
        if (s + 2 < nstage) {
            int slot = (cur + 2) % NBUF;
            load_stage_big(base + slot * BSTAGE, m0, n0, kbase + (s + 2) * KS, tid);
        }

        const uint32_t cb = base + cur * BSTAGE;
        const uint32_t Ah = cb;
        const uint32_t Al = cb + BTILE_A;
        const uint32_t Bh = cb + 2 * BTILE_A;
        const uint32_t Bl = cb + 2 * BTILE_A + BTILE_B;

#pragma unroll
        for (int ks = 0; ks < 2; ks++) {
            uint32_t kb = ks * 32;
            uint32_t bh[4][2], bl[4][2];
#pragma unroll
            for (int nt = 0; nt < 4; nt++) {
                uint32_t boff = b_off + nt * 8 * ROWB + kb;
                LDSM2(bh[nt], Bh + boff);
                LDSM2(bl[nt], Bl + boff);
            }
            uint32_t ah[4][4];
#pragma unroll
            for (int mt = 0; mt < 4; mt++)
                LDSM4(ah[mt], Ah + a_off + mt * 16 * ROWB + kb);
            // pass 1: ah * bh — 16 independent accumulators
#pragma unroll
            for (int mt = 0; mt < 4; mt++)
#pragma unroll
                for (int nt = 0; nt < 4; nt++)
                    MMA16816(acc[mt][nt], ah[mt], bh[nt]);
            // pass 2: ah * bl
#pragma unroll
            for (int mt = 0; mt < 4; mt++)
#pragma unroll
                for (int nt = 0; nt < 4; nt++)
                    MMA16816(acc[mt][nt], ah[mt], bl[nt]);
            // load al (ah dead), pass 3: al * bh
            uint32_t al[4][4];
#pragma unroll
            for (int mt = 0; mt < 4; mt++)
                LDSM4(al[mt], Al + a_off + mt * 16 * ROWB + kb);
#pragma unroll
            for (int mt = 0; mt < 4; mt++)
#pragma unroll
                for (int nt = 0; nt < 4; nt++)
                    MMA16816(acc[mt][nt], al[mt], bh[nt]);
        }
        cur = (cur + 1) % NBUF;
    }

    float* out = g_scratch + (size_t)z * SEQ * EMB;
    const int rbase = m0 + warp_m * 64 + (lane >> 2);
    const int cbase = n0 + warp_n * 32 + ((lane & 3) << 1);
#pragma unroll
    for (int mt = 0; mt < 4; mt++) {
#pragma unroll
        for (int nt = 0; nt < 4; nt++) {
            int r0 = rbase + mt * 16;
            int r1 = r0 + 8;
            int c  = cbase + nt * 8;
            if (r0 < SEQ)
                *(float2*)(out + (size_t)r0 * EMB + c) = make_float2(acc[mt][nt][0], acc[mt][nt][1]);
            if (r1 < SEQ)
                *(float2*)(out + (size_t)r1 * EMB + c) = make_float2(acc[mt][nt][2], acc[mt][nt][3]);
        }
    }
}

// ---------------- unified bf16 3-pass mma GEMM (128x128 tile) ----------------
// EPI 1: (acc+bias)*mask -> bf16 hi/lo outputs (x-embed -> tokens)
// EPI 2: acc+bias -> fp32, rows < Mvalid only (QKV, out-proj)
__device__ __forceinline__ void load_stage_g(
    uint32_t smbuf,
    const __nv_bfloat16* __restrict__ Ahi, const __nv_bfloat16* __restrict__ Alo,
    const __nv_bfloat16* __restrict__ Bhi, const __nv_bfloat16* __restrict__ Blo,
    int m0, int n0, int koff, int Ktot, int tid)
{
#pragma unroll
    for (int it = 0; it < 8; it++) {
        int f = it * 256 + tid;        // 0..2047 chunks of 16B
        int tile = f >> 9;             // 0:Ahi 1:Alo 2:Bhi 3:Blo
        int idx = f & 511;
        int row = idx >> 2;
        int q = idx & 3;
        const __nv_bfloat16* g;
        int r0;
        if (tile == 0)      { g = Ahi; r0 = m0; }
        else if (tile == 1) { g = Alo; r0 = m0; }
        else if (tile == 2) { g = Bhi; r0 = n0; }
        else                { g = Blo; r0 = n0; }
        const __nv_bfloat16* gp = g + (size_t)(r0 + row) * Ktot + koff + q * 8;
        uint32_t sp = smbuf + tile * TILEB + row * ROWB + q * 16;
        CP_ASYNC16(sp, gp);
    }
    CP_COMMIT();
}

template<int EPI>
__global__ void __launch_bounds__(256, 2) mma_gemm(
    const __nv_bfloat16* __restrict__ Ahi, const __nv_bfloat16* __restrict__ Alo,
    const __nv_bfloat16* __restrict__ Bhi, const __nv_bfloat16* __restrict__ Blo,
    int Ktot,
    float* __restrict__ outf,
    __nv_bfloat16* __restrict__ outhi, __nv_bfloat16* __restrict__ outlo,
    const float* __restrict__ bias, const float* __restrict__ maskf,
    int Nld, int Mvalid)
{
    extern __shared__ __align__(128) char dsm[];
    const uint32_t base = smem_u32(dsm);
    const int tid = threadIdx.x;
    const int wid = tid >> 5, lane = tid & 31;
    const int warp_m = wid >> 2;
    const int warp_n = wid & 3;
    const int n0 = blockIdx.x * 128;
    const int m0 = blockIdx.y * 128;
    const int nstage = Ktot / KS;

    float acc[4][4][4];
#pragma unroll
    for (int i = 0; i < 4; i++)
#pragma unroll
        for (int j = 0; j < 4; j++)
#pragma unroll
            for (int c = 0; c < 4; c++) acc[i][j][c] = 0.0f;

    const uint32_t a_off = (uint32_t)((warp_m * 64 + (lane & 15)) * ROWB + ((lane >> 4) << 4));
    const uint32_t b_off = (uint32_t)((warp_n * 32 + (lane & 7)) * ROWB + (((lane >> 3) & 1) << 4));

    load_stage_g(base, Ahi, Alo, Bhi, Blo, m0, n0, 0, Ktot, tid);

#pragma unroll 1
    for (int s = 0; s < nstage; s++) {
        uint32_t cb = base + (s & 1) * STAGEB;
        if (s + 1 < nstage) {
            load_stage_g(base + ((s + 1) & 1) * STAGEB, Ahi, Alo, Bhi, Blo,
                         m0, n0, (s + 1) * KS, Ktot, tid);
            CP_WAIT(1);
        } else {
            CP_WAIT(0);
        }
        __syncthreads();

        const uint32_t Ah = cb;
        const uint32_t Al = cb + TILEB;
        const uint32_t Bh = cb + 2 * TILEB;
        const uint32_t Bl = cb + 3 * TILEB;

#pragma unroll
        for (int ks = 0; ks < 2; ks++) {
            uint32_t kb = ks * 32;
            uint32_t bh[4][2], bl[4][2];
#pragma unroll
            for (int nt = 0; nt < 4; nt++) {
                uint32_t boff = b_off + nt * 8 * ROWB + kb;
                LDSM2(bh[nt], Bh + boff);
                LDSM2(bl[nt], Bl + boff);
            }
            uint32_t ah[4][4];
#pragma unroll
            for (int mt = 0; mt < 4; mt++)
                LDSM4(ah[mt], Ah + a_off + mt * 16 * ROWB + kb);
#pragma unroll
            for (int mt = 0; mt < 4; mt++)
#pragma unroll
                for (int nt = 0; nt < 4; nt++)
                    MMA16816(acc[mt][nt], ah[mt], bh[nt]);
#pragma unroll
            for (int mt = 0; mt < 4; mt++)
#pragma unroll
                for (int nt = 0; nt < 4; nt++)
                    MMA16816(acc[mt][nt], ah[mt], bl[nt]);
            uint32_t al[4][4];
#pragma unroll
            for (int mt = 0; mt < 4; mt++)
                LDSM4(al[mt], Al + a_off + mt * 16 * ROWB + kb);
#pragma unroll
            for (int mt = 0; mt < 4; mt++)
#pragma unroll
                for (int nt = 0; nt < 4; nt++)
                    MMA16816(acc[mt][nt], al[mt], bh[nt]);
        }
        __syncthreads();
    }

    const int rbase = m0 + warp_m * 64 + (lane >> 2);
    const int cbase = n0 + warp_n * 32 + ((lane & 3) << 1);
#pragma unroll
    for (int mt = 0; mt < 4; mt++) {
#pragma unroll
        for (int nt = 0; nt < 4; nt++) {
            int r0 = rbase + mt * 16;
            int r1 = r0 + 8;
            int c  = cbase + nt * 8;
            if (EPI == 1) {
                float b0 = bias[c], b1 = bias[c + 1];
                float mk0 = maskf[r0 % SEQ];
                float mk1 = maskf[r1 % SEQ];
                float v0 = (acc[mt][nt][0] + b0) * mk0;
                float v1 = (acc[mt][nt][1] + b1) * mk0;
                float v2 = (acc[mt][nt][2] + b0) * mk1;
                float v3 = (acc[mt][nt][3] + b1) * mk1;
                __nv_bfloat16 h0 = __float2bfloat16(v0), h1 = __float2bfloat16(v1);
                __nv_bfloat16 h2 = __float2bfloat16(v2), h3 = __float2bfloat16(v3);
                __nv_bfloat162 hh0; hh0.x = h0; hh0.y = h1;
                __nv_bfloat162 hh1; hh1.x = h2; hh1.y = h3;
                __nv_bfloat162 ll0;
                ll0.x = __float2bfloat16(v0 - __bfloat162float(h0));
                ll0.y = __float2bfloat16(v1 - __bfloat162float(h1));
                __nv_bfloat162 ll1;
                ll1.x = __float2bfloat16(v2 - __bfloat162float(h2));
                ll1.y = __float2bfloat16(v3 - __bfloat162float(h3));
                *(__nv_bfloat162*)(outhi + (size_t)r0 * Nld + c) = hh0;
                *(__nv_bfloat162*)(outlo + (size_t)r0 * Nld + c) = ll0;
                *(__nv_bfloat162*)(outhi + (size_t)r1 * Nld + c) = hh1;
                *(__nv_bfloat162*)(outlo + (size_t)r1 * Nld + c) = ll1;
            } else {
                float b0 = bias[c], b1 = bias[c + 1];
                if (r0 < Mvalid)
                    *(float2*)(outf + (size_t)r0 * Nld + c) =
                        make_float2(acc[mt][nt][0] + b0, acc[mt][nt][1] + b1);
                if (r1 < Mvalid)
                    *(float2*)(outf + (size_t)r1 * Nld + c) =
                        make_float2(acc[mt][nt][2] + b0, acc[mt][nt][3] + b1);
            }
        }
    }
}

// ---------------- reduce split-K pe partials + bias + mask ----------------
__global__ void reduce_pe_kernel(const float* __restrict__ bias,
                                 const float* __restrict__ maskf) {
    int idx = blockIdx.x * blockDim.x + threadIdx.x;
    if (idx >= SEQ * EMB) return;
    int n = idx % EMB;
    int m = idx / EMB;
    float acc = bias[n];
#pragma unroll
    for (int z = 0; z < SPLITK; z++) acc += g_scratch[(size_t)z * SEQ * EMB + idx];
    g_pe_tok[idx] = acc * maskf[m];
}

// ---------------- q/k prep, landmarks, attention core ----------------
__device__ __forceinline__ float block64_sum(float v, float* red2) {
    for (int off = 16; off > 0; off >>= 1)
        v += __shfl_xor_sync(0xffffffffu, v, off);
    if ((threadIdx.x & 31) == 0) red2[threadIdx.x >> 5] = v;
    __syncthreads();
    return red2[0] + red2[1];
}

__global__ void prep_q_kernel(const int* __restrict__ ftag) {
    int s = blockIdx.x, h = blockIdx.y, e = threadIdx.x;
    int ft = ftag[0];
    float val = g_qkv[((size_t)(ft * SEQ + s)) * (3 * EMB) + h * (3 * HD) + e]
              + g_pe_tok[(size_t)s * EMB + h * HD + e];
    __shared__ float red2[2];
    float tot = block64_sum(val * val, red2);
    float denom = fmaxf(sqrtf(tot), 1e-12f);
    g_qn[((size_t)h * SEQ + s) * HD + e] = val / denom;
}

__global__ void prep_k_kernel(const int* __restrict__ ftag) {
    int t = blockIdx.x, h = blockIdx.y, e = threadIdx.x;
    int ft = ftag[0];
    int vi = t / SEQ;
    int view = (vi < ft) ? vi : vi + 1;
    int s = t % SEQ;
    size_t base = ((size_t)(view * SEQ + s)) * (3 * EMB) + h * (3 * HD);
    float kval = g_qkv[base + HD + e];
    float vval = g_qkv[base + 2 * HD + e];
    __shared__ float red2[2];
    float tot = block64_sum(kval * kval, red2);
    float denom = fmaxf(sqrtf(tot), 1e-12f);
    g_kn[((size_t)h * KSEQ + t) * HD + e] = kval / denom;
    g_vc[((size_t)h * KSEQ + t) * HD + e] = vval;
}

__global__ void landmark_kernel(const float* __restrict__ src, float* __restrict__ dst, int seg) {
    int l = blockIdx.x, h = blockIdx.y, e = threadIdx.x;
    int S = LM * seg;
    const float* p = src + ((size_t)h * S + (size_t)l * seg) * HD + e;
    float acc = 0.f;
    for (int r = 0; r < seg; r++) acc += p[(size_t)r * HD];
    dst[((size_t)h * LM + l) * HD + e] = acc / (float)seg;
}

__global__ void a1_kernel() {
    int warp = threadIdx.x >> 5, lane = threadIdx.x & 31;
    int s = blockIdx.x * 4 + warp;
    int h = blockIdx.y;
    const float* qp = g_qn + ((size_t)h * SEQ + s) * HD;
    float q0 = qp[lane], q1 = qp[lane + 32];
    float lg[LM];
#pragma unroll
    for (int l = 0; l < LM; l++) {
        const float* kp = g_kL + ((size_t)h * LM + l) * HD;
        float p = q0 * kp[lane] + q1 * kp[lane + 32];
        for (int off = 16; off > 0; off >>= 1)
            p += __shfl_xor_sync(0xffffffffu, p, off);
        lg[l] = p * SCALE;
    }
    float mx = lg[0];
#pragma unroll
    for (int l = 1; l < LM; l++) mx = fmaxf(mx, lg[l]);
    float sum = 0.f;
#pragma unroll
    for (int l = 0; l < LM; l++) { lg[l] = expf(lg[l] - mx); sum += lg[l]; }
    float inv = 1.0f / sum;
    if (lane < LM)
        g_a1[((size_t)h * SEQ + s) * LM + lane] = lg[lane] * inv;
}

__global__ void a2_kernel() {
    int l = blockIdx.x, h = blockIdx.y, tid = threadIdx.x;
    __shared__ float sq[HD];
    __shared__ float lg[KSEQ];
    __shared__ float red[256];
    if (tid < HD) sq[tid] = g_qL[((size_t)h * LM + l) * HD + tid];
    __syncthreads();

    for (int t = tid; t < KSEQ; t += 256) {
        const float* kp = g_kn + ((size_t)h * KSEQ + t) * HD;
        float d = 0.f;
#pragma unroll
        for (int e = 0; e < HD; e += 4) {
            float4 kv = *(const float4*)(kp + e);
            d += kv.x * sq[e] + kv.y * sq[e + 1] + kv.z * sq[e + 2] + kv.w * sq[e + 3];
        }
        lg[t] = d * SCALE;
    }
    __syncthreads();

    float lmax = -1e30f;
    for (int t = tid; t < KSEQ; t += 256) lmax = fmaxf(lmax, lg[t]);
    red[tid] = lmax;
    __syncthreads();
    for (int off = 128; off > 0; off >>= 1) {
        if (tid < off) red[tid] = fmaxf(red[tid], red[tid + off]);
        __syncthreads();
    }
    float gmax = red[0];
    __syncthreads();

    float lsum = 0.f;
    for (int t = tid; t < KSEQ; t += 256) {
        float e = expf(lg[t] - gmax);
        lg[t] = e;
        lsum += e;
    }
    red[tid] = lsum;
    __syncthreads();
    for (int off = 128; off > 0; off >>= 1) {
        if (tid < off) red[tid] += red[tid + off];
        __syncthreads();
    }
    float inv = 1.0f / red[0];
    float* out = g_a2 + ((size_t)h * LM + l) * KSEQ;
    for (int t = tid; t < KSEQ; t += 256) out[t] = lg[t] * inv;
}

// a2v: 256 threads, 4-way partial over K
__global__ void a2v_kernel() {
    int l = blockIdx.x, h = blockIdx.y;
    int e = threadIdx.x & 63;
    int part = threadIdx.x >> 6;          // 0..3
    const float* ar = g_a2 + ((size_t)h * LM + l) * KSEQ;
    const float* vp = g_vc + (size_t)h * KSEQ * HD + e;
    float acc = 0.f;
    int t0 = part * (KSEQ / 4), t1 = t0 + (KSEQ / 4);
#pragma unroll 4
    for (int t = t0; t < t1; t++) acc += ar[t] * vp[(size_t)t * HD];
    __shared__ float red[4][HD];
    red[part][e] = acc;
    __syncthreads();
    if (part == 0)
        g_a2v[((size_t)h * LM + l) * HD + e] =
            red[0][e] + red[1][e] + red[2][e] + red[3][e];
}

// vals = a1 @ a2v -> bf16 hi/lo (input A of out-proj GEMM)
__global__ void vals_kernel() {
    int s = blockIdx.x;
    int h = threadIdx.x >> 6;
    int e = threadIdx.x & 63;
    const float* ap = g_a1 + ((size_t)h * SEQ + s) * LM;
    const float* bp = g_a2v + (size_t)h * LM * HD + e;
    float acc = 0.f;
#pragma unroll
    for (int l = 0; l < LM; l++) acc += ap[l] * bp[(size_t)l * HD];
    __nv_bfloat16 hv = __float2bfloat16(acc);
    size_t off = (size_t)s * EMB + h * HD + e;
    g_Xohi[off] = hv;
    g_Xolo[off] = __float2bfloat16(acc - __bfloat162float(hv));
}

// ---------------- launch ----------------
extern "C" void kernel_launch(void* const* d_in, const int* in_sizes, int n_in,
                              void* d_out, int out_size) {
    const float* x         = (const float*)d_in[0];
    const float* pe        = (const float*)d_in[1];
    const float* mask_map  = (const float*)d_in[2];
    const float* conv_in_w = (const float*)d_in[3];
    const float* conv_in_b = (const float*)d_in[4];
    const float* conv_pe_w = (const float*)d_in[5];
    const float* conv_pe_b = (const float*)d_in[6];
    const float* qkv_w     = (const float*)d_in[7];
    const float* qkv_b     = (const float*)d_in[8];
    const float* o_w       = (const float*)d_in[9];
    const float* o_b       = (const float*)d_in[10];
    const int*   ftag      = (const int*)d_in[11];

    float* maskf_p;   cudaGetSymbolAddress((void**)&maskf_p,   g_maskf);
    float* qkv_p;     cudaGetSymbolAddress((void**)&qkv_p,     g_qkv);
    float* qn_p;      cudaGetSymbolAddress((void**)&qn_p,      g_qn);
    float* kn_p;      cudaGetSymbolAddress((void**)&kn_p,      g_kn);
    float* qL_p;      cudaGetSymbolAddress((void**)&qL_p,      g_qL);
    float* kL_p;      cudaGetSymbolAddress((void**)&kL_p,      g_kL);
    __nv_bfloat16 *Bhi_p, *Blo_p;
    cudaGetSymbolAddress((void**)&Bhi_p, g_Bhi);
    cudaGetSymbolAddress((void**)&Blo_p, g_Blo);
    __nv_bfloat16 *Axhi_p, *Axlo_p, *Bxhi_p, *Bxlo_p;
    cudaGetSymbolAddress((void**)&Axhi_p, g_Axhi);
    cudaGetSymbolAddress((void**)&Axlo_p, g_Axlo);
    cudaGetSymbolAddress((void**)&Bxhi_p, g_Bxhi);
    cudaGetSymbolAddress((void**)&Bxlo_p, g_Bxlo);
    __nv_bfloat16 *Tokhi_p, *Toklo_p, *Bqhi_p, *Bqlo_p;
    cudaGetSymbolAddress((void**)&Tokhi_p, g_Tokhi);
    cudaGetSymbolAddress((void**)&Toklo_p, g_Toklo);
    cudaGetSymbolAddress((void**)&Bqhi_p, g_Bqhi);
    cudaGetSymbolAddress((void**)&Bqlo_p, g_Bqlo);
    __nv_bfloat16 *Xohi_p, *Xolo_p, *Bohi_p, *Bolo_p;
    cudaGetSymbolAddress((void**)&Xohi_p, g_Xohi);
    cudaGetSymbolAddress((void**)&Xolo_p, g_Xolo);
    cudaGetSymbolAddress((void**)&Bohi_p, g_Bohi);
    cudaGetSymbolAddress((void**)&Bolo_p, g_Bolo);

    static int inited = 0;
    if (!inited) {
        cudaFuncSetAttribute(pe_gemm_big, cudaFuncAttributeMaxDynamicSharedMemorySize, NBUF * BSTAGE);
        cudaFuncSetAttribute(mma_gemm<1>, cudaFuncAttributeMaxDynamicSharedMemorySize, 2 * STAGEB);
        cudaFuncSetAttribute(mma_gemm<2>, cudaFuncAttributeMaxDynamicSharedMemorySize, 2 * STAGEB);
        inited = 1;
    }

    // 1. patch mask
    mask_kernel<<<SEQ, 256>>>(mask_map, maskf_p);

    // 2. operand conversions
    conv_a_kernel<<<(MPAD * (K_PE / 4)) / 256, 256>>>(pe, ftag);
    conv_w_kernel<<<(int)(((size_t)EMB * K_PE / 4) / 256), 256>>>(conv_pe_w, Bhi_p, Blo_p);
    conv_ax_kernel<<<(MQ * (K_X / 4)) / 256, 256>>>(x);
    conv_w_kernel<<<(EMB * K_X / 4) / 256, 256>>>(conv_in_w, Bxhi_p, Bxlo_p);
    conv_w_kernel<<<(3 * EMB * EMB / 4) / 256, 256>>>(qkv_w, Bqhi_p, Bqlo_p);
    conv_w_kernel<<<(EMB * EMB / 4) / 256, 256>>>(o_w, Bohi_p, Bolo_p);

    // 3. pe GEMM (big tile, 3-stage ring, split-K=32 into g_scratch)
    pe_gemm_big<<<dim3(EMB / 256, MPAD / 128, SPLITK), 512, NBUF * BSTAGE>>>();

    // 4. reduce split-K + bias + mask -> pe_tok
    reduce_pe_kernel<<<(SEQ * EMB + 255) / 256, 256>>>(conv_pe_b, maskf_p);

    // 5. x patch embed -> tokens as bf16 hi/lo (bias + mask in epilogue)
    mma_gemm<1><<<dim3(EMB / 128, MQ / 128, 1), 256, 2 * STAGEB>>>(
        Axhi_p, Axlo_p, Bxhi_p, Bxlo_p, K_X,
        nullptr, Tokhi_p, Toklo_p, conv_in_b, maskf_p, EMB, MQ);

    // 6. QKV: tokens @ qkv_w^T + b -> fp32 g_qkv
    mma_gemm<2><<<dim3((3 * EMB) / 128, MQ / 128, 1), 256, 2 * STAGEB>>>(
        Tokhi_p, Toklo_p, Bqhi_p, Bqlo_p, EMB,
        qkv_p, nullptr, nullptr, qkv_b, nullptr, 3 * EMB, MQ);

    // 7. normalized q (+pe) and k, raw v gather
    prep_q_kernel<<<dim3(SEQ, NHEADS), HD>>>(ftag);
    prep_k_kernel<<<dim3(KSEQ, NHEADS), HD>>>(ftag);

    // 8. landmarks
    landmark_kernel<<<dim3(LM, NHEADS), HD>>>(qn_p, qL_p, SEQ / LM);
    landmark_kernel<<<dim3(LM, NHEADS), HD>>>(kn_p, kL_p, KSEQ / LM);

    // 9. attention core
    a1_kernel<<<dim3(SEQ / 4, NHEADS), 128>>>();
    a2_kernel<<<dim3(LM, NHEADS), 256>>>();
    a2v_kernel<<<dim3(LM, NHEADS), 256>>>();
    vals_kernel<<<SEQ, EMB>>>();

    // 10. output projection via mma (rows >= SEQ in pad are zero, writes guarded)
    mma_gemm<2><<<dim3(EMB / 128, MPAD / 128, 1), 256, 2 * STAGEB>>>(
        Xohi_p, Xolo_p, Bohi_p, Bolo_p, EMB,
        (float*)d_out, nullptr, nullptr, o_b, nullptr, EMB, SEQ);
}